// round 12
// baseline (speedup 1.0000x reference)
#include <cuda_runtime.h>
#include <cuda_bf16.h>
#include <cuda_fp16.h>
#include <cstdint>
#include <cstdio>

// ---------------- problem constants ----------------
#define Hc   256
#define H4c  64
#define Bc   256
#define Mc   128
#define NHc  8
#define DHc  32
#define NMAX 32768
#define EMAX 524288

// ---------------- device scratch -------------------
__device__ float g_PL    [NMAX * Hc];
__device__ float g_PA    [NMAX * Hc];
__device__ float g_PO    [NMAX * Hc];
__device__ float g_qkv   [Bc * Mc * 3 * Hc];
__device__ float g_hh    [NMAX * Hc];
__device__ float g_bnstats[3 * 2 * Hc];
__device__ int   g_inv   [Bc * Mc];
__device__ int   g_mask  [Bc * Mc];
// CSR by destination
__device__ int   g_deg   [NMAX];
__device__ int   g_cs    [NMAX + 1];
__device__ int   g_cur   [NMAX];
__device__ int   g_csrc  [EMAX];
#define WTOT 655360
__device__ __align__(16) __half g_wh[WTOT];
// fp16 activation buffers (single precision pass)
__device__ __align__(16) __half g_h16 [NMAX * Hc];
__device__ __align__(16) __half g_ha16[NMAX * Hc];
__device__ __align__(16) __half g_z116[NMAX * Hc];
__device__ __align__(16) __half g_ad16[NMAX * Hc];
__device__ __align__(16) __half g_hh16[NMAX * Hc];
__device__ __align__(16) __half g_f116[NMAX * 2 * Hc];
__device__ __align__(16) __half g_zrow[64];

// ---------------- PTX helpers ----------------------
__device__ __forceinline__ uint32_t smem_u32(const void* p) {
    uint32_t a;
    asm("{ .reg .u64 t; cvta.to.shared.u64 t, %1; cvt.u32.u64 %0, t; }"
        : "=r"(a) : "l"(p));
    return a;
}
#define LDSM_X4(r0, r1, r2, r3, addr)                                    \
    asm volatile("ldmatrix.sync.aligned.m8n8.x4.shared.b16 {%0,%1,%2,%3}, [%4];" \
                 : "=r"(r0), "=r"(r1), "=r"(r2), "=r"(r3) : "r"(addr))
#define MMA16816(d, a, b0, b1)                                           \
    asm volatile("mma.sync.aligned.m16n8k16.row.col.f32.f16.f16.f32 "    \
                 "{%0,%1,%2,%3}, {%4,%5,%6,%7}, {%8,%9}, {%0,%1,%2,%3};" \
                 : "+f"((d)[0]), "+f"((d)[1]), "+f"((d)[2]), "+f"((d)[3]) \
                 : "r"((a)[0]), "r"((a)[1]), "r"((a)[2]), "r"((a)[3]),   \
                   "r"(b0), "r"(b1))
#define CP_ASYNC16(dst, src)                                             \
    asm volatile("cp.async.ca.shared.global [%0], [%1], 16;" :: "r"(dst), "l"(src))
#define CP_COMMIT() asm volatile("cp.async.commit_group;")
#define CP_WAIT0()  asm volatile("cp.async.wait_group 0;" ::: "memory")

__device__ __forceinline__ uint32_t pack_h2(__half a, __half b) {
    __half2 p{a, b};
    return *(uint32_t*)&p;
}
__device__ __forceinline__ uint32_t pack_f2h(float a, float b) {
    return pack_h2(__float2half_rn(a), __float2half_rn(b));
}
__device__ __forceinline__ float ex2f(float x) {
    float y;
    asm("ex2.approx.ftz.f32 %0, %1;" : "=f"(y) : "f"(x));
    return y;
}
__device__ __forceinline__ uint2 cvt4(float4 v) {
    return make_uint2(pack_f2h(v.x, v.y), pack_f2h(v.z, v.w));
}
__device__ __forceinline__ void split4(float4 v, uint2& hi, uint2& lo) {
    __half a0 = __float2half_rn(v.x), a1 = __float2half_rn(v.y);
    __half a2 = __float2half_rn(v.z), a3 = __float2half_rn(v.w);
    hi = make_uint2(pack_h2(a0, a1), pack_h2(a2, a3));
    lo = make_uint2(pack_f2h(v.x - __half2float(a0), v.y - __half2float(a1)),
                    pack_f2h(v.z - __half2float(a2), v.w - __half2float(a3)));
}

// ---------------- single-pass fp16 GEMM ------------
// C = act(A @ W^T + bias [+res]); A fp16 buffer, W fp16. 2-stage cp.async.
#define ROWB 80
#define OFF_A 0
#define OFF_B 10240
#define BUFSZ 20480
#define GEMM_SMEM (2 * BUFSZ)

template<bool RELU>
__global__ __launch_bounds__(256, 2)
void mma_gemm(const __half* __restrict__ A, const int* __restrict__ a_inv,
              const __half* __restrict__ W, const float* __restrict__ bias,
              const float* __restrict__ res, const int* __restrict__ c_inv,
              float* __restrict__ C32, __half* __restrict__ C16,
              float* __restrict__ stats, int Nc, int K) {
    extern __shared__ char smem[];
    const uint32_t sb = smem_u32(smem);
    const int tid = threadIdx.x;
    const int wid = tid >> 5, lane = tid & 31;
    const int wm = (wid >> 1) * 32, wn = (wid & 1) * 64;
    const int row0 = blockIdx.y * 128;
    const int col0 = blockIdx.x * 128;
    const int r = tid >> 1, half = tid & 1;

    const __half* pA;
    bool avalid = true;
    {
        int arow = row0 + r;
        if (a_inv) {
            int nd = a_inv[arow];
            avalid = nd >= 0;
            pA = A + (size_t)(avalid ? nd : 0) * K;
        } else {
            pA = A + (size_t)arow * K;
        }
    }

    float acc[2][8][4];
#pragma unroll
    for (int mt = 0; mt < 2; mt++)
#pragma unroll
        for (int nt = 0; nt < 8; nt++)
#pragma unroll
            for (int q = 0; q < 4; q++) acc[mt][nt][q] = 0.f;

    const int nit = K >> 5;

    auto issue = [&](int i) {
        const uint32_t bo = (uint32_t)(i & 1) * BUFSZ;
        const int k0 = i * 32;
        const char* sA = avalid ? (const char*)(pA + k0 + half * 16)
                                : (const char*)(g_zrow + half * 16);
        uint32_t dA = sb + bo + OFF_A + r * ROWB + half * 32;
        CP_ASYNC16(dA, sA); CP_ASYNC16(dA + 16, sA + 16);
        const char* gb = (const char*)(W + (size_t)(col0 + r) * K + k0 + half * 16);
        uint32_t dB = sb + bo + OFF_B + r * ROWB + half * 32;
        CP_ASYNC16(dB, gb); CP_ASYNC16(dB + 16, gb + 16);
        CP_COMMIT();
    };

    issue(0);
    for (int i = 0; i < nit; i++) {
        const uint32_t boff = (uint32_t)(i & 1) * BUFSZ;
        CP_WAIT0();
        __syncthreads();
        if (i + 1 < nit) issue(i + 1);
#pragma unroll
        for (int ks = 0; ks < 2; ks++) {
            uint32_t ah[2][4];
#pragma unroll
            for (int mt = 0; mt < 2; mt++) {
                uint32_t arow = wm + mt * 16 + (lane & 15);
                uint32_t kb = ks * 32 + ((lane >> 4) * 16);
                LDSM_X4(ah[mt][0], ah[mt][1], ah[mt][2], ah[mt][3],
                        sb + boff + OFF_A + arow * ROWB + kb);
            }
#pragma unroll
            for (int np = 0; np < 4; np++) {
                uint32_t nrow = wn + np * 16 + ((lane >> 4) << 3) + (lane & 7);
                uint32_t kb = ks * 32 + (((lane >> 3) & 1) << 4);
                uint32_t bh[4];
                LDSM_X4(bh[0], bh[1], bh[2], bh[3],
                        sb + boff + OFF_B + nrow * ROWB + kb);
#pragma unroll
                for (int mt = 0; mt < 2; mt++) {
                    MMA16816(acc[mt][2 * np],     ah[mt], bh[0], bh[1]);
                    MMA16816(acc[mt][2 * np + 1], ah[mt], bh[2], bh[3]);
                }
            }
        }
    }
    __syncthreads();

    // ---- epilogue ----
    float* ssum = (float*)smem;
    float* ssq  = ssum + 128;
    if (stats) {
        if (tid < 128) { ssum[tid] = 0.f; ssq[tid] = 0.f; }
        __syncthreads();
    }
    int rA0 = row0 + wm + (lane >> 2);
    int nmap[2][2];
    if (c_inv) {
        nmap[0][0] = c_inv[rA0];      nmap[0][1] = c_inv[rA0 + 8];
        nmap[1][0] = c_inv[rA0 + 16]; nmap[1][1] = c_inv[rA0 + 24];
    }
#pragma unroll
    for (int nt = 0; nt < 8; nt++) {
        int c = col0 + wn + nt * 8 + (lane & 3) * 2;
        float2 bi = *(const float2*)(bias + c);
        float cs0 = 0.f, cs1 = 0.f, cq0 = 0.f, cq1 = 0.f;
#pragma unroll
        for (int mt = 0; mt < 2; mt++) {
            int ra = rA0 + mt * 16;
            float o0 = acc[mt][nt][0] + bi.x, o1 = acc[mt][nt][1] + bi.y;
            float o2 = acc[mt][nt][2] + bi.x, o3 = acc[mt][nt][3] + bi.y;
            if (c_inv) {
                int na = nmap[mt][0], nb = nmap[mt][1];
                if (na >= 0) {
                    float2 rv = *(const float2*)(res + (size_t)na * Nc + c);
                    o0 += rv.x; o1 += rv.y;
                    *(float2*)(C32 + (size_t)na * Nc + c) = make_float2(o0, o1);
                    cs0 += o0; cq0 += o0 * o0; cs1 += o1; cq1 += o1 * o1;
                }
                if (nb >= 0) {
                    float2 rv = *(const float2*)(res + (size_t)nb * Nc + c);
                    o2 += rv.x; o3 += rv.y;
                    *(float2*)(C32 + (size_t)nb * Nc + c) = make_float2(o2, o3);
                    cs0 += o2; cq0 += o2 * o2; cs1 += o3; cq1 += o3 * o3;
                }
            } else {
                if (res) {
                    float2 r0 = *(const float2*)(res + (size_t)ra * Nc + c);
                    float2 r1 = *(const float2*)(res + (size_t)(ra + 8) * Nc + c);
                    o0 += r0.x; o1 += r0.y; o2 += r1.x; o3 += r1.y;
                }
                if (RELU) {
                    o0 = fmaxf(o0, 0.f); o1 = fmaxf(o1, 0.f);
                    o2 = fmaxf(o2, 0.f); o3 = fmaxf(o3, 0.f);
                }
                if (C32) {
                    *(float2*)(C32 + (size_t)ra * Nc + c) = make_float2(o0, o1);
                    *(float2*)(C32 + (size_t)(ra + 8) * Nc + c) = make_float2(o2, o3);
                }
                if (C16) {
                    *(uint32_t*)(C16 + (size_t)ra * Nc + c) = pack_f2h(o0, o1);
                    *(uint32_t*)(C16 + (size_t)(ra + 8) * Nc + c) = pack_f2h(o2, o3);
                }
                if (stats) {
                    cs0 += o0 + o2; cq0 += o0 * o0 + o2 * o2;
                    cs1 += o1 + o3; cq1 += o1 * o1 + o3 * o3;
                }
            }
        }
        if (stats) {
            int lc = c - col0;
            atomicAdd(&ssum[lc], cs0); atomicAdd(&ssq[lc], cq0);
            atomicAdd(&ssum[lc + 1], cs1); atomicAdd(&ssq[lc + 1], cq1);
        }
    }
    if (stats) {
        __syncthreads();
        if (tid < 128) {
            atomicAdd(&stats[col0 + tid], ssum[tid]);
            atomicAdd(&stats[Hc + col0 + tid], ssq[tid]);
        }
    }
}

// ---------------- weight convert + deg zero ---------
__global__ void wsplit_all(const float* w0, const float* w1, const float* w2,
                           const float* w3, const float* w4, const float* w5) {
    int blk = blockIdx.x;
    int gid = blk * 256 + threadIdx.x;
    if (gid < NMAX) g_deg[gid] = 0;
    const float* W; int sblk; int oel;
    if      (blk < 64)  { W = w0; sblk = 0;   oel = 0;      }
    else if (blk < 128) { W = w1; sblk = 64;  oel = 65536;  }
    else if (blk < 320) { W = w2; sblk = 128; oel = 131072; }
    else if (blk < 384) { W = w3; sblk = 320; oel = 327680; }
    else if (blk < 512) { W = w4; sblk = 384; oel = 393216; }
    else                { W = w5; sblk = 512; oel = 524288; }
    int i4 = (blk - sblk) * 256 + threadIdx.x;
    float4 v = ((const float4*)W)[i4];
    ((uint2*)(g_wh + oel))[i4] = cvt4(v);
}

// h -> fp16
__global__ void h_split(const float* __restrict__ h, int n4) {
    int gid = blockIdx.x * 256 + threadIdx.x;
    if (gid >= n4) return;
    ((uint2*)g_h16)[gid] = cvt4(((const float4*)h)[gid]);
}

// ---------------- CSR build ------------------------
__global__ void hist_k(const int* __restrict__ dst, int E) {
    int e = blockIdx.x * 256 + threadIdx.x;
    if (e < E) atomicAdd(&g_deg[dst[e]], 1);
}

__global__ void csr_scan() {
    __shared__ int sm[1024];
    int t = threadIdx.x;
    int base = t * 32;
    int loc[32];
    int s = 0;
#pragma unroll
    for (int i = 0; i < 32; i++) { loc[i] = s; s += g_deg[base + i]; }
    sm[t] = s;
    __syncthreads();
    for (int off = 1; off < 1024; off <<= 1) {
        int v = sm[t] + ((t >= off) ? sm[t - off] : 0);
        __syncthreads();
        sm[t] = v;
        __syncthreads();
    }
    int pref = (t == 0) ? 0 : sm[t - 1];
#pragma unroll
    for (int i = 0; i < 32; i++) {
        int v = pref + loc[i];
        g_cs[base + i] = v;
        g_cur[base + i] = v;
    }
    if (t == 1023) g_cs[NMAX] = sm[1023];
}

__global__ void csr_fill(const int* __restrict__ src, const int* __restrict__ dst, int E) {
    int e = blockIdx.x * 256 + threadIdx.x;
    if (e >= E) return;
    int d = dst[e];
    int pos = atomicAdd(&g_cur[d], 1);
    g_csrc[pos] = src[e];
}

// ---------------- fused gather + convert ------------
__global__ __launch_bounds__(256)
void gather_k(const float* __restrict__ h) {
    int w = blockIdx.x * 8 + (threadIdx.x >> 5);
    int lane = threadIdx.x & 31;
    const float4* hr = (const float4*)h + (size_t)w * H4c + lane * 2;
    float4 s0 = hr[0], s1 = hr[1];
    int beg = g_cs[w], end = g_cs[w + 1];
    for (int e = beg; e < end; e++) {
        int src = __ldg(&g_csrc[e]);
        const float4* p = (const float4*)h + (size_t)src * H4c + lane * 2;
        float4 v0 = __ldg(p), v1 = __ldg(p + 1);
        s0.x += v0.x; s0.y += v0.y; s0.z += v0.z; s0.w += v0.w;
        s1.x += v1.x; s1.y += v1.y; s1.z += v1.z; s1.w += v1.w;
    }
    uint2 c0 = cvt4(s0), c1 = cvt4(s1);
    *(uint4*)(g_ha16 + (size_t)w * Hc + lane * 8) = make_uint4(c0.x, c0.y, c1.x, c1.y);
}

// ---------------- misc utility ----------------------
__global__ void inv_k(const int* __restrict__ bnn) {
    __shared__ int sm[256];
    int t = threadIdx.x;
    sm[t] = bnn[t];
    __syncthreads();
    for (int off = 1; off < 256; off <<= 1) {
        int v = sm[t] + ((t >= off) ? sm[t - off] : 0);
        __syncthreads();
        sm[t] = v;
        __syncthreads();
    }
    int s = blockIdx.x * 256 + t;
    int b = s >> 7, rr = s & (Mc - 1);
    int cumb = (b == 0) ? 0 : sm[b - 1];
    int nb = sm[b] - cumb;
    bool v = rr < nb;
    g_inv[s] = v ? (cumb + rr) : -1;
    g_mask[s] = v ? 1 : 0;
    if (blockIdx.x == 0) {
        for (int i = t; i < 6 * Hc; i += 256) g_bnstats[i] = 0.f;
    }
}

__device__ __forceinline__ float4 bn4(float4 x, float4 s, float4 q,
                                      float4 g, float4 b, float invN) {
    float4 o;
    { float m = s.x * invN, v = q.x * invN - m * m; o.x = g.x * (x.x - m) * rsqrtf(v + 1e-5f) + b.x; }
    { float m = s.y * invN, v = q.y * invN - m * m; o.y = g.y * (x.y - m) * rsqrtf(v + 1e-5f) + b.y; }
    { float m = s.z * invN, v = q.z * invN - m * m; o.z = g.z * (x.z - m) * rsqrtf(v + 1e-5f) + b.z; }
    { float m = s.w * invN, v = q.w * invN - m * m; o.w = g.w * (x.w - m) * rsqrtf(v + 1e-5f) + b.w; }
    return o;
}

__global__ void bn_combine(const float* __restrict__ PL, const float* __restrict__ PA,
                           const float* __restrict__ gl, const float* __restrict__ bl,
                           const float* __restrict__ ga, const float* __restrict__ ba,
                           const float* __restrict__ stl, const float* __restrict__ sta,
                           float* __restrict__ out, float invN, int n4tot) {
    int gid = blockIdx.x * 256 + threadIdx.x;
    if (gid >= n4tot) return;
    int c4 = gid & 63;
    float4 a = bn4(((const float4*)PL)[gid], ((const float4*)stl)[c4],
                   ((const float4*)stl)[H4c + c4], ((const float4*)gl)[c4],
                   ((const float4*)bl)[c4], invN);
    float4 b = bn4(((const float4*)PA)[gid], ((const float4*)sta)[c4],
                   ((const float4*)sta)[H4c + c4], ((const float4*)ga)[c4],
                   ((const float4*)ba)[c4], invN);
    a.x += b.x; a.y += b.y; a.z += b.z; a.w += b.w;
    ((float4*)out)[gid] = a;
    ((uint2*)g_hh16)[gid] = cvt4(a);
}

__global__ void bn_apply(const float* __restrict__ X, const float* __restrict__ st,
                         const float* __restrict__ gamma, const float* __restrict__ beta,
                         float* __restrict__ out, float invN, int n4total) {
    int gid = blockIdx.x * 256 + threadIdx.x;
    if (gid >= n4total) return;
    int c4 = gid & 63;
    float4 o = bn4(((const float4*)X)[gid], ((const float4*)st)[c4],
                   ((const float4*)st)[H4c + c4], ((const float4*)gamma)[c4],
                   ((const float4*)beta)[c4], invN);
    ((float4*)out)[gid] = o;
}

// ---------------- tensor-core attention -------------
// Q kept hi/lo (scores feed softmax; cheap here), K/V single fp16.
#define AQHI 0
#define AQLO 10240
#define AKS  20480
#define AVT  30720
#define AMB  39424
#define ASMEM 39936

__global__ __launch_bounds__(128)
void attn_mma() {
    __shared__ char smem[ASMEM];
    const uint32_t sb = smem_u32(smem);
    const int b = blockIdx.x >> 3;
    const int head = blockIdx.x & 7;
    const int tid = threadIdx.x;
    const int wid = tid >> 5, lane = tid & 31;
    const int wm = wid * 32;

    const float sc2 = 0.17677669529663687f * 1.44269504088896341f;

    {
        const float* base = g_qkv + (size_t)(b * Mc + tid) * (3 * Hc);
        const float* qp = base + head * DHc;
        const float* kp = base + Hc + head * DHc;
        const float* vp = base + 2 * Hc + head * DHc;
#pragma unroll
        for (int j = 0; j < 8; j++) {
            float4 q4 = *(const float4*)(qp + j * 4);
            q4.x *= sc2; q4.y *= sc2; q4.z *= sc2; q4.w *= sc2;
            uint2 qhi, qlo;
            split4(q4, qhi, qlo);
            *(uint2*)(smem + AQHI + tid * ROWB + j * 8) = qhi;
            *(uint2*)(smem + AQLO + tid * ROWB + j * 8) = qlo;
            float4 k4 = *(const float4*)(kp + j * 4);
            *(uint2*)(smem + AKS + tid * ROWB + j * 8) = cvt4(k4);
            float4 v4 = *(const float4*)(vp + j * 4);
            __half* vt = (__half*)(smem + AVT);
            vt[(j * 4 + 0) * 136 + tid] = __float2half_rn(v4.x);
            vt[(j * 4 + 1) * 136 + tid] = __float2half_rn(v4.y);
            vt[(j * 4 + 2) * 136 + tid] = __float2half_rn(v4.z);
            vt[(j * 4 + 3) * 136 + tid] = __float2half_rn(v4.w);
        }
        ((float*)(smem + AMB))[tid] = g_mask[b * Mc + tid] ? 0.f : -1e30f;
    }
    __syncthreads();

    float sc[2][16][4];
#pragma unroll
    for (int mt = 0; mt < 2; mt++)
#pragma unroll
        for (int nt = 0; nt < 16; nt++)
#pragma unroll
            for (int q = 0; q < 4; q++) sc[mt][nt][q] = 0.f;

#pragma unroll
    for (int pass = 0; pass < 2; pass++) {
        const uint32_t aoff = pass ? AQLO : AQHI;
#pragma unroll
        for (int ks = 0; ks < 2; ks++) {
            uint32_t ah[2][4];
#pragma unroll
            for (int mt = 0; mt < 2; mt++) {
                uint32_t arow = wm + mt * 16 + (lane & 15);
                uint32_t kb = ks * 32 + ((lane >> 4) * 16);
                LDSM_X4(ah[mt][0], ah[mt][1], ah[mt][2], ah[mt][3],
                        sb + aoff + arow * ROWB + kb);
            }
#pragma unroll
            for (int np = 0; np < 8; np++) {
                uint32_t nrow = np * 16 + ((lane >> 4) << 3) + (lane & 7);
                uint32_t kb = ks * 32 + (((lane >> 3) & 1) << 4);
                uint32_t bh[4];
                LDSM_X4(bh[0], bh[1], bh[2], bh[3], sb + AKS + nrow * ROWB + kb);
#pragma unroll
                for (int mt = 0; mt < 2; mt++) {
                    MMA16816(sc[mt][2 * np],     ah[mt], bh[0], bh[1]);
                    MMA16816(sc[mt][2 * np + 1], ah[mt], bh[2], bh[3]);
                }
            }
        }
    }

    const float* mb = (const float*)(smem + AMB);
#pragma unroll
    for (int nt = 0; nt < 16; nt++) {
        float2 mp = *(const float2*)(mb + nt * 8 + (lane & 3) * 2);
#pragma unroll
        for (int mt = 0; mt < 2; mt++) {
            sc[mt][nt][0] += mp.x; sc[mt][nt][1] += mp.y;
            sc[mt][nt][2] += mp.x; sc[mt][nt][3] += mp.y;
        }
    }
    float rinv[4];
#pragma unroll
    for (int rg = 0; rg < 4; rg++) {
        const int mt = rg >> 1, off = (rg & 1) * 2;
        float m = -3.0e38f;
#pragma unroll
        for (int nt = 0; nt < 16; nt++)
            m = fmaxf(m, fmaxf(sc[mt][nt][off], sc[mt][nt][off + 1]));
        m = fmaxf(m, __shfl_xor_sync(0xffffffff, m, 1));
        m = fmaxf(m, __shfl_xor_sync(0xffffffff, m, 2));
        float l = 0.f;
#pragma unroll
        for (int nt = 0; nt < 16; nt++) {
            float p0 = ex2f(sc[mt][nt][off] - m);
            float p1 = ex2f(sc[mt][nt][off + 1] - m);
            sc[mt][nt][off] = p0; sc[mt][nt][off + 1] = p1;
            l += p0 + p1;
        }
        l += __shfl_xor_sync(0xffffffff, l, 1);
        l += __shfl_xor_sync(0xffffffff, l, 2);
        rinv[rg] = 1.f / l;
    }

    float av[2][4][4];
#pragma unroll
    for (int mt = 0; mt < 2; mt++)
#pragma unroll
        for (int nd = 0; nd < 4; nd++)
#pragma unroll
            for (int q = 0; q < 4; q++) av[mt][nd][q] = 0.f;

#pragma unroll
    for (int j = 0; j < 8; j++) {
        uint32_t pa[2][4];
#pragma unroll
        for (int mt = 0; mt < 2; mt++) {
            pa[mt][0] = pack_f2h(sc[mt][2 * j][0],     sc[mt][2 * j][1]);
            pa[mt][1] = pack_f2h(sc[mt][2 * j][2],     sc[mt][2 * j][3]);
            pa[mt][2] = pack_f2h(sc[mt][2 * j + 1][0], sc[mt][2 * j + 1][1]);
            pa[mt][3] = pack_f2h(sc[mt][2 * j + 1][2], sc[mt][2 * j + 1][3]);
        }
#pragma unroll
        for (int np = 0; np < 2; np++) {
            uint32_t nrow = np * 16 + ((lane >> 4) << 3) + (lane & 7);
            uint32_t kb = j * 32 + (((lane >> 3) & 1) << 4);
            uint32_t vb[4];
            LDSM_X4(vb[0], vb[1], vb[2], vb[3], sb + AVT + nrow * 272 + kb);
#pragma unroll
            for (int mt = 0; mt < 2; mt++) {
                MMA16816(av[mt][2 * np],     pa[mt], vb[0], vb[1]);
                MMA16816(av[mt][2 * np + 1], pa[mt], vb[2], vb[3]);
            }
        }
    }

#pragma unroll
    for (int mt = 0; mt < 2; mt++) {
        int row = b * Mc + wm + mt * 16 + (lane >> 2);
#pragma unroll
        for (int nd = 0; nd < 4; nd++) {
            int col = head * DHc + nd * 8 + (lane & 3) * 2;
            float i0 = rinv[mt * 2 + 0], i1 = rinv[mt * 2 + 1];
            *(uint32_t*)(g_ad16 + (size_t)row * Hc + col) =
                pack_f2h(av[mt][nd][0] * i0, av[mt][nd][1] * i0);
            *(uint32_t*)(g_ad16 + (size_t)(row + 8) * Hc + col) =
                pack_f2h(av[mt][nd][2] * i1, av[mt][nd][3] * i1);
        }
    }
}

// ---------------- host orchestration ----------------
static inline int cdiv(long a, int b) { return (int)((a + b - 1) / b); }

extern "C" void kernel_launch(void* const* d_in, const int* in_sizes, int n_in,
                              void* d_out, int out_size) {
    const float* h         = (const float*)d_in[0];
    const float* gin_w1    = (const float*)d_in[1];
    const float* gin_b1    = (const float*)d_in[2];
    const float* gin_w2    = (const float*)d_in[3];
    const float* gin_b2    = (const float*)d_in[4];
    const float* in_proj_w = (const float*)d_in[5];
    const float* in_proj_b = (const float*)d_in[6];
    const float* out_proj_w= (const float*)d_in[7];
    const float* out_proj_b= (const float*)d_in[8];
    const float* bnl_g     = (const float*)d_in[9];
    const float* bnl_b     = (const float*)d_in[10];
    const float* bna_g     = (const float*)d_in[11];
    const float* bna_b     = (const float*)d_in[12];
    const float* bno_g     = (const float*)d_in[13];
    const float* bno_b     = (const float*)d_in[14];
    const float* ffn1_w    = (const float*)d_in[15];
    const float* ffn1_b    = (const float*)d_in[16];
    const float* ffn2_w    = (const float*)d_in[17];
    const float* ffn2_b    = (const float*)d_in[18];
    const int*   e_src     = (const int*)d_in[19];
    const int*   e_dst     = (const int*)d_in[20];
    const int*   bnn       = (const int*)d_in[21];

    const int nN = in_sizes[0] / Hc;
    const int nE = in_sizes[19];
    const int n4 = nN * H4c;
    const float invN = 1.0f / (float)nN;

    float *p_PL, *p_PA, *p_PO, *p_qkv, *p_hh, *p_st;
    int *p_inv;
    __half *p_wh, *p_h16, *p_ha16, *p_z116, *p_ad16, *p_hh16, *p_f116;
    cudaGetSymbolAddress((void**)&p_PL,   g_PL);
    cudaGetSymbolAddress((void**)&p_PA,   g_PA);
    cudaGetSymbolAddress((void**)&p_PO,   g_PO);
    cudaGetSymbolAddress((void**)&p_qkv,  g_qkv);
    cudaGetSymbolAddress((void**)&p_hh,   g_hh);
    cudaGetSymbolAddress((void**)&p_st,   g_bnstats);
    cudaGetSymbolAddress((void**)&p_inv,  g_inv);
    cudaGetSymbolAddress((void**)&p_wh,   g_wh);
    cudaGetSymbolAddress((void**)&p_h16,  g_h16);
    cudaGetSymbolAddress((void**)&p_ha16, g_ha16);
    cudaGetSymbolAddress((void**)&p_z116, g_z116);
    cudaGetSymbolAddress((void**)&p_ad16, g_ad16);
    cudaGetSymbolAddress((void**)&p_hh16, g_hh16);
    cudaGetSymbolAddress((void**)&p_f116, g_f116);

    float* st_l = p_st;
    float* st_a = p_st + 2 * Hc;
    float* st_o = p_st + 4 * Hc;

    cudaFuncSetAttribute(mma_gemm<true>,  cudaFuncAttributeMaxDynamicSharedMemorySize, GEMM_SMEM);
    cudaFuncSetAttribute(mma_gemm<false>, cudaFuncAttributeMaxDynamicSharedMemorySize, GEMM_SMEM);

    const int OFF_GIN1 = 0;
    const int OFF_GIN2 = 65536;
    const int OFF_QKV  = 131072;
    const int OFF_OUT  = 327680;
    const int OFF_F1   = 393216;
    const int OFF_F2   = 524288;

    auto gemm = [&](bool relu, const __half* A, const int* a_inv, int woff,
                    const float* bias, const float* res, const int* c_inv,
                    float* C32, __half* C16, float* stats, int Nc, int K) {
        dim3 grid(Nc / 128, nN / 128);
        if (relu)
            mma_gemm<true><<<grid, 256, GEMM_SMEM>>>(A, a_inv, p_wh + woff,
                bias, res, c_inv, C32, C16, stats, Nc, K);
        else
            mma_gemm<false><<<grid, 256, GEMM_SMEM>>>(A, a_inv, p_wh + woff,
                bias, res, c_inv, C32, C16, stats, Nc, K);
    };

    // launch 0-2: prep needed by qkv
    wsplit_all<<<640, 256>>>(gin_w1, gin_w2, in_proj_w, out_proj_w, ffn1_w, ffn2_w);
    h_split<<<cdiv(n4, 256), 256>>>(h, n4);
    inv_k<<<Bc * Mc / 256, 256>>>(bnn);

    // launch 3: qkv GEMM  <-- ncu profiles launch index 3
    gemm(false, p_h16, p_inv, OFF_QKV, in_proj_b, nullptr, nullptr,
         p_qkv, nullptr, nullptr, 3 * Hc, Hc);

    // launch 4-7: CSR build + gather (GIN input)
    hist_k<<<cdiv(nE, 256), 256>>>(e_dst, nE);
    csr_scan<<<1, 1024>>>();
    csr_fill<<<cdiv(nE, 256), 256>>>(e_src, e_dst, nE);
    gather_k<<<nN / 8, 256>>>(h);

    // GIN branch
    gemm(true,  p_ha16, nullptr, OFF_GIN1, gin_b1, nullptr, nullptr,
         nullptr, p_z116, nullptr, Hc, Hc);
    gemm(false, p_z116, nullptr, OFF_GIN2, gin_b2, h, nullptr,
         p_PL, nullptr, st_l, Hc, Hc);

    // attention tail
    attn_mma<<<Bc * NHc, 128>>>();
    gemm(false, p_ad16, nullptr, OFF_OUT, out_proj_b, h, p_inv,
         p_PA, nullptr, st_a, Hc, Hc);

    // combine BNs
    bn_combine<<<cdiv(n4, 256), 256>>>(p_PL, p_PA, bnl_g, bnl_b, bna_g, bna_b,
                                       st_l, st_a, p_hh, invN, n4);

    // FFN + final norm
    gemm(true,  p_hh16, nullptr, OFF_F1, ffn1_b, nullptr, nullptr,
         nullptr, p_f116, nullptr, 2 * Hc, Hc);
    gemm(false, p_f116, nullptr, OFF_F2, ffn2_b, p_hh, nullptr,
         p_PO, nullptr, st_o, Hc, 2 * Hc);
    bn_apply<<<cdiv(n4, 256), 256>>>(p_PO, st_o, bno_g, bno_b, (float*)d_out, invN, n4);
}

// round 13
// speedup vs baseline: 1.0796x; 1.0796x over previous
#include <cuda_runtime.h>
#include <cuda_bf16.h>
#include <cuda_fp16.h>
#include <cstdint>
#include <cstdio>

// ---------------- problem constants ----------------
#define Hc   256
#define H4c  64
#define Bc   256
#define Mc   128
#define NHc  8
#define DHc  32
#define NMAX 32768
#define EMAX 524288

// ---------------- device scratch -------------------
__device__ float g_PL    [NMAX * Hc];
__device__ float g_PA    [NMAX * Hc];
__device__ float g_hh    [NMAX * Hc];
__device__ float g_bnstats[3 * 2 * Hc];
__device__ int   g_inv   [Bc * Mc];
__device__ int   g_mask  [Bc * Mc];
// CSR by destination
__device__ int   g_deg   [NMAX];
__device__ int   g_cs    [NMAX + 1];
__device__ int   g_cur   [NMAX];
__device__ int   g_csrc  [EMAX];
#define WTOT 655360
__device__ __align__(16) __half g_wh[WTOT];
// fp16 activation buffers
__device__ __align__(16) __half g_h16  [NMAX * Hc];
__device__ __align__(16) __half g_ha16 [NMAX * Hc];
__device__ __align__(16) __half g_z116 [NMAX * Hc];
__device__ __align__(16) __half g_qkv16[Bc * Mc * 3 * Hc];
__device__ __align__(16) __half g_ad16 [NMAX * Hc];   // attn out, later reused as PO16
__device__ __align__(16) __half g_hh16 [NMAX * Hc];
__device__ __align__(16) __half g_f116 [NMAX * 2 * Hc];
__device__ __align__(16) __half g_zrow[64];

// ---------------- PTX helpers ----------------------
__device__ __forceinline__ uint32_t smem_u32(const void* p) {
    uint32_t a;
    asm("{ .reg .u64 t; cvta.to.shared.u64 t, %1; cvt.u32.u64 %0, t; }"
        : "=r"(a) : "l"(p));
    return a;
}
#define LDSM_X4(r0, r1, r2, r3, addr)                                    \
    asm volatile("ldmatrix.sync.aligned.m8n8.x4.shared.b16 {%0,%1,%2,%3}, [%4];" \
                 : "=r"(r0), "=r"(r1), "=r"(r2), "=r"(r3) : "r"(addr))
#define MMA16816(d, a, b0, b1)                                           \
    asm volatile("mma.sync.aligned.m16n8k16.row.col.f32.f16.f16.f32 "    \
                 "{%0,%1,%2,%3}, {%4,%5,%6,%7}, {%8,%9}, {%0,%1,%2,%3};" \
                 : "+f"((d)[0]), "+f"((d)[1]), "+f"((d)[2]), "+f"((d)[3]) \
                 : "r"((a)[0]), "r"((a)[1]), "r"((a)[2]), "r"((a)[3]),   \
                   "r"(b0), "r"(b1))
#define CP_ASYNC16(dst, src)                                             \
    asm volatile("cp.async.ca.shared.global [%0], [%1], 16;" :: "r"(dst), "l"(src))
#define CP_COMMIT() asm volatile("cp.async.commit_group;")
#define CP_WAIT0()  asm volatile("cp.async.wait_group 0;" ::: "memory")

__device__ __forceinline__ uint32_t pack_h2(__half a, __half b) {
    __half2 p{a, b};
    return *(uint32_t*)&p;
}
__device__ __forceinline__ uint32_t pack_f2h(float a, float b) {
    return pack_h2(__float2half_rn(a), __float2half_rn(b));
}
__device__ __forceinline__ float ex2f(float x) {
    float y;
    asm("ex2.approx.ftz.f32 %0, %1;" : "=f"(y) : "f"(x));
    return y;
}
__device__ __forceinline__ uint2 cvt4(float4 v) {
    return make_uint2(pack_f2h(v.x, v.y), pack_f2h(v.z, v.w));
}

// ---------------- single-pass fp16 GEMM ------------
#define ROWB 80
#define OFF_A 0
#define OFF_B 10240
#define BUFSZ 20480
#define GEMM_SMEM (2 * BUFSZ)

template<bool RELU>
__global__ __launch_bounds__(256, 2)
void mma_gemm(const __half* __restrict__ A, const int* __restrict__ a_inv,
              const __half* __restrict__ W, const float* __restrict__ bias,
              const float* __restrict__ res, const int* __restrict__ c_inv,
              float* __restrict__ C32, __half* __restrict__ C16,
              float* __restrict__ stats, int Nc, int K) {
    extern __shared__ char smem[];
    const uint32_t sb = smem_u32(smem);
    const int tid = threadIdx.x;
    const int wid = tid >> 5, lane = tid & 31;
    const int wm = (wid >> 1) * 32, wn = (wid & 1) * 64;
    const int row0 = blockIdx.y * 128;
    const int col0 = blockIdx.x * 128;
    const int r = tid >> 1, half = tid & 1;

    const __half* pA;
    bool avalid = true;
    {
        int arow = row0 + r;
        if (a_inv) {
            int nd = a_inv[arow];
            avalid = nd >= 0;
            pA = A + (size_t)(avalid ? nd : 0) * K;
        } else {
            pA = A + (size_t)arow * K;
        }
    }

    float acc[2][8][4];
#pragma unroll
    for (int mt = 0; mt < 2; mt++)
#pragma unroll
        for (int nt = 0; nt < 8; nt++)
#pragma unroll
            for (int q = 0; q < 4; q++) acc[mt][nt][q] = 0.f;

    const int nit = K >> 5;

    auto issue = [&](int i) {
        const uint32_t bo = (uint32_t)(i & 1) * BUFSZ;
        const int k0 = i * 32;
        const char* sA = avalid ? (const char*)(pA + k0 + half * 16)
                                : (const char*)(g_zrow + half * 16);
        uint32_t dA = sb + bo + OFF_A + r * ROWB + half * 32;
        CP_ASYNC16(dA, sA); CP_ASYNC16(dA + 16, sA + 16);
        const char* gb = (const char*)(W + (size_t)(col0 + r) * K + k0 + half * 16);
        uint32_t dB = sb + bo + OFF_B + r * ROWB + half * 32;
        CP_ASYNC16(dB, gb); CP_ASYNC16(dB + 16, gb + 16);
        CP_COMMIT();
    };

    issue(0);
    for (int i = 0; i < nit; i++) {
        const uint32_t boff = (uint32_t)(i & 1) * BUFSZ;
        CP_WAIT0();
        __syncthreads();
        if (i + 1 < nit) issue(i + 1);
#pragma unroll
        for (int ks = 0; ks < 2; ks++) {
            uint32_t ah[2][4];
#pragma unroll
            for (int mt = 0; mt < 2; mt++) {
                uint32_t arow = wm + mt * 16 + (lane & 15);
                uint32_t kb = ks * 32 + ((lane >> 4) * 16);
                LDSM_X4(ah[mt][0], ah[mt][1], ah[mt][2], ah[mt][3],
                        sb + boff + OFF_A + arow * ROWB + kb);
            }
#pragma unroll
            for (int np = 0; np < 4; np++) {
                uint32_t nrow = wn + np * 16 + ((lane >> 4) << 3) + (lane & 7);
                uint32_t kb = ks * 32 + (((lane >> 3) & 1) << 4);
                uint32_t bh[4];
                LDSM_X4(bh[0], bh[1], bh[2], bh[3],
                        sb + boff + OFF_B + nrow * ROWB + kb);
#pragma unroll
                for (int mt = 0; mt < 2; mt++) {
                    MMA16816(acc[mt][2 * np],     ah[mt], bh[0], bh[1]);
                    MMA16816(acc[mt][2 * np + 1], ah[mt], bh[2], bh[3]);
                }
            }
        }
    }
    __syncthreads();

    // ---- epilogue ----
    float* ssum = (float*)smem;
    float* ssq  = ssum + 128;
    if (stats) {
        if (tid < 128) { ssum[tid] = 0.f; ssq[tid] = 0.f; }
        __syncthreads();
    }
    int rA0 = row0 + wm + (lane >> 2);
    int nmap[2][2];
    if (c_inv) {
        nmap[0][0] = c_inv[rA0];      nmap[0][1] = c_inv[rA0 + 8];
        nmap[1][0] = c_inv[rA0 + 16]; nmap[1][1] = c_inv[rA0 + 24];
    }
#pragma unroll
    for (int nt = 0; nt < 8; nt++) {
        int c = col0 + wn + nt * 8 + (lane & 3) * 2;
        float2 bi = *(const float2*)(bias + c);
        float cs0 = 0.f, cs1 = 0.f, cq0 = 0.f, cq1 = 0.f;
#pragma unroll
        for (int mt = 0; mt < 2; mt++) {
            int ra = rA0 + mt * 16;
            float o0 = acc[mt][nt][0] + bi.x, o1 = acc[mt][nt][1] + bi.y;
            float o2 = acc[mt][nt][2] + bi.x, o3 = acc[mt][nt][3] + bi.y;
            if (c_inv) {
                int na = nmap[mt][0], nb = nmap[mt][1];
                if (na >= 0) {
                    float2 rv = *(const float2*)(res + (size_t)na * Nc + c);
                    o0 += rv.x; o1 += rv.y;
                    *(float2*)(C32 + (size_t)na * Nc + c) = make_float2(o0, o1);
                    cs0 += o0; cq0 += o0 * o0; cs1 += o1; cq1 += o1 * o1;
                }
                if (nb >= 0) {
                    float2 rv = *(const float2*)(res + (size_t)nb * Nc + c);
                    o2 += rv.x; o3 += rv.y;
                    *(float2*)(C32 + (size_t)nb * Nc + c) = make_float2(o2, o3);
                    cs0 += o2; cq0 += o2 * o2; cs1 += o3; cq1 += o3 * o3;
                }
            } else {
                if (res) {
                    float2 r0 = *(const float2*)(res + (size_t)ra * Nc + c);
                    float2 r1 = *(const float2*)(res + (size_t)(ra + 8) * Nc + c);
                    o0 += r0.x; o1 += r0.y; o2 += r1.x; o3 += r1.y;
                }
                if (RELU) {
                    o0 = fmaxf(o0, 0.f); o1 = fmaxf(o1, 0.f);
                    o2 = fmaxf(o2, 0.f); o3 = fmaxf(o3, 0.f);
                }
                if (C32) {
                    *(float2*)(C32 + (size_t)ra * Nc + c) = make_float2(o0, o1);
                    *(float2*)(C32 + (size_t)(ra + 8) * Nc + c) = make_float2(o2, o3);
                }
                if (C16) {
                    *(uint32_t*)(C16 + (size_t)ra * Nc + c) = pack_f2h(o0, o1);
                    *(uint32_t*)(C16 + (size_t)(ra + 8) * Nc + c) = pack_f2h(o2, o3);
                }
                if (stats) {
                    cs0 += o0 + o2; cq0 += o0 * o0 + o2 * o2;
                    cs1 += o1 + o3; cq1 += o1 * o1 + o3 * o3;
                }
            }
        }
        if (stats) {
            int lc = c - col0;
            atomicAdd(&ssum[lc], cs0); atomicAdd(&ssq[lc], cq0);
            atomicAdd(&ssum[lc + 1], cs1); atomicAdd(&ssq[lc + 1], cq1);
        }
    }
    if (stats) {
        __syncthreads();
        if (tid < 128) {
            atomicAdd(&stats[col0 + tid], ssum[tid]);
            atomicAdd(&stats[Hc + col0 + tid], ssq[tid]);
        }
    }
}

// ---------------- weight convert + deg zero + inv fused ---------
__global__ void wsplit_all(const float* w0, const float* w1, const float* w2,
                           const float* w3, const float* w4, const float* w5,
                           const int* __restrict__ bnn) {
    int blk = blockIdx.x;
    int t = threadIdx.x;
    if (blk >= 640) {
        // inv_k logic: blocks 640..767 cover Bc*Mc slots
        __shared__ int sm[256];
        sm[t] = bnn[t];
        __syncthreads();
        for (int off = 1; off < 256; off <<= 1) {
            int v = sm[t] + ((t >= off) ? sm[t - off] : 0);
            __syncthreads();
            sm[t] = v;
            __syncthreads();
        }
        int s = (blk - 640) * 256 + t;
        int b = s >> 7, rr = s & (Mc - 1);
        int cumb = (b == 0) ? 0 : sm[b - 1];
        int nb = sm[b] - cumb;
        bool v = rr < nb;
        g_inv[s] = v ? (cumb + rr) : -1;
        g_mask[s] = v ? 1 : 0;
        if (blk == 640) {
            for (int i = t; i < 6 * Hc; i += 256) g_bnstats[i] = 0.f;
        }
        return;
    }
    int gid = blk * 256 + t;
    if (gid < NMAX) g_deg[gid] = 0;
    const float* W; int sblk; int oel;
    if      (blk < 64)  { W = w0; sblk = 0;   oel = 0;      }
    else if (blk < 128) { W = w1; sblk = 64;  oel = 65536;  }
    else if (blk < 320) { W = w2; sblk = 128; oel = 131072; }
    else if (blk < 384) { W = w3; sblk = 320; oel = 327680; }
    else if (blk < 512) { W = w4; sblk = 384; oel = 393216; }
    else                { W = w5; sblk = 512; oel = 524288; }
    int i4 = (blk - sblk) * 256 + t;
    float4 v = ((const float4*)W)[i4];
    ((uint2*)(g_wh + oel))[i4] = cvt4(v);
}

// h -> fp16, plus edge histogram fused (hist covers first E threads)
__global__ void h_split(const float* __restrict__ h, int n4,
                        const int* __restrict__ dst, int E) {
    int gid = blockIdx.x * 256 + threadIdx.x;
    if (gid < n4)
        ((uint2*)g_h16)[gid] = cvt4(((const float4*)h)[gid]);
    if (gid < E)
        atomicAdd(&g_deg[dst[gid]], 1);
}

// ---------------- CSR build ------------------------
__global__ void csr_scan() {
    __shared__ int sm[1024];
    int t = threadIdx.x;
    int base = t * 32;
    int loc[32];
    int s = 0;
#pragma unroll
    for (int i = 0; i < 32; i++) { loc[i] = s; s += g_deg[base + i]; }
    sm[t] = s;
    __syncthreads();
    for (int off = 1; off < 1024; off <<= 1) {
        int v = sm[t] + ((t >= off) ? sm[t - off] : 0);
        __syncthreads();
        sm[t] = v;
        __syncthreads();
    }
    int pref = (t == 0) ? 0 : sm[t - 1];
#pragma unroll
    for (int i = 0; i < 32; i++) {
        int v = pref + loc[i];
        g_cs[base + i] = v;
        g_cur[base + i] = v;
    }
    if (t == 1023) g_cs[NMAX] = sm[1023];
}

__global__ void csr_fill(const int* __restrict__ src, const int* __restrict__ dst, int E) {
    int e = blockIdx.x * 256 + threadIdx.x;
    if (e >= E) return;
    int d = dst[e];
    int pos = atomicAdd(&g_cur[d], 1);
    g_csrc[pos] = src[e];
}

// ---------------- fused gather (from fp16) + convert ----
__global__ __launch_bounds__(256)
void gather_k() {
    int w = blockIdx.x * 8 + (threadIdx.x >> 5);
    int lane = threadIdx.x & 31;
    // each lane owns 8 contiguous halves (16B) of the 256-half row
    const uint4* hr = (const uint4*)(g_h16 + (size_t)w * Hc) + lane;
    float s[8];
    {
        uint4 v = *hr;
        const __half2* h2 = (const __half2*)&v;
#pragma unroll
        for (int j = 0; j < 4; j++) {
            float2 f = __half22float2(h2[j]);
            s[j * 2] = f.x; s[j * 2 + 1] = f.y;
        }
    }
    int beg = g_cs[w], end = g_cs[w + 1];
    for (int e = beg; e < end; e++) {
        int src = __ldg(&g_csrc[e]);
        uint4 v = __ldg((const uint4*)(g_h16 + (size_t)src * Hc) + lane);
        const __half2* h2 = (const __half2*)&v;
#pragma unroll
        for (int j = 0; j < 4; j++) {
            float2 f = __half22float2(h2[j]);
            s[j * 2] += f.x; s[j * 2 + 1] += f.y;
        }
    }
    uint4 o;
    o.x = pack_f2h(s[0], s[1]); o.y = pack_f2h(s[2], s[3]);
    o.z = pack_f2h(s[4], s[5]); o.w = pack_f2h(s[6], s[7]);
    *((uint4*)(g_ha16 + (size_t)w * Hc) + lane) = o;
}

// ---------------- BN kernels ------------------------
__device__ __forceinline__ float4 bn4(float4 x, float4 s, float4 q,
                                      float4 g, float4 b, float invN) {
    float4 o;
    { float m = s.x * invN, v = q.x * invN - m * m; o.x = g.x * (x.x - m) * rsqrtf(v + 1e-5f) + b.x; }
    { float m = s.y * invN, v = q.y * invN - m * m; o.y = g.y * (x.y - m) * rsqrtf(v + 1e-5f) + b.y; }
    { float m = s.z * invN, v = q.z * invN - m * m; o.z = g.z * (x.z - m) * rsqrtf(v + 1e-5f) + b.z; }
    { float m = s.w * invN, v = q.w * invN - m * m; o.w = g.w * (x.w - m) * rsqrtf(v + 1e-5f) + b.w; }
    return o;
}

__global__ void bn_combine(const float* __restrict__ PL, const float* __restrict__ PA,
                           const float* __restrict__ gl, const float* __restrict__ bl,
                           const float* __restrict__ ga, const float* __restrict__ ba,
                           const float* __restrict__ stl, const float* __restrict__ sta,
                           float* __restrict__ out, float invN, int n4tot) {
    int gid = blockIdx.x * 256 + threadIdx.x;
    if (gid >= n4tot) return;
    int c4 = gid & 63;
    float4 a = bn4(((const float4*)PL)[gid], ((const float4*)stl)[c4],
                   ((const float4*)stl)[H4c + c4], ((const float4*)gl)[c4],
                   ((const float4*)bl)[c4], invN);
    float4 b = bn4(((const float4*)PA)[gid], ((const float4*)sta)[c4],
                   ((const float4*)sta)[H4c + c4], ((const float4*)ga)[c4],
                   ((const float4*)ba)[c4], invN);
    a.x += b.x; a.y += b.y; a.z += b.z; a.w += b.w;
    ((float4*)out)[gid] = a;
    ((uint2*)g_hh16)[gid] = cvt4(a);
}

// final BN from fp16 input
__global__ void bn_apply16(const __half* __restrict__ X16, const float* __restrict__ st,
                           const float* __restrict__ gamma, const float* __restrict__ beta,
                           float* __restrict__ out, float invN, int n4total) {
    int gid = blockIdx.x * 256 + threadIdx.x;
    if (gid >= n4total) return;
    int c4 = gid & 63;
    uint2 xv = ((const uint2*)X16)[gid];
    const __half2* h2 = (const __half2*)&xv;
    float2 f0 = __half22float2(h2[0]), f1 = __half22float2(h2[1]);
    float4 x = make_float4(f0.x, f0.y, f1.x, f1.y);
    float4 o = bn4(x, ((const float4*)st)[c4],
                   ((const float4*)st)[H4c + c4], ((const float4*)gamma)[c4],
                   ((const float4*)beta)[c4], invN);
    ((float4*)out)[gid] = o;
}

// ---------------- tensor-core attention (all fp16 in) ----
#define AQ   0
#define AKS  10240
#define AVT  20480          // 32 rows x 272B = 8704
#define AMB  29184
#define ASMEM 29696

__global__ __launch_bounds__(128)
void attn_mma() {
    __shared__ char smem[ASMEM];
    const uint32_t sb = smem_u32(smem);
    const int b = blockIdx.x >> 3;
    const int head = blockIdx.x & 7;
    const int tid = threadIdx.x;
    const int wid = tid >> 5, lane = tid & 31;
    const int wm = wid * 32;

    const float sc2 = 0.17677669529663687f * 1.44269504088896341f;

    {
        const __half* base = g_qkv16 + (size_t)(b * Mc + tid) * (3 * Hc);
        const uint4* qp = (const uint4*)(base + head * DHc);
        const uint4* kp = (const uint4*)(base + Hc + head * DHc);
        const uint4* vp = (const uint4*)(base + 2 * Hc + head * DHc);
        __half2 s2 = __float2half2_rn(sc2);
        __half* vt = (__half*)(smem + AVT);
#pragma unroll
        for (int j = 0; j < 4; j++) {
            uint4 q = qp[j];
            __half2* qh = (__half2*)&q;
#pragma unroll
            for (int u = 0; u < 4; u++) qh[u] = __hmul2(qh[u], s2);
            *(uint4*)(smem + AQ + tid * ROWB + j * 16) = q;
            *(uint4*)(smem + AKS + tid * ROWB + j * 16) = kp[j];
            uint4 v = vp[j];
            const __half* vh = (const __half*)&v;
#pragma unroll
            for (int u = 0; u < 8; u++)
                vt[(j * 8 + u) * 136 + tid] = vh[u];
        }
        ((float*)(smem + AMB))[tid] = g_mask[b * Mc + tid] ? 0.f : -1e30f;
    }
    __syncthreads();

    float sc[2][16][4];
#pragma unroll
    for (int mt = 0; mt < 2; mt++)
#pragma unroll
        for (int nt = 0; nt < 16; nt++)
#pragma unroll
            for (int q = 0; q < 4; q++) sc[mt][nt][q] = 0.f;

#pragma unroll
    for (int ks = 0; ks < 2; ks++) {
        uint32_t ah[2][4];
#pragma unroll
        for (int mt = 0; mt < 2; mt++) {
            uint32_t arow = wm + mt * 16 + (lane & 15);
            uint32_t kb = ks * 32 + ((lane >> 4) * 16);
            LDSM_X4(ah[mt][0], ah[mt][1], ah[mt][2], ah[mt][3],
                    sb + AQ + arow * ROWB + kb);
        }
#pragma unroll
        for (int np = 0; np < 8; np++) {
            uint32_t nrow = np * 16 + ((lane >> 4) << 3) + (lane & 7);
            uint32_t kb = ks * 32 + (((lane >> 3) & 1) << 4);
            uint32_t bh[4];
            LDSM_X4(bh[0], bh[1], bh[2], bh[3], sb + AKS + nrow * ROWB + kb);
#pragma unroll
            for (int mt = 0; mt < 2; mt++) {
                MMA16816(sc[mt][2 * np],     ah[mt], bh[0], bh[1]);
                MMA16816(sc[mt][2 * np + 1], ah[mt], bh[2], bh[3]);
            }
        }
    }

    const float* mb = (const float*)(smem + AMB);
#pragma unroll
    for (int nt = 0; nt < 16; nt++) {
        float2 mp = *(const float2*)(mb + nt * 8 + (lane & 3) * 2);
#pragma unroll
        for (int mt = 0; mt < 2; mt++) {
            sc[mt][nt][0] += mp.x; sc[mt][nt][1] += mp.y;
            sc[mt][nt][2] += mp.x; sc[mt][nt][3] += mp.y;
        }
    }
    float rinv[4];
#pragma unroll
    for (int rg = 0; rg < 4; rg++) {
        const int mt = rg >> 1, off = (rg & 1) * 2;
        float m = -3.0e38f;
#pragma unroll
        for (int nt = 0; nt < 16; nt++)
            m = fmaxf(m, fmaxf(sc[mt][nt][off], sc[mt][nt][off + 1]));
        m = fmaxf(m, __shfl_xor_sync(0xffffffff, m, 1));
        m = fmaxf(m, __shfl_xor_sync(0xffffffff, m, 2));
        float l = 0.f;
#pragma unroll
        for (int nt = 0; nt < 16; nt++) {
            float p0 = ex2f(sc[mt][nt][off] - m);
            float p1 = ex2f(sc[mt][nt][off + 1] - m);
            sc[mt][nt][off] = p0; sc[mt][nt][off + 1] = p1;
            l += p0 + p1;
        }
        l += __shfl_xor_sync(0xffffffff, l, 1);
        l += __shfl_xor_sync(0xffffffff, l, 2);
        rinv[rg] = 1.f / l;
    }

    float av[2][4][4];
#pragma unroll
    for (int mt = 0; mt < 2; mt++)
#pragma unroll
        for (int nd = 0; nd < 4; nd++)
#pragma unroll
            for (int q = 0; q < 4; q++) av[mt][nd][q] = 0.f;

#pragma unroll
    for (int j = 0; j < 8; j++) {
        uint32_t pa[2][4];
#pragma unroll
        for (int mt = 0; mt < 2; mt++) {
            pa[mt][0] = pack_f2h(sc[mt][2 * j][0],     sc[mt][2 * j][1]);
            pa[mt][1] = pack_f2h(sc[mt][2 * j][2],     sc[mt][2 * j][3]);
            pa[mt][2] = pack_f2h(sc[mt][2 * j + 1][0], sc[mt][2 * j + 1][1]);
            pa[mt][3] = pack_f2h(sc[mt][2 * j + 1][2], sc[mt][2 * j + 1][3]);
        }
#pragma unroll
        for (int np = 0; np < 2; np++) {
            uint32_t nrow = np * 16 + ((lane >> 4) << 3) + (lane & 7);
            uint32_t kb = j * 32 + (((lane >> 3) & 1) << 4);
            uint32_t vb[4];
            LDSM_X4(vb[0], vb[1], vb[2], vb[3], sb + AVT + nrow * 272 + kb);
#pragma unroll
            for (int mt = 0; mt < 2; mt++) {
                MMA16816(av[mt][2 * np],     pa[mt], vb[0], vb[1]);
                MMA16816(av[mt][2 * np + 1], pa[mt], vb[2], vb[3]);
            }
        }
    }

#pragma unroll
    for (int mt = 0; mt < 2; mt++) {
        int row = b * Mc + wm + mt * 16 + (lane >> 2);
#pragma unroll
        for (int nd = 0; nd < 4; nd++) {
            int col = head * DHc + nd * 8 + (lane & 3) * 2;
            float i0 = rinv[mt * 2 + 0], i1 = rinv[mt * 2 + 1];
            *(uint32_t*)(g_ad16 + (size_t)row * Hc + col) =
                pack_f2h(av[mt][nd][0] * i0, av[mt][nd][1] * i0);
            *(uint32_t*)(g_ad16 + (size_t)(row + 8) * Hc + col) =
                pack_f2h(av[mt][nd][2] * i1, av[mt][nd][3] * i1);
        }
    }
}

// ---------------- host orchestration ----------------
static inline int cdiv(long a, int b) { return (int)((a + b - 1) / b); }

extern "C" void kernel_launch(void* const* d_in, const int* in_sizes, int n_in,
                              void* d_out, int out_size) {
    const float* h         = (const float*)d_in[0];
    const float* gin_w1    = (const float*)d_in[1];
    const float* gin_b1    = (const float*)d_in[2];
    const float* gin_w2    = (const float*)d_in[3];
    const float* gin_b2    = (const float*)d_in[4];
    const float* in_proj_w = (const float*)d_in[5];
    const float* in_proj_b = (const float*)d_in[6];
    const float* out_proj_w= (const float*)d_in[7];
    const float* out_proj_b= (const float*)d_in[8];
    const float* bnl_g     = (const float*)d_in[9];
    const float* bnl_b     = (const float*)d_in[10];
    const float* bna_g     = (const float*)d_in[11];
    const float* bna_b     = (const float*)d_in[12];
    const float* bno_g     = (const float*)d_in[13];
    const float* bno_b     = (const float*)d_in[14];
    const float* ffn1_w    = (const float*)d_in[15];
    const float* ffn1_b    = (const float*)d_in[16];
    const float* ffn2_w    = (const float*)d_in[17];
    const float* ffn2_b    = (const float*)d_in[18];
    const int*   e_src     = (const int*)d_in[19];
    const int*   e_dst     = (const int*)d_in[20];
    const int*   bnn       = (const int*)d_in[21];

    const int nN = in_sizes[0] / Hc;
    const int nE = in_sizes[19];
    const int n4 = nN * H4c;
    const float invN = 1.0f / (float)nN;

    float *p_PL, *p_PA, *p_hh, *p_st;
    int *p_inv;
    __half *p_wh, *p_h16, *p_ha16, *p_z116, *p_qkv16, *p_ad16, *p_hh16, *p_f116;
    cudaGetSymbolAddress((void**)&p_PL,    g_PL);
    cudaGetSymbolAddress((void**)&p_PA,    g_PA);
    cudaGetSymbolAddress((void**)&p_hh,    g_hh);
    cudaGetSymbolAddress((void**)&p_st,    g_bnstats);
    cudaGetSymbolAddress((void**)&p_inv,   g_inv);
    cudaGetSymbolAddress((void**)&p_wh,    g_wh);
    cudaGetSymbolAddress((void**)&p_h16,   g_h16);
    cudaGetSymbolAddress((void**)&p_ha16,  g_ha16);
    cudaGetSymbolAddress((void**)&p_z116,  g_z116);
    cudaGetSymbolAddress((void**)&p_qkv16, g_qkv16);
    cudaGetSymbolAddress((void**)&p_ad16,  g_ad16);
    cudaGetSymbolAddress((void**)&p_hh16,  g_hh16);
    cudaGetSymbolAddress((void**)&p_f116,  g_f116);

    float* st_l = p_st;
    float* st_a = p_st + 2 * Hc;
    float* st_o = p_st + 4 * Hc;

    cudaFuncSetAttribute(mma_gemm<true>,  cudaFuncAttributeMaxDynamicSharedMemorySize, GEMM_SMEM);
    cudaFuncSetAttribute(mma_gemm<false>, cudaFuncAttributeMaxDynamicSharedMemorySize, GEMM_SMEM);

    const int OFF_GIN1 = 0;
    const int OFF_GIN2 = 65536;
    const int OFF_QKV  = 131072;
    const int OFF_OUT  = 327680;
    const int OFF_F1   = 393216;
    const int OFF_F2   = 524288;

    auto gemm = [&](bool relu, const __half* A, const int* a_inv, int woff,
                    const float* bias, const float* res, const int* c_inv,
                    float* C32, __half* C16, float* stats, int Nc, int K) {
        dim3 grid(Nc / 128, nN / 128);
        if (relu)
            mma_gemm<true><<<grid, 256, GEMM_SMEM>>>(A, a_inv, p_wh + woff,
                bias, res, c_inv, C32, C16, stats, Nc, K);
        else
            mma_gemm<false><<<grid, 256, GEMM_SMEM>>>(A, a_inv, p_wh + woff,
                bias, res, c_inv, C32, C16, stats, Nc, K);
    };

    // 0: weights + deg zero + inv + stats zero
    wsplit_all<<<768, 256>>>(gin_w1, gin_w2, in_proj_w, out_proj_w, ffn1_w, ffn2_w, bnn);
    // 1: h->fp16 + edge histogram
    h_split<<<cdiv(n4, 256), 256>>>(h, n4, e_dst, nE);
    // 2: CSR scan
    csr_scan<<<1, 1024>>>();
    // 3: qkv GEMM (fp16 output only) <-- ncu target
    gemm(false, p_h16, p_inv, OFF_QKV, in_proj_b, nullptr, nullptr,
         nullptr, p_qkv16, nullptr, 3 * Hc, Hc);
    // 4-5: CSR fill + gather (fp16 source)
    csr_fill<<<cdiv(nE, 256), 256>>>(e_src, e_dst, nE);
    gather_k<<<nN / 8, 256>>>();
    // 6-7: GIN branch
    gemm(true,  p_ha16, nullptr, OFF_GIN1, gin_b1, nullptr, nullptr,
         nullptr, p_z116, nullptr, Hc, Hc);
    gemm(false, p_z116, nullptr, OFF_GIN2, gin_b2, h, nullptr,
         p_PL, nullptr, st_l, Hc, Hc);
    // 8-9: attention tail
    attn_mma<<<Bc * NHc, 128>>>();
    gemm(false, p_ad16, nullptr, OFF_OUT, out_proj_b, h, p_inv,
         p_PA, nullptr, st_a, Hc, Hc);
    // 10: combine BNs
    bn_combine<<<cdiv(n4, 256), 256>>>(p_PL, p_PA, bnl_g, bnl_b, bna_g, bna_b,
                                       st_l, st_a, p_hh, invN, n4);
    // 11-12: FFN (ffn2 emits fp16 PO into ad16, now free)
    gemm(true,  p_hh16, nullptr, OFF_F1, ffn1_b, nullptr, nullptr,
         nullptr, p_f116, nullptr, 2 * Hc, Hc);
    gemm(false, p_f116, nullptr, OFF_F2, ffn2_b, p_hh, nullptr,
         nullptr, p_ad16, st_o, Hc, 2 * Hc);
    // 13: final BN from fp16
    bn_apply16<<<cdiv(n4, 256), 256>>>(p_ad16, st_o, bno_g, bno_b,
                                       (float*)d_out, invN, n4);
}

// round 14
// speedup vs baseline: 1.2506x; 1.1584x over previous
#include <cuda_runtime.h>
#include <cuda_bf16.h>
#include <cuda_fp16.h>
#include <cstdint>
#include <cstdio>

// ---------------- problem constants ----------------
#define Hc   256
#define H4c  64
#define Bc   256
#define Mc   128
#define NHc  8
#define DHc  32
#define NMAX 32768
#define EMAX 524288

// ---------------- device scratch -------------------
__device__ float g_PL    [NMAX * Hc];
__device__ float g_PA    [NMAX * Hc];
__device__ float g_hh    [NMAX * Hc];
__device__ float g_bnstats[3 * 2 * Hc];
__device__ int   g_inv   [Bc * Mc];
__device__ int   g_mask  [Bc * Mc];
// CSR by destination
__device__ int   g_deg   [NMAX];
__device__ int   g_cs    [NMAX + 1];
__device__ int   g_cur   [NMAX];
__device__ int   g_csrc  [EMAX];
#define WTOT 655360
__device__ __align__(16) __half g_wh[WTOT];
// fp16 activation buffers
__device__ __align__(16) __half g_h16  [NMAX * Hc];
__device__ __align__(16) __half g_ha16 [NMAX * Hc];
__device__ __align__(16) __half g_z116 [NMAX * Hc];
__device__ __align__(16) __half g_qkv16[Bc * Mc * 3 * Hc];
__device__ __align__(16) __half g_ad16 [NMAX * Hc];   // attn out, later reused as PO16
__device__ __align__(16) __half g_hh16 [NMAX * Hc];
__device__ __align__(16) __half g_f116 [NMAX * 2 * Hc];
__device__ __align__(16) __half g_zrow[64];

// ---------------- PTX helpers ----------------------
__device__ __forceinline__ uint32_t smem_u32(const void* p) {
    uint32_t a;
    asm("{ .reg .u64 t; cvta.to.shared.u64 t, %1; cvt.u32.u64 %0, t; }"
        : "=r"(a) : "l"(p));
    return a;
}
#define LDSM_X4(r0, r1, r2, r3, addr)                                    \
    asm volatile("ldmatrix.sync.aligned.m8n8.x4.shared.b16 {%0,%1,%2,%3}, [%4];" \
                 : "=r"(r0), "=r"(r1), "=r"(r2), "=r"(r3) : "r"(addr))
#define MMA16816(d, a, b0, b1)                                           \
    asm volatile("mma.sync.aligned.m16n8k16.row.col.f32.f16.f16.f32 "    \
                 "{%0,%1,%2,%3}, {%4,%5,%6,%7}, {%8,%9}, {%0,%1,%2,%3};" \
                 : "+f"((d)[0]), "+f"((d)[1]), "+f"((d)[2]), "+f"((d)[3]) \
                 : "r"((a)[0]), "r"((a)[1]), "r"((a)[2]), "r"((a)[3]),   \
                   "r"(b0), "r"(b1))
#define CP_ASYNC16(dst, src)                                             \
    asm volatile("cp.async.ca.shared.global [%0], [%1], 16;" :: "r"(dst), "l"(src))
#define CP_COMMIT() asm volatile("cp.async.commit_group;")
#define CP_WAIT0()  asm volatile("cp.async.wait_group 0;" ::: "memory")

__device__ __forceinline__ uint32_t pack_h2(__half a, __half b) {
    __half2 p{a, b};
    return *(uint32_t*)&p;
}
__device__ __forceinline__ uint32_t pack_f2h(float a, float b) {
    return pack_h2(__float2half_rn(a), __float2half_rn(b));
}
__device__ __forceinline__ float ex2f(float x) {
    float y;
    asm("ex2.approx.ftz.f32 %0, %1;" : "=f"(y) : "f"(x));
    return y;
}
__device__ __forceinline__ uint2 cvt4(float4 v) {
    return make_uint2(pack_f2h(v.x, v.y), pack_f2h(v.z, v.w));
}

// ---------------- single-pass fp16 GEMM ------------
#define ROWB 80
#define OFF_A 0
#define OFF_B 10240
#define BUFSZ 20480
#define GEMM_SMEM (2 * BUFSZ)

template<bool RELU>
__global__ __launch_bounds__(256, 2)
void mma_gemm(const __half* __restrict__ A, const int* __restrict__ a_inv,
              const __half* __restrict__ W, const float* __restrict__ bias,
              const float* __restrict__ res, const int* __restrict__ c_inv,
              float* __restrict__ C32, __half* __restrict__ C16,
              float* __restrict__ stats, int Nc, int K) {
    extern __shared__ char smem[];
    const uint32_t sb = smem_u32(smem);
    const int tid = threadIdx.x;
    const int wid = tid >> 5, lane = tid & 31;
    const int wm = (wid >> 1) * 32, wn = (wid & 1) * 64;
    const int row0 = blockIdx.y * 128;
    const int col0 = blockIdx.x * 128;
    const int r = tid >> 1, half = tid & 1;

    const __half* pA;
    bool avalid = true;
    {
        int arow = row0 + r;
        if (a_inv) {
            int nd = a_inv[arow];
            avalid = nd >= 0;
            pA = A + (size_t)(avalid ? nd : 0) * K;
        } else {
            pA = A + (size_t)arow * K;
        }
    }

    float acc[2][8][4];
#pragma unroll
    for (int mt = 0; mt < 2; mt++)
#pragma unroll
        for (int nt = 0; nt < 8; nt++)
#pragma unroll
            for (int q = 0; q < 4; q++) acc[mt][nt][q] = 0.f;

    const int nit = K >> 5;

    auto issue = [&](int i) {
        const uint32_t bo = (uint32_t)(i & 1) * BUFSZ;
        const int k0 = i * 32;
        const char* sA = avalid ? (const char*)(pA + k0 + half * 16)
                                : (const char*)(g_zrow + half * 16);
        uint32_t dA = sb + bo + OFF_A + r * ROWB + half * 32;
        CP_ASYNC16(dA, sA); CP_ASYNC16(dA + 16, sA + 16);
        const char* gb = (const char*)(W + (size_t)(col0 + r) * K + k0 + half * 16);
        uint32_t dB = sb + bo + OFF_B + r * ROWB + half * 32;
        CP_ASYNC16(dB, gb); CP_ASYNC16(dB + 16, gb + 16);
        CP_COMMIT();
    };

    issue(0);
    for (int i = 0; i < nit; i++) {
        const uint32_t boff = (uint32_t)(i & 1) * BUFSZ;
        CP_WAIT0();
        __syncthreads();
        if (i + 1 < nit) issue(i + 1);
#pragma unroll
        for (int ks = 0; ks < 2; ks++) {
            uint32_t ah[2][4];
#pragma unroll
            for (int mt = 0; mt < 2; mt++) {
                uint32_t arow = wm + mt * 16 + (lane & 15);
                uint32_t kb = ks * 32 + ((lane >> 4) * 16);
                LDSM_X4(ah[mt][0], ah[mt][1], ah[mt][2], ah[mt][3],
                        sb + boff + OFF_A + arow * ROWB + kb);
            }
#pragma unroll
            for (int np = 0; np < 4; np++) {
                uint32_t nrow = wn + np * 16 + ((lane >> 4) << 3) + (lane & 7);
                uint32_t kb = ks * 32 + (((lane >> 3) & 1) << 4);
                uint32_t bh[4];
                LDSM_X4(bh[0], bh[1], bh[2], bh[3],
                        sb + boff + OFF_B + nrow * ROWB + kb);
#pragma unroll
                for (int mt = 0; mt < 2; mt++) {
                    MMA16816(acc[mt][2 * np],     ah[mt], bh[0], bh[1]);
                    MMA16816(acc[mt][2 * np + 1], ah[mt], bh[2], bh[3]);
                }
            }
        }
    }
    __syncthreads();

    // ---- epilogue ----
    float* ssum = (float*)smem;
    float* ssq  = ssum + 128;
    if (stats) {
        if (tid < 128) { ssum[tid] = 0.f; ssq[tid] = 0.f; }
        __syncthreads();
    }
    int rA0 = row0 + wm + (lane >> 2);
    int nmap[2][2];
    if (c_inv) {
        nmap[0][0] = c_inv[rA0];      nmap[0][1] = c_inv[rA0 + 8];
        nmap[1][0] = c_inv[rA0 + 16]; nmap[1][1] = c_inv[rA0 + 24];
    }
#pragma unroll
    for (int nt = 0; nt < 8; nt++) {
        int c = col0 + wn + nt * 8 + (lane & 3) * 2;
        float2 bi = *(const float2*)(bias + c);
        float cs0 = 0.f, cs1 = 0.f, cq0 = 0.f, cq1 = 0.f;
#pragma unroll
        for (int mt = 0; mt < 2; mt++) {
            int ra = rA0 + mt * 16;
            float o0 = acc[mt][nt][0] + bi.x, o1 = acc[mt][nt][1] + bi.y;
            float o2 = acc[mt][nt][2] + bi.x, o3 = acc[mt][nt][3] + bi.y;
            if (c_inv) {
                int na = nmap[mt][0], nb = nmap[mt][1];
                if (na >= 0) {
                    float2 rv = *(const float2*)(res + (size_t)na * Nc + c);
                    o0 += rv.x; o1 += rv.y;
                    *(float2*)(C32 + (size_t)na * Nc + c) = make_float2(o0, o1);
                    cs0 += o0; cq0 += o0 * o0; cs1 += o1; cq1 += o1 * o1;
                }
                if (nb >= 0) {
                    float2 rv = *(const float2*)(res + (size_t)nb * Nc + c);
                    o2 += rv.x; o3 += rv.y;
                    *(float2*)(C32 + (size_t)nb * Nc + c) = make_float2(o2, o3);
                    cs0 += o2; cq0 += o2 * o2; cs1 += o3; cq1 += o3 * o3;
                }
            } else {
                if (res) {
                    float2 r0 = *(const float2*)(res + (size_t)ra * Nc + c);
                    float2 r1 = *(const float2*)(res + (size_t)(ra + 8) * Nc + c);
                    o0 += r0.x; o1 += r0.y; o2 += r1.x; o3 += r1.y;
                }
                if (RELU) {
                    o0 = fmaxf(o0, 0.f); o1 = fmaxf(o1, 0.f);
                    o2 = fmaxf(o2, 0.f); o3 = fmaxf(o3, 0.f);
                }
                if (C32) {
                    *(float2*)(C32 + (size_t)ra * Nc + c) = make_float2(o0, o1);
                    *(float2*)(C32 + (size_t)(ra + 8) * Nc + c) = make_float2(o2, o3);
                }
                if (C16) {
                    *(uint32_t*)(C16 + (size_t)ra * Nc + c) = pack_f2h(o0, o1);
                    *(uint32_t*)(C16 + (size_t)(ra + 8) * Nc + c) = pack_f2h(o2, o3);
                }
                if (stats) {
                    cs0 += o0 + o2; cq0 += o0 * o0 + o2 * o2;
                    cs1 += o1 + o3; cq1 += o1 * o1 + o3 * o3;
                }
            }
        }
        if (stats) {
            int lc = c - col0;
            atomicAdd(&ssum[lc], cs0); atomicAdd(&ssq[lc], cq0);
            atomicAdd(&ssum[lc + 1], cs1); atomicAdd(&ssq[lc + 1], cq1);
        }
    }
    if (stats) {
        __syncthreads();
        if (tid < 128) {
            atomicAdd(&stats[col0 + tid], ssum[tid]);
            atomicAdd(&stats[Hc + col0 + tid], ssq[tid]);
        }
    }
}

// ---------------- weight convert + deg zero + inv fused ---------
__global__ void wsplit_all(const float* w0, const float* w1, const float* w2,
                           const float* w3, const float* w4, const float* w5,
                           const int* __restrict__ bnn) {
    int blk = blockIdx.x;
    int t = threadIdx.x;
    if (blk >= 640) {
        __shared__ int sm[256];
        sm[t] = bnn[t];
        __syncthreads();
        for (int off = 1; off < 256; off <<= 1) {
            int v = sm[t] + ((t >= off) ? sm[t - off] : 0);
            __syncthreads();
            sm[t] = v;
            __syncthreads();
        }
        int s = (blk - 640) * 256 + t;
        int b = s >> 7, rr = s & (Mc - 1);
        int cumb = (b == 0) ? 0 : sm[b - 1];
        int nb = sm[b] - cumb;
        bool v = rr < nb;
        g_inv[s] = v ? (cumb + rr) : -1;
        g_mask[s] = v ? 1 : 0;
        if (blk == 640) {
            for (int i = t; i < 6 * Hc; i += 256) g_bnstats[i] = 0.f;
        }
        return;
    }
    int gid = blk * 256 + t;
    if (gid < NMAX) g_deg[gid] = 0;
    const float* W; int sblk; int oel;
    if      (blk < 64)  { W = w0; sblk = 0;   oel = 0;      }
    else if (blk < 128) { W = w1; sblk = 64;  oel = 65536;  }
    else if (blk < 320) { W = w2; sblk = 128; oel = 131072; }
    else if (blk < 384) { W = w3; sblk = 320; oel = 327680; }
    else if (blk < 512) { W = w4; sblk = 384; oel = 393216; }
    else                { W = w5; sblk = 512; oel = 524288; }
    int i4 = (blk - sblk) * 256 + t;
    float4 v = ((const float4*)W)[i4];
    ((uint2*)(g_wh + oel))[i4] = cvt4(v);
}

// h -> fp16, plus edge histogram fused
__global__ void h_split(const float* __restrict__ h, int n4,
                        const int* __restrict__ dst, int E) {
    int gid = blockIdx.x * 256 + threadIdx.x;
    if (gid < n4)
        ((uint2*)g_h16)[gid] = cvt4(((const float4*)h)[gid]);
    if (gid < E)
        atomicAdd(&g_deg[dst[gid]], 1);
}

// ---------------- CSR build ------------------------
__global__ void csr_scan() {
    __shared__ int sm[1024];
    int t = threadIdx.x;
    int base = t * 32;
    int loc[32];
    int s = 0;
#pragma unroll
    for (int i = 0; i < 32; i++) { loc[i] = s; s += g_deg[base + i]; }
    sm[t] = s;
    __syncthreads();
    for (int off = 1; off < 1024; off <<= 1) {
        int v = sm[t] + ((t >= off) ? sm[t - off] : 0);
        __syncthreads();
        sm[t] = v;
        __syncthreads();
    }
    int pref = (t == 0) ? 0 : sm[t - 1];
#pragma unroll
    for (int i = 0; i < 32; i++) {
        int v = pref + loc[i];
        g_cs[base + i] = v;
        g_cur[base + i] = v;
    }
    if (t == 1023) g_cs[NMAX] = sm[1023];
}

__global__ void csr_fill(const int* __restrict__ src, const int* __restrict__ dst, int E) {
    int e = blockIdx.x * 256 + threadIdx.x;
    if (e >= E) return;
    int d = dst[e];
    int pos = atomicAdd(&g_cur[d], 1);
    g_csrc[pos] = src[e];
}

// ---------------- fused gather (from fp16) + convert ----
__global__ __launch_bounds__(256)
void gather_k() {
    int w = blockIdx.x * 8 + (threadIdx.x >> 5);
    int lane = threadIdx.x & 31;
    const uint4* hr = (const uint4*)(g_h16 + (size_t)w * Hc) + lane;
    float s[8];
    {
        uint4 v = *hr;
        const __half2* h2 = (const __half2*)&v;
#pragma unroll
        for (int j = 0; j < 4; j++) {
            float2 f = __half22float2(h2[j]);
            s[j * 2] = f.x; s[j * 2 + 1] = f.y;
        }
    }
    int beg = g_cs[w], end = g_cs[w + 1];
    for (int e = beg; e < end; e++) {
        int src = __ldg(&g_csrc[e]);
        uint4 v = __ldg((const uint4*)(g_h16 + (size_t)src * Hc) + lane);
        const __half2* h2 = (const __half2*)&v;
#pragma unroll
        for (int j = 0; j < 4; j++) {
            float2 f = __half22float2(h2[j]);
            s[j * 2] += f.x; s[j * 2 + 1] += f.y;
        }
    }
    uint4 o;
    o.x = pack_f2h(s[0], s[1]); o.y = pack_f2h(s[2], s[3]);
    o.z = pack_f2h(s[4], s[5]); o.w = pack_f2h(s[6], s[7]);
    *((uint4*)(g_ha16 + (size_t)w * Hc) + lane) = o;
}

// ---------------- BN kernels ------------------------
__device__ __forceinline__ float4 bn4(float4 x, float4 s, float4 q,
                                      float4 g, float4 b, float invN) {
    float4 o;
    { float m = s.x * invN, v = q.x * invN - m * m; o.x = g.x * (x.x - m) * rsqrtf(v + 1e-5f) + b.x; }
    { float m = s.y * invN, v = q.y * invN - m * m; o.y = g.y * (x.y - m) * rsqrtf(v + 1e-5f) + b.y; }
    { float m = s.z * invN, v = q.z * invN - m * m; o.z = g.z * (x.z - m) * rsqrtf(v + 1e-5f) + b.z; }
    { float m = s.w * invN, v = q.w * invN - m * m; o.w = g.w * (x.w - m) * rsqrtf(v + 1e-5f) + b.w; }
    return o;
}

__global__ void bn_combine(const float* __restrict__ PL, const float* __restrict__ PA,
                           const float* __restrict__ gl, const float* __restrict__ bl,
                           const float* __restrict__ ga, const float* __restrict__ ba,
                           const float* __restrict__ stl, const float* __restrict__ sta,
                           float* __restrict__ out, float invN, int n4tot) {
    int gid = blockIdx.x * 256 + threadIdx.x;
    if (gid >= n4tot) return;
    int c4 = gid & 63;
    float4 a = bn4(((const float4*)PL)[gid], ((const float4*)stl)[c4],
                   ((const float4*)stl)[H4c + c4], ((const float4*)gl)[c4],
                   ((const float4*)bl)[c4], invN);
    float4 b = bn4(((const float4*)PA)[gid], ((const float4*)sta)[c4],
                   ((const float4*)sta)[H4c + c4], ((const float4*)ga)[c4],
                   ((const float4*)ba)[c4], invN);
    a.x += b.x; a.y += b.y; a.z += b.z; a.w += b.w;
    ((float4*)out)[gid] = a;
    ((uint2*)g_hh16)[gid] = cvt4(a);
}

__global__ void bn_apply16(const __half* __restrict__ X16, const float* __restrict__ st,
                           const float* __restrict__ gamma, const float* __restrict__ beta,
                           float* __restrict__ out, float invN, int n4total) {
    int gid = blockIdx.x * 256 + threadIdx.x;
    if (gid >= n4total) return;
    int c4 = gid & 63;
    uint2 xv = ((const uint2*)X16)[gid];
    const __half2* h2 = (const __half2*)&xv;
    float2 f0 = __half22float2(h2[0]), f1 = __half22float2(h2[1]);
    float4 x = make_float4(f0.x, f0.y, f1.x, f1.y);
    float4 o = bn4(x, ((const float4*)st)[c4],
                   ((const float4*)st)[H4c + c4], ((const float4*)gamma)[c4],
                   ((const float4*)beta)[c4], invN);
    ((float4*)out)[gid] = o;
}

// ---------------- tensor-core attention (all fp16 in) ----
#define AQ   0
#define AKS  10240
#define AVT  20480
#define AMB  29184
#define ASMEM 29696

__global__ __launch_bounds__(128)
void attn_mma() {
    __shared__ char smem[ASMEM];
    const uint32_t sb = smem_u32(smem);
    const int b = blockIdx.x >> 3;
    const int head = blockIdx.x & 7;
    const int tid = threadIdx.x;
    const int wid = tid >> 5, lane = tid & 31;
    const int wm = wid * 32;

    const float sc2 = 0.17677669529663687f * 1.44269504088896341f;

    {
        const __half* base = g_qkv16 + (size_t)(b * Mc + tid) * (3 * Hc);
        const uint4* qp = (const uint4*)(base + head * DHc);
        const uint4* kp = (const uint4*)(base + Hc + head * DHc);
        const uint4* vp = (const uint4*)(base + 2 * Hc + head * DHc);
        __half2 s2 = __float2half2_rn(sc2);
        __half* vt = (__half*)(smem + AVT);
#pragma unroll
        for (int j = 0; j < 4; j++) {
            uint4 q = qp[j];
            __half2* qh = (__half2*)&q;
#pragma unroll
            for (int u = 0; u < 4; u++) qh[u] = __hmul2(qh[u], s2);
            *(uint4*)(smem + AQ + tid * ROWB + j * 16) = q;
            *(uint4*)(smem + AKS + tid * ROWB + j * 16) = kp[j];
            uint4 v = vp[j];
            const __half* vh = (const __half*)&v;
#pragma unroll
            for (int u = 0; u < 8; u++)
                vt[(j * 8 + u) * 136 + tid] = vh[u];
        }
        ((float*)(smem + AMB))[tid] = g_mask[b * Mc + tid] ? 0.f : -1e30f;
    }
    __syncthreads();

    float sc[2][16][4];
#pragma unroll
    for (int mt = 0; mt < 2; mt++)
#pragma unroll
        for (int nt = 0; nt < 16; nt++)
#pragma unroll
            for (int q = 0; q < 4; q++) sc[mt][nt][q] = 0.f;

#pragma unroll
    for (int ks = 0; ks < 2; ks++) {
        uint32_t ah[2][4];
#pragma unroll
        for (int mt = 0; mt < 2; mt++) {
            uint32_t arow = wm + mt * 16 + (lane & 15);
            uint32_t kb = ks * 32 + ((lane >> 4) * 16);
            LDSM_X4(ah[mt][0], ah[mt][1], ah[mt][2], ah[mt][3],
                    sb + AQ + arow * ROWB + kb);
        }
#pragma unroll
        for (int np = 0; np < 8; np++) {
            uint32_t nrow = np * 16 + ((lane >> 4) << 3) + (lane & 7);
            uint32_t kb = ks * 32 + (((lane >> 3) & 1) << 4);
            uint32_t bh[4];
            LDSM_X4(bh[0], bh[1], bh[2], bh[3], sb + AKS + nrow * ROWB + kb);
#pragma unroll
            for (int mt = 0; mt < 2; mt++) {
                MMA16816(sc[mt][2 * np],     ah[mt], bh[0], bh[1]);
                MMA16816(sc[mt][2 * np + 1], ah[mt], bh[2], bh[3]);
            }
        }
    }

    const float* mb = (const float*)(smem + AMB);
#pragma unroll
    for (int nt = 0; nt < 16; nt++) {
        float2 mp = *(const float2*)(mb + nt * 8 + (lane & 3) * 2);
#pragma unroll
        for (int mt = 0; mt < 2; mt++) {
            sc[mt][nt][0] += mp.x; sc[mt][nt][1] += mp.y;
            sc[mt][nt][2] += mp.x; sc[mt][nt][3] += mp.y;
        }
    }
    float rinv[4];
#pragma unroll
    for (int rg = 0; rg < 4; rg++) {
        const int mt = rg >> 1, off = (rg & 1) * 2;
        float m = -3.0e38f;
#pragma unroll
        for (int nt = 0; nt < 16; nt++)
            m = fmaxf(m, fmaxf(sc[mt][nt][off], sc[mt][nt][off + 1]));
        m = fmaxf(m, __shfl_xor_sync(0xffffffff, m, 1));
        m = fmaxf(m, __shfl_xor_sync(0xffffffff, m, 2));
        float l = 0.f;
#pragma unroll
        for (int nt = 0; nt < 16; nt++) {
            float p0 = ex2f(sc[mt][nt][off] - m);
            float p1 = ex2f(sc[mt][nt][off + 1] - m);
            sc[mt][nt][off] = p0; sc[mt][nt][off + 1] = p1;
            l += p0 + p1;
        }
        l += __shfl_xor_sync(0xffffffff, l, 1);
        l += __shfl_xor_sync(0xffffffff, l, 2);
        rinv[rg] = 1.f / l;
    }

    float av[2][4][4];
#pragma unroll
    for (int mt = 0; mt < 2; mt++)
#pragma unroll
        for (int nd = 0; nd < 4; nd++)
#pragma unroll
            for (int q = 0; q < 4; q++) av[mt][nd][q] = 0.f;

#pragma unroll
    for (int j = 0; j < 8; j++) {
        uint32_t pa[2][4];
#pragma unroll
        for (int mt = 0; mt < 2; mt++) {
            pa[mt][0] = pack_f2h(sc[mt][2 * j][0],     sc[mt][2 * j][1]);
            pa[mt][1] = pack_f2h(sc[mt][2 * j][2],     sc[mt][2 * j][3]);
            pa[mt][2] = pack_f2h(sc[mt][2 * j + 1][0], sc[mt][2 * j + 1][1]);
            pa[mt][3] = pack_f2h(sc[mt][2 * j + 1][2], sc[mt][2 * j + 1][3]);
        }
#pragma unroll
        for (int np = 0; np < 2; np++) {
            uint32_t nrow = np * 16 + ((lane >> 4) << 3) + (lane & 7);
            uint32_t kb = j * 32 + (((lane >> 3) & 1) << 4);
            uint32_t vb[4];
            LDSM_X4(vb[0], vb[1], vb[2], vb[3], sb + AVT + nrow * 272 + kb);
#pragma unroll
            for (int mt = 0; mt < 2; mt++) {
                MMA16816(av[mt][2 * np],     pa[mt], vb[0], vb[1]);
                MMA16816(av[mt][2 * np + 1], pa[mt], vb[2], vb[3]);
            }
        }
    }

#pragma unroll
    for (int mt = 0; mt < 2; mt++) {
        int row = b * Mc + wm + mt * 16 + (lane >> 2);
#pragma unroll
        for (int nd = 0; nd < 4; nd++) {
            int col = head * DHc + nd * 8 + (lane & 3) * 2;
            float i0 = rinv[mt * 2 + 0], i1 = rinv[mt * 2 + 1];
            *(uint32_t*)(g_ad16 + (size_t)row * Hc + col) =
                pack_f2h(av[mt][nd][0] * i0, av[mt][nd][1] * i0);
            *(uint32_t*)(g_ad16 + (size_t)(row + 8) * Hc + col) =
                pack_f2h(av[mt][nd][2] * i1, av[mt][nd][3] * i1);
        }
    }
}

// ---------------- host orchestration ----------------
static inline int cdiv(long a, int b) { return (int)((a + b - 1) / b); }

extern "C" void kernel_launch(void* const* d_in, const int* in_sizes, int n_in,
                              void* d_out, int out_size) {
    const float* h         = (const float*)d_in[0];
    const float* gin_w1    = (const float*)d_in[1];
    const float* gin_b1    = (const float*)d_in[2];
    const float* gin_w2    = (const float*)d_in[3];
    const float* gin_b2    = (const float*)d_in[4];
    const float* in_proj_w = (const float*)d_in[5];
    const float* in_proj_b = (const float*)d_in[6];
    const float* out_proj_w= (const float*)d_in[7];
    const float* out_proj_b= (const float*)d_in[8];
    const float* bnl_g     = (const float*)d_in[9];
    const float* bnl_b     = (const float*)d_in[10];
    const float* bna_g     = (const float*)d_in[11];
    const float* bna_b     = (const float*)d_in[12];
    const float* bno_g     = (const float*)d_in[13];
    const float* bno_b     = (const float*)d_in[14];
    const float* ffn1_w    = (const float*)d_in[15];
    const float* ffn1_b    = (const float*)d_in[16];
    const float* ffn2_w    = (const float*)d_in[17];
    const float* ffn2_b    = (const float*)d_in[18];
    const int*   e_src     = (const int*)d_in[19];
    const int*   e_dst     = (const int*)d_in[20];
    const int*   bnn       = (const int*)d_in[21];

    const int nN = in_sizes[0] / Hc;
    const int nE = in_sizes[19];
    const int n4 = nN * H4c;
    const float invN = 1.0f / (float)nN;

    float *p_PL, *p_PA, *p_hh, *p_st;
    int *p_inv;
    __half *p_wh, *p_h16, *p_ha16, *p_z116, *p_qkv16, *p_ad16, *p_hh16, *p_f116;
    cudaGetSymbolAddress((void**)&p_PL,    g_PL);
    cudaGetSymbolAddress((void**)&p_PA,    g_PA);
    cudaGetSymbolAddress((void**)&p_hh,    g_hh);
    cudaGetSymbolAddress((void**)&p_st,    g_bnstats);
    cudaGetSymbolAddress((void**)&p_inv,   g_inv);
    cudaGetSymbolAddress((void**)&p_wh,    g_wh);
    cudaGetSymbolAddress((void**)&p_h16,   g_h16);
    cudaGetSymbolAddress((void**)&p_ha16,  g_ha16);
    cudaGetSymbolAddress((void**)&p_z116,  g_z116);
    cudaGetSymbolAddress((void**)&p_qkv16, g_qkv16);
    cudaGetSymbolAddress((void**)&p_ad16,  g_ad16);
    cudaGetSymbolAddress((void**)&p_hh16,  g_hh16);
    cudaGetSymbolAddress((void**)&p_f116,  g_f116);

    float* st_l = p_st;
    float* st_a = p_st + 2 * Hc;
    float* st_o = p_st + 4 * Hc;

    cudaFuncSetAttribute(mma_gemm<true>,  cudaFuncAttributeMaxDynamicSharedMemorySize, GEMM_SMEM);
    cudaFuncSetAttribute(mma_gemm<false>, cudaFuncAttributeMaxDynamicSharedMemorySize, GEMM_SMEM);

    // side stream + fork/join events: created ONCE on the first (non-capture)
    // correctness call; reused (and re-captured) on the capture call.
    static cudaStream_t s_side = nullptr;
    static cudaEvent_t  e_fork = nullptr, e_join = nullptr;
    if (s_side == nullptr) {
        cudaStreamCreateWithFlags(&s_side, cudaStreamNonBlocking);
        cudaEventCreateWithFlags(&e_fork, cudaEventDisableTiming);
        cudaEventCreateWithFlags(&e_join, cudaEventDisableTiming);
    }

    const int OFF_GIN1 = 0;
    const int OFF_GIN2 = 65536;
    const int OFF_QKV  = 131072;
    const int OFF_OUT  = 327680;
    const int OFF_F1   = 393216;
    const int OFF_F2   = 524288;

    auto gemm = [&](cudaStream_t st, bool relu, const __half* A, const int* a_inv,
                    int woff, const float* bias, const float* res, const int* c_inv,
                    float* C32, __half* C16, float* stats, int Nc, int K) {
        dim3 grid(Nc / 128, nN / 128);
        if (relu)
            mma_gemm<true><<<grid, 256, GEMM_SMEM, st>>>(A, a_inv, p_wh + woff,
                bias, res, c_inv, C32, C16, stats, Nc, K);
        else
            mma_gemm<false><<<grid, 256, GEMM_SMEM, st>>>(A, a_inv, p_wh + woff,
                bias, res, c_inv, C32, C16, stats, Nc, K);
    };

    // ---- serial prologue on legacy stream ----
    wsplit_all<<<768, 256>>>(gin_w1, gin_w2, in_proj_w, out_proj_w, ffn1_w, ffn2_w, bnn);
    h_split<<<cdiv(n4, 256), 256>>>(h, n4, e_dst, nE);

    // ---- fork: GIN branch on side stream, attention branch on legacy ----
    cudaEventRecord(e_fork, 0);
    cudaStreamWaitEvent(s_side, e_fork, 0);

    // legacy stream: attention branch
    gemm(0, false, p_h16, p_inv, OFF_QKV, in_proj_b, nullptr, nullptr,
         nullptr, p_qkv16, nullptr, 3 * Hc, Hc);
    attn_mma<<<Bc * NHc, 128>>>();
    gemm(0, false, p_ad16, nullptr, OFF_OUT, out_proj_b, h, p_inv,
         p_PA, nullptr, st_a, Hc, Hc);

    // side stream: CSR + GIN branch
    csr_scan<<<1, 1024, 0, s_side>>>();
    csr_fill<<<cdiv(nE, 256), 256, 0, s_side>>>(e_src, e_dst, nE);
    gather_k<<<nN / 8, 256, 0, s_side>>>();
    gemm(s_side, true,  p_ha16, nullptr, OFF_GIN1, gin_b1, nullptr, nullptr,
         nullptr, p_z116, nullptr, Hc, Hc);
    gemm(s_side, false, p_z116, nullptr, OFF_GIN2, gin_b2, h, nullptr,
         p_PL, nullptr, st_l, Hc, Hc);

    // ---- join back onto legacy ----
    cudaEventRecord(e_join, s_side);
    cudaStreamWaitEvent(0, e_join, 0);

    // ---- tail: combine + FFN + final norm ----
    bn_combine<<<cdiv(n4, 256), 256>>>(p_PL, p_PA, bnl_g, bnl_b, bna_g, bna_b,
                                       st_l, st_a, p_hh, invN, n4);
    gemm(0, true,  p_hh16, nullptr, OFF_F1, ffn1_b, nullptr, nullptr,
         nullptr, p_f116, nullptr, 2 * Hc, Hc);
    gemm(0, false, p_f116, nullptr, OFF_F2, ffn2_b, p_hh, nullptr,
         nullptr, p_ad16, st_o, Hc, 2 * Hc);
    bn_apply16<<<cdiv(n4, 256), 256>>>(p_ad16, st_o, bno_g, bno_b,
                                       (float*)d_out, invN, n4);
}

// round 15
// speedup vs baseline: 1.2812x; 1.0245x over previous
#include <cuda_runtime.h>
#include <cuda_bf16.h>
#include <cuda_fp16.h>
#include <cstdint>
#include <cstdio>

// ---------------- problem constants ----------------
#define Hc   256
#define H4c  64
#define Bc   256
#define Mc   128
#define NHc  8
#define DHc  32
#define NMAX 32768
#define EMAX 524288

// ---------------- device scratch -------------------
__device__ float g_PL    [NMAX * Hc];
__device__ float g_PA    [NMAX * Hc];
__device__ float g_hh    [NMAX * Hc];
__device__ float g_bnstats[3 * 2 * Hc];
__device__ int   g_inv   [Bc * Mc];
__device__ int   g_mask  [Bc * Mc];
__device__ int   g_deg   [NMAX];
__device__ int   g_cs    [NMAX + 1];
__device__ int   g_cur   [NMAX];
__device__ int   g_csrc  [EMAX];
#define WTOT 655360
__device__ __align__(16) __half g_wh[WTOT];
__device__ __align__(16) __half g_h16  [NMAX * Hc];
__device__ __align__(16) __half g_ha16 [NMAX * Hc];
__device__ __align__(16) __half g_z116 [NMAX * Hc];
__device__ __align__(16) __half g_qkv16[Bc * Mc * 3 * Hc];
__device__ __align__(16) __half g_ad16 [NMAX * Hc];   // attn out; later PO16
__device__ __align__(16) __half g_hh16 [NMAX * Hc];
__device__ __align__(16) __half g_f116 [NMAX * 2 * Hc];
__device__ __align__(16) __half g_zrow[64];

// ---------------- PTX helpers ----------------------
__device__ __forceinline__ uint32_t smem_u32(const void* p) {
    uint32_t a;
    asm("{ .reg .u64 t; cvta.to.shared.u64 t, %1; cvt.u32.u64 %0, t; }"
        : "=r"(a) : "l"(p));
    return a;
}
#define LDSM_X4(r0, r1, r2, r3, addr)                                    \
    asm volatile("ldmatrix.sync.aligned.m8n8.x4.shared.b16 {%0,%1,%2,%3}, [%4];" \
                 : "=r"(r0), "=r"(r1), "=r"(r2), "=r"(r3) : "r"(addr))
#define MMA16816(d, a, b0, b1)                                           \
    asm volatile("mma.sync.aligned.m16n8k16.row.col.f32.f16.f16.f32 "    \
                 "{%0,%1,%2,%3}, {%4,%5,%6,%7}, {%8,%9}, {%0,%1,%2,%3};" \
                 : "+f"((d)[0]), "+f"((d)[1]), "+f"((d)[2]), "+f"((d)[3]) \
                 : "r"((a)[0]), "r"((a)[1]), "r"((a)[2]), "r"((a)[3]),   \
                   "r"(b0), "r"(b1))
#define CP_ASYNC16(dst, src)                                             \
    asm volatile("cp.async.ca.shared.global [%0], [%1], 16;" :: "r"(dst), "l"(src))
#define CP_COMMIT() asm volatile("cp.async.commit_group;")
#define CP_WAIT0()  asm volatile("cp.async.wait_group 0;" ::: "memory")

__device__ __forceinline__ uint32_t pack_h2(__half a, __half b) {
    __half2 p{a, b};
    return *(uint32_t*)&p;
}
__device__ __forceinline__ uint32_t pack_f2h(float a, float b) {
    return pack_h2(__float2half_rn(a), __float2half_rn(b));
}
__device__ __forceinline__ float ex2f(float x) {
    float y;
    asm("ex2.approx.ftz.f32 %0, %1;" : "=f"(y) : "f"(x));
    return y;
}
__device__ __forceinline__ uint2 cvt4(float4 v) {
    return make_uint2(pack_f2h(v.x, v.y), pack_f2h(v.z, v.w));
}

// ---------------- single-pass fp16 GEMM ------------
#define ROWB 80
#define OFF_A 0
#define OFF_B 10240
#define BUFSZ 20480
#define GEMM_SMEM (2 * BUFSZ)

template<bool RELU>
__global__ __launch_bounds__(256, 2)
void mma_gemm(const __half* __restrict__ A, const int* __restrict__ a_inv,
              const __half* __restrict__ W, const float* __restrict__ bias,
              const float* __restrict__ res, const int* __restrict__ c_inv,
              float* __restrict__ C32, __half* __restrict__ C16,
              float* __restrict__ stats, int Nc, int K) {
    extern __shared__ char smem[];
    const uint32_t sb = smem_u32(smem);
    const int tid = threadIdx.x;
    const int wid = tid >> 5, lane = tid & 31;
    const int wm = (wid >> 1) * 32, wn = (wid & 1) * 64;
    const int row0 = blockIdx.y * 128;
    const int col0 = blockIdx.x * 128;
    const int r = tid >> 1, half = tid & 1;

    const __half* pA;
    bool avalid = true;
    {
        int arow = row0 + r;
        if (a_inv) {
            int nd = a_inv[arow];
            avalid = nd >= 0;
            pA = A + (size_t)(avalid ? nd : 0) * K;
        } else {
            pA = A + (size_t)arow * K;
        }
    }

    float acc[2][8][4];
#pragma unroll
    for (int mt = 0; mt < 2; mt++)
#pragma unroll
        for (int nt = 0; nt < 8; nt++)
#pragma unroll
            for (int q = 0; q < 4; q++) acc[mt][nt][q] = 0.f;

    const int nit = K >> 5;

    auto issue = [&](int i) {
        const uint32_t bo = (uint32_t)(i & 1) * BUFSZ;
        const int k0 = i * 32;
        const char* sA = avalid ? (const char*)(pA + k0 + half * 16)
                                : (const char*)(g_zrow + half * 16);
        uint32_t dA = sb + bo + OFF_A + r * ROWB + half * 32;
        CP_ASYNC16(dA, sA); CP_ASYNC16(dA + 16, sA + 16);
        const char* gb = (const char*)(W + (size_t)(col0 + r) * K + k0 + half * 16);
        uint32_t dB = sb + bo + OFF_B + r * ROWB + half * 32;
        CP_ASYNC16(dB, gb); CP_ASYNC16(dB + 16, gb + 16);
        CP_COMMIT();
    };

    issue(0);
    for (int i = 0; i < nit; i++) {
        const uint32_t boff = (uint32_t)(i & 1) * BUFSZ;
        CP_WAIT0();
        __syncthreads();
        if (i + 1 < nit) issue(i + 1);
#pragma unroll
        for (int ks = 0; ks < 2; ks++) {
            uint32_t ah[2][4];
#pragma unroll
            for (int mt = 0; mt < 2; mt++) {
                uint32_t arow = wm + mt * 16 + (lane & 15);
                uint32_t kb = ks * 32 + ((lane >> 4) * 16);
                LDSM_X4(ah[mt][0], ah[mt][1], ah[mt][2], ah[mt][3],
                        sb + boff + OFF_A + arow * ROWB + kb);
            }
#pragma unroll
            for (int np = 0; np < 4; np++) {
                uint32_t nrow = wn + np * 16 + ((lane >> 4) << 3) + (lane & 7);
                uint32_t kb = ks * 32 + (((lane >> 3) & 1) << 4);
                uint32_t bh[4];
                LDSM_X4(bh[0], bh[1], bh[2], bh[3],
                        sb + boff + OFF_B + nrow * ROWB + kb);
#pragma unroll
                for (int mt = 0; mt < 2; mt++) {
                    MMA16816(acc[mt][2 * np],     ah[mt], bh[0], bh[1]);
                    MMA16816(acc[mt][2 * np + 1], ah[mt], bh[2], bh[3]);
                }
            }
        }
    }
    __syncthreads();

    // ---- epilogue ----
    float* ssum = (float*)smem;
    float* ssq  = ssum + 128;
    if (stats) {
        if (tid < 128) { ssum[tid] = 0.f; ssq[tid] = 0.f; }
        __syncthreads();
    }
    int rA0 = row0 + wm + (lane >> 2);
    int nmap[2][2];
    if (c_inv) {
        nmap[0][0] = c_inv[rA0];      nmap[0][1] = c_inv[rA0 + 8];
        nmap[1][0] = c_inv[rA0 + 16]; nmap[1][1] = c_inv[rA0 + 24];
    }
#pragma unroll
    for (int nt = 0; nt < 8; nt++) {
        int c = col0 + wn + nt * 8 + (lane & 3) * 2;
        float2 bi = *(const float2*)(bias + c);
        float cs0 = 0.f, cs1 = 0.f, cq0 = 0.f, cq1 = 0.f;
#pragma unroll
        for (int mt = 0; mt < 2; mt++) {
            int ra = rA0 + mt * 16;
            float o0 = acc[mt][nt][0] + bi.x, o1 = acc[mt][nt][1] + bi.y;
            float o2 = acc[mt][nt][2] + bi.x, o3 = acc[mt][nt][3] + bi.y;
            if (c_inv) {
                int na = nmap[mt][0], nb = nmap[mt][1];
                if (na >= 0) {
                    float2 rv = *(const float2*)(res + (size_t)na * Nc + c);
                    o0 += rv.x; o1 += rv.y;
                    *(float2*)(C32 + (size_t)na * Nc + c) = make_float2(o0, o1);
                    cs0 += o0; cq0 += o0 * o0; cs1 += o1; cq1 += o1 * o1;
                }
                if (nb >= 0) {
                    float2 rv = *(const float2*)(res + (size_t)nb * Nc + c);
                    o2 += rv.x; o3 += rv.y;
                    *(float2*)(C32 + (size_t)nb * Nc + c) = make_float2(o2, o3);
                    cs0 += o2; cq0 += o2 * o2; cs1 += o3; cq1 += o3 * o3;
                }
            } else {
                if (res) {
                    float2 r0 = *(const float2*)(res + (size_t)ra * Nc + c);
                    float2 r1 = *(const float2*)(res + (size_t)(ra + 8) * Nc + c);
                    o0 += r0.x; o1 += r0.y; o2 += r1.x; o3 += r1.y;
                }
                if (RELU) {
                    o0 = fmaxf(o0, 0.f); o1 = fmaxf(o1, 0.f);
                    o2 = fmaxf(o2, 0.f); o3 = fmaxf(o3, 0.f);
                }
                if (C32) {
                    *(float2*)(C32 + (size_t)ra * Nc + c) = make_float2(o0, o1);
                    *(float2*)(C32 + (size_t)(ra + 8) * Nc + c) = make_float2(o2, o3);
                }
                if (C16) {
                    *(uint32_t*)(C16 + (size_t)ra * Nc + c) = pack_f2h(o0, o1);
                    *(uint32_t*)(C16 + (size_t)(ra + 8) * Nc + c) = pack_f2h(o2, o3);
                }
                if (stats) {
                    cs0 += o0 + o2; cq0 += o0 * o0 + o2 * o2;
                    cs1 += o1 + o3; cq1 += o1 * o1 + o3 * o3;
                }
            }
        }
        if (stats) {
            int lc = c - col0;
            atomicAdd(&ssum[lc], cs0); atomicAdd(&ssq[lc], cq0);
            atomicAdd(&ssum[lc + 1], cs1); atomicAdd(&ssq[lc + 1], cq1);
        }
    }
    if (stats) {
        __syncthreads();
        if (tid < 128) {
            atomicAdd(&stats[col0 + tid], ssum[tid]);
            atomicAdd(&stats[Hc + col0 + tid], ssq[tid]);
        }
    }
}

// ---------------- weight convert + deg zero + inv fused ---------
__global__ void wsplit_all(const float* w0, const float* w1, const float* w2,
                           const float* w3, const float* w4, const float* w5,
                           const int* __restrict__ bnn) {
    int blk = blockIdx.x;
    int t = threadIdx.x;
    if (blk >= 640) {
        __shared__ int sm[256];
        sm[t] = bnn[t];
        __syncthreads();
        for (int off = 1; off < 256; off <<= 1) {
            int v = sm[t] + ((t >= off) ? sm[t - off] : 0);
            __syncthreads();
            sm[t] = v;
            __syncthreads();
        }
        int s = (blk - 640) * 256 + t;
        int b = s >> 7, rr = s & (Mc - 1);
        int cumb = (b == 0) ? 0 : sm[b - 1];
        int nb = sm[b] - cumb;
        bool v = rr < nb;
        g_inv[s] = v ? (cumb + rr) : -1;
        g_mask[s] = v ? 1 : 0;
        if (blk == 640) {
            for (int i = t; i < 6 * Hc; i += 256) g_bnstats[i] = 0.f;
        }
        return;
    }
    int gid = blk * 256 + t;
    if (gid < NMAX) g_deg[gid] = 0;
    const float* W; int sblk; int oel;
    if      (blk < 64)  { W = w0; sblk = 0;   oel = 0;      }
    else if (blk < 128) { W = w1; sblk = 64;  oel = 65536;  }
    else if (blk < 320) { W = w2; sblk = 128; oel = 131072; }
    else if (blk < 384) { W = w3; sblk = 320; oel = 327680; }
    else if (blk < 512) { W = w4; sblk = 384; oel = 393216; }
    else                { W = w5; sblk = 512; oel = 524288; }
    int i4 = (blk - sblk) * 256 + t;
    float4 v = ((const float4*)W)[i4];
    ((uint2*)(g_wh + oel))[i4] = cvt4(v);
}

// h -> fp16, plus edge histogram fused
__global__ void h_split(const float* __restrict__ h, int n4,
                        const int* __restrict__ dst, int E) {
    int gid = blockIdx.x * 256 + threadIdx.x;
    if (gid < n4)
        ((uint2*)g_h16)[gid] = cvt4(((const float4*)h)[gid]);
    if (gid < E)
        atomicAdd(&g_deg[dst[gid]], 1);
}

// ---------------- CSR build ------------------------
__global__ void csr_scan() {
    __shared__ int sm[1024];
    int t = threadIdx.x;
    int base = t * 32;
    int loc[32];
    int s = 0;
#pragma unroll
    for (int i = 0; i < 32; i++) { loc[i] = s; s += g_deg[base + i]; }
    sm[t] = s;
    __syncthreads();
    for (int off = 1; off < 1024; off <<= 1) {
        int v = sm[t] + ((t >= off) ? sm[t - off] : 0);
        __syncthreads();
        sm[t] = v;
        __syncthreads();
    }
    int pref = (t == 0) ? 0 : sm[t - 1];
#pragma unroll
    for (int i = 0; i < 32; i++) {
        int v = pref + loc[i];
        g_cs[base + i] = v;
        g_cur[base + i] = v;
    }
    if (t == 1023) g_cs[NMAX] = sm[1023];
}

__global__ void csr_fill(const int* __restrict__ src, const int* __restrict__ dst, int E) {
    int e = blockIdx.x * 256 + threadIdx.x;
    if (e >= E) return;
    int d = dst[e];
    int pos = atomicAdd(&g_cur[d], 1);
    g_csrc[pos] = src[e];
}

// ---------------- fused gather (from fp16) ----------
__global__ __launch_bounds__(256)
void gather_k() {
    int w = blockIdx.x * 8 + (threadIdx.x >> 5);
    int lane = threadIdx.x & 31;
    const uint4* hr = (const uint4*)(g_h16 + (size_t)w * Hc) + lane;
    float s[8];
    {
        uint4 v = *hr;
        const __half2* h2 = (const __half2*)&v;
#pragma unroll
        for (int j = 0; j < 4; j++) {
            float2 f = __half22float2(h2[j]);
            s[j * 2] = f.x; s[j * 2 + 1] = f.y;
        }
    }
    int beg = g_cs[w], end = g_cs[w + 1];
    for (int e = beg; e < end; e++) {
        int src = __ldg(&g_csrc[e]);
        uint4 v = __ldg((const uint4*)(g_h16 + (size_t)src * Hc) + lane);
        const __half2* h2 = (const __half2*)&v;
#pragma unroll
        for (int j = 0; j < 4; j++) {
            float2 f = __half22float2(h2[j]);
            s[j * 2] += f.x; s[j * 2 + 1] += f.y;
        }
    }
    uint4 o;
    o.x = pack_f2h(s[0], s[1]); o.y = pack_f2h(s[2], s[3]);
    o.z = pack_f2h(s[4], s[5]); o.w = pack_f2h(s[6], s[7]);
    *((uint4*)(g_ha16 + (size_t)w * Hc) + lane) = o;
}

// ---------------- BN kernels ------------------------
__device__ __forceinline__ float4 bn4(float4 x, float4 s, float4 q,
                                      float4 g, float4 b, float invN) {
    float4 o;
    { float m = s.x * invN, v = q.x * invN - m * m; o.x = g.x * (x.x - m) * rsqrtf(v + 1e-5f) + b.x; }
    { float m = s.y * invN, v = q.y * invN - m * m; o.y = g.y * (x.y - m) * rsqrtf(v + 1e-5f) + b.y; }
    { float m = s.z * invN, v = q.z * invN - m * m; o.z = g.z * (x.z - m) * rsqrtf(v + 1e-5f) + b.z; }
    { float m = s.w * invN, v = q.w * invN - m * m; o.w = g.w * (x.w - m) * rsqrtf(v + 1e-5f) + b.w; }
    return o;
}

// bn_combine over a row range [base4, base4+cnt4) of float4 indices
__global__ void bn_combine(const float* __restrict__ PL, const float* __restrict__ PA,
                           const float* __restrict__ gl, const float* __restrict__ bl,
                           const float* __restrict__ ga, const float* __restrict__ ba,
                           const float* __restrict__ stl, const float* __restrict__ sta,
                           float* __restrict__ out, float invN, int base4, int cnt4) {
    int gid = base4 + blockIdx.x * 256 + threadIdx.x;
    if (gid >= base4 + cnt4) return;
    int c4 = gid & 63;
    float4 a = bn4(((const float4*)PL)[gid], ((const float4*)stl)[c4],
                   ((const float4*)stl)[H4c + c4], ((const float4*)gl)[c4],
                   ((const float4*)bl)[c4], invN);
    float4 b = bn4(((const float4*)PA)[gid], ((const float4*)sta)[c4],
                   ((const float4*)sta)[H4c + c4], ((const float4*)ga)[c4],
                   ((const float4*)ba)[c4], invN);
    a.x += b.x; a.y += b.y; a.z += b.z; a.w += b.w;
    ((float4*)out)[gid] = a;
    ((uint2*)g_hh16)[gid] = cvt4(a);
}

__global__ void bn_apply16(const __half* __restrict__ X16, const float* __restrict__ st,
                           const float* __restrict__ gamma, const float* __restrict__ beta,
                           float* __restrict__ out, float invN, int n4total) {
    int gid = blockIdx.x * 256 + threadIdx.x;
    if (gid >= n4total) return;
    int c4 = gid & 63;
    uint2 xv = ((const uint2*)X16)[gid];
    const __half2* h2 = (const __half2*)&xv;
    float2 f0 = __half22float2(h2[0]), f1 = __half22float2(h2[1]);
    float4 x = make_float4(f0.x, f0.y, f1.x, f1.y);
    float4 o = bn4(x, ((const float4*)st)[c4],
                   ((const float4*)st)[H4c + c4], ((const float4*)gamma)[c4],
                   ((const float4*)beta)[c4], invN);
    ((float4*)out)[gid] = o;
}

// ---------------- tensor-core attention (online softmax, 2 halves) ----
#define AQ   0
#define AKS  10240
#define AVT  20480
#define AMB  29184
#define ASMEM 29696

__global__ __launch_bounds__(128)
void attn_mma() {
    __shared__ char smem[ASMEM];
    const uint32_t sb = smem_u32(smem);
    const int b = blockIdx.x >> 3;
    const int head = blockIdx.x & 7;
    const int tid = threadIdx.x;
    const int wid = tid >> 5, lane = tid & 31;
    const int wm = wid * 32;

    const float sc2 = 0.17677669529663687f * 1.44269504088896341f;

    {
        const __half* base = g_qkv16 + (size_t)(b * Mc + tid) * (3 * Hc);
        const uint4* qp = (const uint4*)(base + head * DHc);
        const uint4* kp = (const uint4*)(base + Hc + head * DHc);
        const uint4* vp = (const uint4*)(base + 2 * Hc + head * DHc);
        __half2 s2 = __float2half2_rn(sc2);
        __half* vt = (__half*)(smem + AVT);
#pragma unroll
        for (int j = 0; j < 4; j++) {
            uint4 q = qp[j];
            __half2* qh = (__half2*)&q;
#pragma unroll
            for (int u = 0; u < 4; u++) qh[u] = __hmul2(qh[u], s2);
            *(uint4*)(smem + AQ + tid * ROWB + j * 16) = q;
            *(uint4*)(smem + AKS + tid * ROWB + j * 16) = kp[j];
            uint4 v = vp[j];
            const __half* vh = (const __half*)&v;
#pragma unroll
            for (int u = 0; u < 8; u++)
                vt[(j * 8 + u) * 136 + tid] = vh[u];
        }
        ((float*)(smem + AMB))[tid] = g_mask[b * Mc + tid] ? 0.f : -1e30f;
    }
    __syncthreads();

    float m[4], l[4];
#pragma unroll
    for (int rg = 0; rg < 4; rg++) { m[rg] = -3.0e38f; l[rg] = 0.f; }
    float av[2][4][4];
#pragma unroll
    for (int mt = 0; mt < 2; mt++)
#pragma unroll
        for (int nd = 0; nd < 4; nd++)
#pragma unroll
            for (int q = 0; q < 4; q++) av[mt][nd][q] = 0.f;

    const float* mb = (const float*)(smem + AMB);

#pragma unroll
    for (int hf = 0; hf < 2; hf++) {
        // ---- scores for key columns [hf*64, hf*64+64) ----
        float sch[2][8][4];
#pragma unroll
        for (int mt = 0; mt < 2; mt++)
#pragma unroll
            for (int nt = 0; nt < 8; nt++)
#pragma unroll
                for (int q = 0; q < 4; q++) sch[mt][nt][q] = 0.f;

#pragma unroll
        for (int ks = 0; ks < 2; ks++) {
            uint32_t ah[2][4];
#pragma unroll
            for (int mt = 0; mt < 2; mt++) {
                uint32_t arow = wm + mt * 16 + (lane & 15);
                uint32_t kb = ks * 32 + ((lane >> 4) * 16);
                LDSM_X4(ah[mt][0], ah[mt][1], ah[mt][2], ah[mt][3],
                        sb + AQ + arow * ROWB + kb);
            }
#pragma unroll
            for (int npl = 0; npl < 4; npl++) {
                uint32_t nrow = hf * 64 + npl * 16 + ((lane >> 4) << 3) + (lane & 7);
                uint32_t kb = ks * 32 + (((lane >> 3) & 1) << 4);
                uint32_t bh[4];
                LDSM_X4(bh[0], bh[1], bh[2], bh[3], sb + AKS + nrow * ROWB + kb);
#pragma unroll
                for (int mt = 0; mt < 2; mt++) {
                    MMA16816(sch[mt][2 * npl],     ah[mt], bh[0], bh[1]);
                    MMA16816(sch[mt][2 * npl + 1], ah[mt], bh[2], bh[3]);
                }
            }
        }
        // mask bias
#pragma unroll
        for (int nt = 0; nt < 8; nt++) {
            float2 mp = *(const float2*)(mb + hf * 64 + nt * 8 + (lane & 3) * 2);
#pragma unroll
            for (int mt = 0; mt < 2; mt++) {
                sch[mt][nt][0] += mp.x; sch[mt][nt][1] += mp.y;
                sch[mt][nt][2] += mp.x; sch[mt][nt][3] += mp.y;
            }
        }
        // online softmax update per row group
#pragma unroll
        for (int rg = 0; rg < 4; rg++) {
            const int mt = rg >> 1, off = (rg & 1) * 2;
            float mh = -3.0e38f;
#pragma unroll
            for (int nt = 0; nt < 8; nt++)
                mh = fmaxf(mh, fmaxf(sch[mt][nt][off], sch[mt][nt][off + 1]));
            mh = fmaxf(mh, __shfl_xor_sync(0xffffffff, mh, 1));
            mh = fmaxf(mh, __shfl_xor_sync(0xffffffff, mh, 2));
            float mnew = fmaxf(m[rg], mh);
            float corr = ex2f(m[rg] - mnew);
            float lh = 0.f;
#pragma unroll
            for (int nt = 0; nt < 8; nt++) {
                float p0 = ex2f(sch[mt][nt][off] - mnew);
                float p1 = ex2f(sch[mt][nt][off + 1] - mnew);
                sch[mt][nt][off] = p0; sch[mt][nt][off + 1] = p1;
                lh += p0 + p1;
            }
            lh += __shfl_xor_sync(0xffffffff, lh, 1);
            lh += __shfl_xor_sync(0xffffffff, lh, 2);
            l[rg] = l[rg] * corr + lh;
            m[rg] = mnew;
#pragma unroll
            for (int nd = 0; nd < 4; nd++) {
                av[mt][nd][off] *= corr;
                av[mt][nd][off + 1] *= corr;
            }
        }
        // P @ V^T for this half
#pragma unroll
        for (int jl = 0; jl < 4; jl++) {
            uint32_t pa[2][4];
#pragma unroll
            for (int mt = 0; mt < 2; mt++) {
                pa[mt][0] = pack_f2h(sch[mt][2 * jl][0],     sch[mt][2 * jl][1]);
                pa[mt][1] = pack_f2h(sch[mt][2 * jl][2],     sch[mt][2 * jl][3]);
                pa[mt][2] = pack_f2h(sch[mt][2 * jl + 1][0], sch[mt][2 * jl + 1][1]);
                pa[mt][3] = pack_f2h(sch[mt][2 * jl + 1][2], sch[mt][2 * jl + 1][3]);
            }
#pragma unroll
            for (int np = 0; np < 2; np++) {
                uint32_t nrow = np * 16 + ((lane >> 4) << 3) + (lane & 7);
                uint32_t kb = (hf * 4 + jl) * 32 + (((lane >> 3) & 1) << 4);
                uint32_t vb[4];
                LDSM_X4(vb[0], vb[1], vb[2], vb[3], sb + AVT + nrow * 272 + kb);
#pragma unroll
                for (int mt = 0; mt < 2; mt++) {
                    MMA16816(av[mt][2 * np],     pa[mt], vb[0], vb[1]);
                    MMA16816(av[mt][2 * np + 1], pa[mt], vb[2], vb[3]);
                }
            }
        }
    }

#pragma unroll
    for (int mt = 0; mt < 2; mt++) {
        int row = b * Mc + wm + mt * 16 + (lane >> 2);
        float i0 = 1.f / l[mt * 2 + 0], i1 = 1.f / l[mt * 2 + 1];
#pragma unroll
        for (int nd = 0; nd < 4; nd++) {
            int col = head * DHc + nd * 8 + (lane & 3) * 2;
            *(uint32_t*)(g_ad16 + (size_t)row * Hc + col) =
                pack_f2h(av[mt][nd][0] * i0, av[mt][nd][1] * i0);
            *(uint32_t*)(g_ad16 + (size_t)(row + 8) * Hc + col) =
                pack_f2h(av[mt][nd][2] * i1, av[mt][nd][3] * i1);
        }
    }
}

// ---------------- host orchestration ----------------
static inline int cdiv(long a, int b) { return (int)((a + b - 1) / b); }

extern "C" void kernel_launch(void* const* d_in, const int* in_sizes, int n_in,
                              void* d_out, int out_size) {
    const float* h         = (const float*)d_in[0];
    const float* gin_w1    = (const float*)d_in[1];
    const float* gin_b1    = (const float*)d_in[2];
    const float* gin_w2    = (const float*)d_in[3];
    const float* gin_b2    = (const float*)d_in[4];
    const float* in_proj_w = (const float*)d_in[5];
    const float* in_proj_b = (const float*)d_in[6];
    const float* out_proj_w= (const float*)d_in[7];
    const float* out_proj_b= (const float*)d_in[8];
    const float* bnl_g     = (const float*)d_in[9];
    const float* bnl_b     = (const float*)d_in[10];
    const float* bna_g     = (const float*)d_in[11];
    const float* bna_b     = (const float*)d_in[12];
    const float* bno_g     = (const float*)d_in[13];
    const float* bno_b     = (const float*)d_in[14];
    const float* ffn1_w    = (const float*)d_in[15];
    const float* ffn1_b    = (const float*)d_in[16];
    const float* ffn2_w    = (const float*)d_in[17];
    const float* ffn2_b    = (const float*)d_in[18];
    const int*   e_src     = (const int*)d_in[19];
    const int*   e_dst     = (const int*)d_in[20];
    const int*   bnn       = (const int*)d_in[21];

    const int nN = in_sizes[0] / Hc;
    const int nE = in_sizes[19];
    const int n4 = nN * H4c;
    const float invN = 1.0f / (float)nN;
    const int halfN = nN / 2;           // row split for tail pipelining

    float *p_PL, *p_PA, *p_hh, *p_st;
    int *p_inv;
    __half *p_wh, *p_h16, *p_ha16, *p_z116, *p_qkv16, *p_ad16, *p_hh16, *p_f116;
    cudaGetSymbolAddress((void**)&p_PL,    g_PL);
    cudaGetSymbolAddress((void**)&p_PA,    g_PA);
    cudaGetSymbolAddress((void**)&p_hh,    g_hh);
    cudaGetSymbolAddress((void**)&p_st,    g_bnstats);
    cudaGetSymbolAddress((void**)&p_inv,   g_inv);
    cudaGetSymbolAddress((void**)&p_wh,    g_wh);
    cudaGetSymbolAddress((void**)&p_h16,   g_h16);
    cudaGetSymbolAddress((void**)&p_ha16,  g_ha16);
    cudaGetSymbolAddress((void**)&p_z116,  g_z116);
    cudaGetSymbolAddress((void**)&p_qkv16, g_qkv16);
    cudaGetSymbolAddress((void**)&p_ad16,  g_ad16);
    cudaGetSymbolAddress((void**)&p_hh16,  g_hh16);
    cudaGetSymbolAddress((void**)&p_f116,  g_f116);

    float* st_l = p_st;
    float* st_a = p_st + 2 * Hc;
    float* st_o = p_st + 4 * Hc;

    cudaFuncSetAttribute(mma_gemm<true>,  cudaFuncAttributeMaxDynamicSharedMemorySize, GEMM_SMEM);
    cudaFuncSetAttribute(mma_gemm<false>, cudaFuncAttributeMaxDynamicSharedMemorySize, GEMM_SMEM);

    static cudaStream_t s_side = nullptr;
    static cudaEvent_t  e_fork = nullptr, e_join = nullptr, e_fork2 = nullptr, e_join2 = nullptr;
    if (s_side == nullptr) {
        cudaStreamCreateWithFlags(&s_side, cudaStreamNonBlocking);
        cudaEventCreateWithFlags(&e_fork,  cudaEventDisableTiming);
        cudaEventCreateWithFlags(&e_join,  cudaEventDisableTiming);
        cudaEventCreateWithFlags(&e_fork2, cudaEventDisableTiming);
        cudaEventCreateWithFlags(&e_join2, cudaEventDisableTiming);
    }

    const int OFF_GIN1 = 0;
    const int OFF_GIN2 = 65536;
    const int OFF_QKV  = 131072;
    const int OFF_OUT  = 327680;
    const int OFF_F1   = 393216;
    const int OFF_F2   = 524288;

    auto gemm = [&](cudaStream_t st, bool relu, const __half* A, const int* a_inv,
                    int woff, const float* bias, const float* res, const int* c_inv,
                    float* C32, __half* C16, float* stats, int Nc, int K, int nRows) {
        dim3 grid(Nc / 128, nRows / 128);
        if (relu)
            mma_gemm<true><<<grid, 256, GEMM_SMEM, st>>>(A, a_inv, p_wh + woff,
                bias, res, c_inv, C32, C16, stats, Nc, K);
        else
            mma_gemm<false><<<grid, 256, GEMM_SMEM, st>>>(A, a_inv, p_wh + woff,
                bias, res, c_inv, C32, C16, stats, Nc, K);
    };

    // ---- serial prologue ----
    wsplit_all<<<768, 256>>>(gin_w1, gin_w2, in_proj_w, out_proj_w, ffn1_w, ffn2_w, bnn);
    h_split<<<cdiv(n4, 256), 256>>>(h, n4, e_dst, nE);

    // ---- fork: GIN on side, attention on legacy ----
    cudaEventRecord(e_fork, 0);
    cudaStreamWaitEvent(s_side, e_fork, 0);

    gemm(0, false, p_h16, p_inv, OFF_QKV, in_proj_b, nullptr, nullptr,
         nullptr, p_qkv16, nullptr, 3 * Hc, Hc, nN);
    attn_mma<<<Bc * NHc, 128>>>();
    gemm(0, false, p_ad16, nullptr, OFF_OUT, out_proj_b, h, p_inv,
         p_PA, nullptr, st_a, Hc, Hc, nN);

    csr_scan<<<1, 1024, 0, s_side>>>();
    csr_fill<<<cdiv(nE, 256), 256, 0, s_side>>>(e_src, e_dst, nE);
    gather_k<<<nN / 8, 256, 0, s_side>>>();
    gemm(s_side, true,  p_ha16, nullptr, OFF_GIN1, gin_b1, nullptr, nullptr,
         nullptr, p_z116, nullptr, Hc, Hc, nN);
    gemm(s_side, false, p_z116, nullptr, OFF_GIN2, gin_b2, h, nullptr,
         p_PL, nullptr, st_l, Hc, Hc, nN);

    // ---- join both branches onto legacy ----
    cudaEventRecord(e_join, s_side);
    cudaStreamWaitEvent(0, e_join, 0);

    // ---- tail fork: row halves pipelined on both streams ----
    cudaEventRecord(e_fork2, 0);
    cudaStreamWaitEvent(s_side, e_fork2, 0);

    const int h4 = halfN * H4c;
    // legacy: rows [0, halfN)
    bn_combine<<<cdiv(h4, 256), 256>>>(p_PL, p_PA, bnl_g, bnl_b, bna_g, bna_b,
                                       st_l, st_a, p_hh, invN, 0, h4);
    gemm(0, true,  p_hh16, nullptr, OFF_F1, ffn1_b, nullptr, nullptr,
         nullptr, p_f116, nullptr, 2 * Hc, Hc, halfN);
    gemm(0, false, p_f116, nullptr, OFF_F2, ffn2_b, p_hh, nullptr,
         nullptr, p_ad16, st_o, Hc, 2 * Hc, halfN);
    // side: rows [halfN, nN)
    bn_combine<<<cdiv(h4, 256), 256, 0, s_side>>>(p_PL, p_PA, bnl_g, bnl_b,
                                                  bna_g, bna_b, st_l, st_a,
                                                  p_hh, invN, h4, h4);
    gemm(s_side, true,  p_hh16 + (size_t)halfN * Hc, nullptr, OFF_F1, ffn1_b,
         nullptr, nullptr, nullptr, p_f116 + (size_t)halfN * 2 * Hc, nullptr,
         2 * Hc, Hc, halfN);
    gemm(s_side, false, p_f116 + (size_t)halfN * 2 * Hc, nullptr, OFF_F2, ffn2_b,
         p_hh + (size_t)halfN * Hc, nullptr, nullptr,
         p_ad16 + (size_t)halfN * Hc, st_o, Hc, 2 * Hc, halfN);

    cudaEventRecord(e_join2, s_side);
    cudaStreamWaitEvent(0, e_join2, 0);

    // ---- final BN (needs complete st_o) ----
    bn_apply16<<<cdiv(n4, 256), 256>>>(p_ad16, st_o, bno_g, bno_b,
                                       (float*)d_out, invN, n4);
}

// round 16
// speedup vs baseline: 1.3041x; 1.0179x over previous
#include <cuda_runtime.h>
#include <cuda_bf16.h>
#include <cuda_fp16.h>
#include <cstdint>
#include <cstdio>

// ---------------- problem constants ----------------
#define Hc   256
#define H4c  64
#define Bc   256
#define Mc   128
#define NHc  8
#define DHc  32
#define NMAX 32768
#define EMAX 524288

// ---------------- device scratch -------------------
__device__ float g_hh    [NMAX * Hc];
__device__ float g_bnstats[3 * 2 * Hc];
__device__ int   g_inv   [Bc * Mc];
__device__ int   g_mask  [Bc * Mc];
__device__ int   g_deg   [NMAX];
__device__ int   g_cs    [NMAX + 1];
__device__ int   g_cur   [NMAX];
__device__ int   g_csrc  [EMAX];
#define WTOT 655360
__device__ __align__(16) __half g_wh[WTOT];
__device__ __align__(16) __half g_h16  [NMAX * Hc];
__device__ __align__(16) __half g_ha16 [NMAX * Hc];
__device__ __align__(16) __half g_z116 [NMAX * Hc];
__device__ __align__(16) __half g_qkv16[Bc * Mc * 3 * Hc];
__device__ __align__(16) __half g_ad16 [NMAX * Hc];   // attn out; later PO16
__device__ __align__(16) __half g_hh16 [NMAX * Hc];
__device__ __align__(16) __half g_f116 [NMAX * 2 * Hc];
__device__ __align__(16) __half g_PL16 [NMAX * Hc];
__device__ __align__(16) __half g_PA16 [NMAX * Hc];
__device__ __align__(16) __half g_zrow[64];

// ---------------- PTX helpers ----------------------
__device__ __forceinline__ uint32_t smem_u32(const void* p) {
    uint32_t a;
    asm("{ .reg .u64 t; cvta.to.shared.u64 t, %1; cvt.u32.u64 %0, t; }"
        : "=r"(a) : "l"(p));
    return a;
}
#define LDSM_X4(r0, r1, r2, r3, addr)                                    \
    asm volatile("ldmatrix.sync.aligned.m8n8.x4.shared.b16 {%0,%1,%2,%3}, [%4];" \
                 : "=r"(r0), "=r"(r1), "=r"(r2), "=r"(r3) : "r"(addr))
#define MMA16816(d, a, b0, b1)                                           \
    asm volatile("mma.sync.aligned.m16n8k16.row.col.f32.f16.f16.f32 "    \
                 "{%0,%1,%2,%3}, {%4,%5,%6,%7}, {%8,%9}, {%0,%1,%2,%3};" \
                 : "+f"((d)[0]), "+f"((d)[1]), "+f"((d)[2]), "+f"((d)[3]) \
                 : "r"((a)[0]), "r"((a)[1]), "r"((a)[2]), "r"((a)[3]),   \
                   "r"(b0), "r"(b1))
#define CP_ASYNC16(dst, src)                                             \
    asm volatile("cp.async.ca.shared.global [%0], [%1], 16;" :: "r"(dst), "l"(src))
#define CP_COMMIT() asm volatile("cp.async.commit_group;")
#define CP_WAIT0()  asm volatile("cp.async.wait_group 0;" ::: "memory")

__device__ __forceinline__ uint32_t pack_h2(__half a, __half b) {
    __half2 p{a, b};
    return *(uint32_t*)&p;
}
__device__ __forceinline__ uint32_t pack_f2h(float a, float b) {
    return pack_h2(__float2half_rn(a), __float2half_rn(b));
}
__device__ __forceinline__ float ex2f(float x) {
    float y;
    asm("ex2.approx.ftz.f32 %0, %1;" : "=f"(y) : "f"(x));
    return y;
}
__device__ __forceinline__ uint2 cvt4(float4 v) {
    return make_uint2(pack_f2h(v.x, v.y), pack_f2h(v.z, v.w));
}
__device__ __forceinline__ float4 up4(uint2 x) {
    const __half2* h2 = (const __half2*)&x;
    float2 f0 = __half22float2(h2[0]), f1 = __half22float2(h2[1]);
    return make_float4(f0.x, f0.y, f1.x, f1.y);
}

// ---------------- single-pass fp16 GEMM ------------
#define ROWB 80
#define OFF_A 0
#define OFF_B 10240
#define BUFSZ 20480
#define GEMM_SMEM (2 * BUFSZ)

template<bool RELU>
__global__ __launch_bounds__(256, 2)
void mma_gemm(const __half* __restrict__ A, const int* __restrict__ a_inv,
              const __half* __restrict__ W, const float* __restrict__ bias,
              const float* __restrict__ res, const int* __restrict__ c_inv,
              float* __restrict__ C32, __half* __restrict__ C16,
              float* __restrict__ stats, int Nc, int K) {
    extern __shared__ char smem[];
    const uint32_t sb = smem_u32(smem);
    const int tid = threadIdx.x;
    const int wid = tid >> 5, lane = tid & 31;
    const int wm = (wid >> 1) * 32, wn = (wid & 1) * 64;
    const int row0 = blockIdx.y * 128;
    const int col0 = blockIdx.x * 128;
    const int r = tid >> 1, half = tid & 1;

    const __half* pA;
    bool avalid = true;
    {
        int arow = row0 + r;
        if (a_inv) {
            int nd = a_inv[arow];
            avalid = nd >= 0;
            pA = A + (size_t)(avalid ? nd : 0) * K;
        } else {
            pA = A + (size_t)arow * K;
        }
    }

    float acc[2][8][4];
#pragma unroll
    for (int mt = 0; mt < 2; mt++)
#pragma unroll
        for (int nt = 0; nt < 8; nt++)
#pragma unroll
            for (int q = 0; q < 4; q++) acc[mt][nt][q] = 0.f;

    const int nit = K >> 5;

    auto issue = [&](int i) {
        const uint32_t bo = (uint32_t)(i & 1) * BUFSZ;
        const int k0 = i * 32;
        const char* sA = avalid ? (const char*)(pA + k0 + half * 16)
                                : (const char*)(g_zrow + half * 16);
        uint32_t dA = sb + bo + OFF_A + r * ROWB + half * 32;
        CP_ASYNC16(dA, sA); CP_ASYNC16(dA + 16, sA + 16);
        const char* gb = (const char*)(W + (size_t)(col0 + r) * K + k0 + half * 16);
        uint32_t dB = sb + bo + OFF_B + r * ROWB + half * 32;
        CP_ASYNC16(dB, gb); CP_ASYNC16(dB + 16, gb + 16);
        CP_COMMIT();
    };

    issue(0);
    for (int i = 0; i < nit; i++) {
        const uint32_t boff = (uint32_t)(i & 1) * BUFSZ;
        CP_WAIT0();
        __syncthreads();
        if (i + 1 < nit) issue(i + 1);
#pragma unroll
        for (int ks = 0; ks < 2; ks++) {
            uint32_t ah[2][4];
#pragma unroll
            for (int mt = 0; mt < 2; mt++) {
                uint32_t arow = wm + mt * 16 + (lane & 15);
                uint32_t kb = ks * 32 + ((lane >> 4) * 16);
                LDSM_X4(ah[mt][0], ah[mt][1], ah[mt][2], ah[mt][3],
                        sb + boff + OFF_A + arow * ROWB + kb);
            }
#pragma unroll
            for (int np = 0; np < 4; np++) {
                uint32_t nrow = wn + np * 16 + ((lane >> 4) << 3) + (lane & 7);
                uint32_t kb = ks * 32 + (((lane >> 3) & 1) << 4);
                uint32_t bh[4];
                LDSM_X4(bh[0], bh[1], bh[2], bh[3],
                        sb + boff + OFF_B + nrow * ROWB + kb);
#pragma unroll
                for (int mt = 0; mt < 2; mt++) {
                    MMA16816(acc[mt][2 * np],     ah[mt], bh[0], bh[1]);
                    MMA16816(acc[mt][2 * np + 1], ah[mt], bh[2], bh[3]);
                }
            }
        }
    }
    __syncthreads();

    // ---- epilogue ----
    float* ssum = (float*)smem;
    float* ssq  = ssum + 128;
    if (stats) {
        if (tid < 128) { ssum[tid] = 0.f; ssq[tid] = 0.f; }
        __syncthreads();
    }
    int rA0 = row0 + wm + (lane >> 2);
    int nmap[2][2];
    if (c_inv) {
        nmap[0][0] = c_inv[rA0];      nmap[0][1] = c_inv[rA0 + 8];
        nmap[1][0] = c_inv[rA0 + 16]; nmap[1][1] = c_inv[rA0 + 24];
    }
#pragma unroll
    for (int nt = 0; nt < 8; nt++) {
        int c = col0 + wn + nt * 8 + (lane & 3) * 2;
        float2 bi = *(const float2*)(bias + c);
        float cs0 = 0.f, cs1 = 0.f, cq0 = 0.f, cq1 = 0.f;
#pragma unroll
        for (int mt = 0; mt < 2; mt++) {
            int ra = rA0 + mt * 16;
            float o0 = acc[mt][nt][0] + bi.x, o1 = acc[mt][nt][1] + bi.y;
            float o2 = acc[mt][nt][2] + bi.x, o3 = acc[mt][nt][3] + bi.y;
            if (c_inv) {
                int na = nmap[mt][0], nb = nmap[mt][1];
                if (na >= 0) {
                    float2 rv = *(const float2*)(res + (size_t)na * Nc + c);
                    o0 += rv.x; o1 += rv.y;
                    *(uint32_t*)(C16 + (size_t)na * Nc + c) = pack_f2h(o0, o1);
                    cs0 += o0; cq0 += o0 * o0; cs1 += o1; cq1 += o1 * o1;
                }
                if (nb >= 0) {
                    float2 rv = *(const float2*)(res + (size_t)nb * Nc + c);
                    o2 += rv.x; o3 += rv.y;
                    *(uint32_t*)(C16 + (size_t)nb * Nc + c) = pack_f2h(o2, o3);
                    cs0 += o2; cq0 += o2 * o2; cs1 += o3; cq1 += o3 * o3;
                }
            } else {
                if (res) {
                    float2 r0 = *(const float2*)(res + (size_t)ra * Nc + c);
                    float2 r1 = *(const float2*)(res + (size_t)(ra + 8) * Nc + c);
                    o0 += r0.x; o1 += r0.y; o2 += r1.x; o3 += r1.y;
                }
                if (RELU) {
                    o0 = fmaxf(o0, 0.f); o1 = fmaxf(o1, 0.f);
                    o2 = fmaxf(o2, 0.f); o3 = fmaxf(o3, 0.f);
                }
                if (C32) {
                    *(float2*)(C32 + (size_t)ra * Nc + c) = make_float2(o0, o1);
                    *(float2*)(C32 + (size_t)(ra + 8) * Nc + c) = make_float2(o2, o3);
                }
                if (C16) {
                    *(uint32_t*)(C16 + (size_t)ra * Nc + c) = pack_f2h(o0, o1);
                    *(uint32_t*)(C16 + (size_t)(ra + 8) * Nc + c) = pack_f2h(o2, o3);
                }
                if (stats) {
                    cs0 += o0 + o2; cq0 += o0 * o0 + o2 * o2;
                    cs1 += o1 + o3; cq1 += o1 * o1 + o3 * o3;
                }
            }
        }
        if (stats) {
            int lc = c - col0;
            atomicAdd(&ssum[lc], cs0); atomicAdd(&ssq[lc], cq0);
            atomicAdd(&ssum[lc + 1], cs1); atomicAdd(&ssq[lc + 1], cq1);
        }
    }
    if (stats) {
        __syncthreads();
        if (tid < 128) {
            atomicAdd(&stats[col0 + tid], ssum[tid]);
            atomicAdd(&stats[Hc + col0 + tid], ssq[tid]);
        }
    }
}

// ---------------- weight convert + deg zero + inv fused ---------
__global__ void wsplit_all(const float* w0, const float* w1, const float* w2,
                           const float* w3, const float* w4, const float* w5,
                           const int* __restrict__ bnn) {
    int blk = blockIdx.x;
    int t = threadIdx.x;
    if (blk >= 640) {
        __shared__ int sm[256];
        sm[t] = bnn[t];
        __syncthreads();
        for (int off = 1; off < 256; off <<= 1) {
            int v = sm[t] + ((t >= off) ? sm[t - off] : 0);
            __syncthreads();
            sm[t] = v;
            __syncthreads();
        }
        int s = (blk - 640) * 256 + t;
        int b = s >> 7, rr = s & (Mc - 1);
        int cumb = (b == 0) ? 0 : sm[b - 1];
        int nb = sm[b] - cumb;
        bool v = rr < nb;
        g_inv[s] = v ? (cumb + rr) : -1;
        g_mask[s] = v ? 1 : 0;
        if (blk == 640) {
            for (int i = t; i < 6 * Hc; i += 256) g_bnstats[i] = 0.f;
        }
        return;
    }
    int gid = blk * 256 + t;
    if (gid < NMAX) g_deg[gid] = 0;
    const float* W; int sblk; int oel;
    if      (blk < 64)  { W = w0; sblk = 0;   oel = 0;      }
    else if (blk < 128) { W = w1; sblk = 64;  oel = 65536;  }
    else if (blk < 320) { W = w2; sblk = 128; oel = 131072; }
    else if (blk < 384) { W = w3; sblk = 320; oel = 327680; }
    else if (blk < 512) { W = w4; sblk = 384; oel = 393216; }
    else                { W = w5; sblk = 512; oel = 524288; }
    int i4 = (blk - sblk) * 256 + t;
    float4 v = ((const float4*)W)[i4];
    ((uint2*)(g_wh + oel))[i4] = cvt4(v);
}

// h -> fp16, plus edge histogram fused
__global__ void h_split(const float* __restrict__ h, int n4,
                        const int* __restrict__ dst, int E) {
    int gid = blockIdx.x * 256 + threadIdx.x;
    if (gid < n4)
        ((uint2*)g_h16)[gid] = cvt4(((const float4*)h)[gid]);
    if (gid < E)
        atomicAdd(&g_deg[dst[gid]], 1);
}

// ---------------- CSR build ------------------------
__global__ void csr_scan() {
    __shared__ int sm[1024];
    int t = threadIdx.x;
    int base = t * 32;
    int loc[32];
    int s = 0;
#pragma unroll
    for (int i = 0; i < 32; i++) { loc[i] = s; s += g_deg[base + i]; }
    sm[t] = s;
    __syncthreads();
    for (int off = 1; off < 1024; off <<= 1) {
        int v = sm[t] + ((t >= off) ? sm[t - off] : 0);
        __syncthreads();
        sm[t] = v;
        __syncthreads();
    }
    int pref = (t == 0) ? 0 : sm[t - 1];
#pragma unroll
    for (int i = 0; i < 32; i++) {
        int v = pref + loc[i];
        g_cs[base + i] = v;
        g_cur[base + i] = v;
    }
    if (t == 1023) g_cs[NMAX] = sm[1023];
}

__global__ void csr_fill(const int* __restrict__ src, const int* __restrict__ dst, int E) {
    int e = blockIdx.x * 256 + threadIdx.x;
    if (e >= E) return;
    int d = dst[e];
    int pos = atomicAdd(&g_cur[d], 1);
    g_csrc[pos] = src[e];
}

// ---------------- fused gather (from fp16) ----------
__global__ __launch_bounds__(256)
void gather_k() {
    int w = blockIdx.x * 8 + (threadIdx.x >> 5);
    int lane = threadIdx.x & 31;
    const uint4* hr = (const uint4*)(g_h16 + (size_t)w * Hc) + lane;
    float s[8];
    {
        uint4 v = *hr;
        const __half2* h2 = (const __half2*)&v;
#pragma unroll
        for (int j = 0; j < 4; j++) {
            float2 f = __half22float2(h2[j]);
            s[j * 2] = f.x; s[j * 2 + 1] = f.y;
        }
    }
    int beg = g_cs[w], end = g_cs[w + 1];
    for (int e = beg; e < end; e++) {
        int src = __ldg(&g_csrc[e]);
        uint4 v = __ldg((const uint4*)(g_h16 + (size_t)src * Hc) + lane);
        const __half2* h2 = (const __half2*)&v;
#pragma unroll
        for (int j = 0; j < 4; j++) {
            float2 f = __half22float2(h2[j]);
            s[j * 2] += f.x; s[j * 2 + 1] += f.y;
        }
    }
    uint4 o;
    o.x = pack_f2h(s[0], s[1]); o.y = pack_f2h(s[2], s[3]);
    o.z = pack_f2h(s[4], s[5]); o.w = pack_f2h(s[6], s[7]);
    *((uint4*)(g_ha16 + (size_t)w * Hc) + lane) = o;
}

// ---------------- BN kernels ------------------------
__device__ __forceinline__ float4 bn4(float4 x, float4 s, float4 q,
                                      float4 g, float4 b, float invN) {
    float4 o;
    { float m = s.x * invN, v = q.x * invN - m * m; o.x = g.x * (x.x - m) * rsqrtf(v + 1e-5f) + b.x; }
    { float m = s.y * invN, v = q.y * invN - m * m; o.y = g.y * (x.y - m) * rsqrtf(v + 1e-5f) + b.y; }
    { float m = s.z * invN, v = q.z * invN - m * m; o.z = g.z * (x.z - m) * rsqrtf(v + 1e-5f) + b.z; }
    { float m = s.w * invN, v = q.w * invN - m * m; o.w = g.w * (x.w - m) * rsqrtf(v + 1e-5f) + b.w; }
    return o;
}

// bn_combine over a row range, fp16 inputs
__global__ void bn_combine(const __half* __restrict__ PL16, const __half* __restrict__ PA16,
                           const float* __restrict__ gl, const float* __restrict__ bl,
                           const float* __restrict__ ga, const float* __restrict__ ba,
                           const float* __restrict__ stl, const float* __restrict__ sta,
                           float* __restrict__ out, float invN, int base4, int cnt4) {
    int gid = base4 + blockIdx.x * 256 + threadIdx.x;
    if (gid >= base4 + cnt4) return;
    int c4 = gid & 63;
    float4 a = bn4(up4(((const uint2*)PL16)[gid]), ((const float4*)stl)[c4],
                   ((const float4*)stl)[H4c + c4], ((const float4*)gl)[c4],
                   ((const float4*)bl)[c4], invN);
    float4 b = bn4(up4(((const uint2*)PA16)[gid]), ((const float4*)sta)[c4],
                   ((const float4*)sta)[H4c + c4], ((const float4*)ga)[c4],
                   ((const float4*)ba)[c4], invN);
    a.x += b.x; a.y += b.y; a.z += b.z; a.w += b.w;
    ((float4*)out)[gid] = a;
    ((uint2*)g_hh16)[gid] = cvt4(a);
}

__global__ void bn_apply16(const __half* __restrict__ X16, const float* __restrict__ st,
                           const float* __restrict__ gamma, const float* __restrict__ beta,
                           float* __restrict__ out, float invN, int n4total) {
    int gid = blockIdx.x * 256 + threadIdx.x;
    if (gid >= n4total) return;
    int c4 = gid & 63;
    float4 x = up4(((const uint2*)X16)[gid]);
    float4 o = bn4(x, ((const float4*)st)[c4],
                   ((const float4*)st)[H4c + c4], ((const float4*)gamma)[c4],
                   ((const float4*)beta)[c4], invN);
    ((float4*)out)[gid] = o;
}

// ---------------- tensor-core attention (online softmax, 2 halves) ----
#define AQ   0
#define AKS  10240
#define AVT  20480
#define AMB  29184
#define ASMEM 29696

__global__ __launch_bounds__(128, 3)
void attn_mma() {
    __shared__ char smem[ASMEM];
    const uint32_t sb = smem_u32(smem);
    const int b = blockIdx.x >> 3;
    const int head = blockIdx.x & 7;
    const int tid = threadIdx.x;
    const int wid = tid >> 5, lane = tid & 31;
    const int wm = wid * 32;

    const float sc2 = 0.17677669529663687f * 1.44269504088896341f;

    {
        const __half* base = g_qkv16 + (size_t)(b * Mc + tid) * (3 * Hc);
        const uint4* qp = (const uint4*)(base + head * DHc);
        const uint4* kp = (const uint4*)(base + Hc + head * DHc);
        const uint4* vp = (const uint4*)(base + 2 * Hc + head * DHc);
        __half2 s2 = __float2half2_rn(sc2);
        __half* vt = (__half*)(smem + AVT);
#pragma unroll
        for (int j = 0; j < 4; j++) {
            uint4 q = qp[j];
            __half2* qh = (__half2*)&q;
#pragma unroll
            for (int u = 0; u < 4; u++) qh[u] = __hmul2(qh[u], s2);
            *(uint4*)(smem + AQ + tid * ROWB + j * 16) = q;
            *(uint4*)(smem + AKS + tid * ROWB + j * 16) = kp[j];
            uint4 v = vp[j];
            const __half* vh = (const __half*)&v;
#pragma unroll
            for (int u = 0; u < 8; u++)
                vt[(j * 8 + u) * 136 + tid] = vh[u];
        }
        ((float*)(smem + AMB))[tid] = g_mask[b * Mc + tid] ? 0.f : -1e30f;
    }
    __syncthreads();

    // hoist Q fragments across both halves
    uint32_t aq[2][2][4];
#pragma unroll
    for (int ks = 0; ks < 2; ks++)
#pragma unroll
        for (int mt = 0; mt < 2; mt++) {
            uint32_t arow = wm + mt * 16 + (lane & 15);
            uint32_t kb = ks * 32 + ((lane >> 4) * 16);
            LDSM_X4(aq[ks][mt][0], aq[ks][mt][1], aq[ks][mt][2], aq[ks][mt][3],
                    sb + AQ + arow * ROWB + kb);
        }

    float m[4], l[4];
#pragma unroll
    for (int rg = 0; rg < 4; rg++) { m[rg] = -3.0e38f; l[rg] = 0.f; }
    float av[2][4][4];
#pragma unroll
    for (int mt = 0; mt < 2; mt++)
#pragma unroll
        for (int nd = 0; nd < 4; nd++)
#pragma unroll
            for (int q = 0; q < 4; q++) av[mt][nd][q] = 0.f;

    const float* mb = (const float*)(smem + AMB);

#pragma unroll
    for (int hf = 0; hf < 2; hf++) {
        float sch[2][8][4];
#pragma unroll
        for (int mt = 0; mt < 2; mt++)
#pragma unroll
            for (int nt = 0; nt < 8; nt++)
#pragma unroll
                for (int q = 0; q < 4; q++) sch[mt][nt][q] = 0.f;

#pragma unroll
        for (int ks = 0; ks < 2; ks++) {
#pragma unroll
            for (int npl = 0; npl < 4; npl++) {
                uint32_t nrow = hf * 64 + npl * 16 + ((lane >> 4) << 3) + (lane & 7);
                uint32_t kb = ks * 32 + (((lane >> 3) & 1) << 4);
                uint32_t bh[4];
                LDSM_X4(bh[0], bh[1], bh[2], bh[3], sb + AKS + nrow * ROWB + kb);
#pragma unroll
                for (int mt = 0; mt < 2; mt++) {
                    MMA16816(sch[mt][2 * npl],     aq[ks][mt], bh[0], bh[1]);
                    MMA16816(sch[mt][2 * npl + 1], aq[ks][mt], bh[2], bh[3]);
                }
            }
        }
#pragma unroll
        for (int nt = 0; nt < 8; nt++) {
            float2 mp = *(const float2*)(mb + hf * 64 + nt * 8 + (lane & 3) * 2);
#pragma unroll
            for (int mt = 0; mt < 2; mt++) {
                sch[mt][nt][0] += mp.x; sch[mt][nt][1] += mp.y;
                sch[mt][nt][2] += mp.x; sch[mt][nt][3] += mp.y;
            }
        }
#pragma unroll
        for (int rg = 0; rg < 4; rg++) {
            const int mt = rg >> 1, off = (rg & 1) * 2;
            float mh = -3.0e38f;
#pragma unroll
            for (int nt = 0; nt < 8; nt++)
                mh = fmaxf(mh, fmaxf(sch[mt][nt][off], sch[mt][nt][off + 1]));
            mh = fmaxf(mh, __shfl_xor_sync(0xffffffff, mh, 1));
            mh = fmaxf(mh, __shfl_xor_sync(0xffffffff, mh, 2));
            float mnew = fmaxf(m[rg], mh);
            float corr = ex2f(m[rg] - mnew);
            float lh = 0.f;
#pragma unroll
            for (int nt = 0; nt < 8; nt++) {
                float p0 = ex2f(sch[mt][nt][off] - mnew);
                float p1 = ex2f(sch[mt][nt][off + 1] - mnew);
                sch[mt][nt][off] = p0; sch[mt][nt][off + 1] = p1;
                lh += p0 + p1;
            }
            lh += __shfl_xor_sync(0xffffffff, lh, 1);
            lh += __shfl_xor_sync(0xffffffff, lh, 2);
            l[rg] = l[rg] * corr + lh;
            m[rg] = mnew;
#pragma unroll
            for (int nd = 0; nd < 4; nd++) {
                av[mt][nd][off] *= corr;
                av[mt][nd][off + 1] *= corr;
            }
        }
#pragma unroll
        for (int jl = 0; jl < 4; jl++) {
            uint32_t pa[2][4];
#pragma unroll
            for (int mt = 0; mt < 2; mt++) {
                pa[mt][0] = pack_f2h(sch[mt][2 * jl][0],     sch[mt][2 * jl][1]);
                pa[mt][1] = pack_f2h(sch[mt][2 * jl][2],     sch[mt][2 * jl][3]);
                pa[mt][2] = pack_f2h(sch[mt][2 * jl + 1][0], sch[mt][2 * jl + 1][1]);
                pa[mt][3] = pack_f2h(sch[mt][2 * jl + 1][2], sch[mt][2 * jl + 1][3]);
            }
#pragma unroll
            for (int np = 0; np < 2; np++) {
                uint32_t nrow = np * 16 + ((lane >> 4) << 3) + (lane & 7);
                uint32_t kb = (hf * 4 + jl) * 32 + (((lane >> 3) & 1) << 4);
                uint32_t vb[4];
                LDSM_X4(vb[0], vb[1], vb[2], vb[3], sb + AVT + nrow * 272 + kb);
#pragma unroll
                for (int mt = 0; mt < 2; mt++) {
                    MMA16816(av[mt][2 * np],     pa[mt], vb[0], vb[1]);
                    MMA16816(av[mt][2 * np + 1], pa[mt], vb[2], vb[3]);
                }
            }
        }
    }

#pragma unroll
    for (int mt = 0; mt < 2; mt++) {
        int row = b * Mc + wm + mt * 16 + (lane >> 2);
        float i0 = 1.f / l[mt * 2 + 0], i1 = 1.f / l[mt * 2 + 1];
#pragma unroll
        for (int nd = 0; nd < 4; nd++) {
            int col = head * DHc + nd * 8 + (lane & 3) * 2;
            *(uint32_t*)(g_ad16 + (size_t)row * Hc + col) =
                pack_f2h(av[mt][nd][0] * i0, av[mt][nd][1] * i0);
            *(uint32_t*)(g_ad16 + (size_t)(row + 8) * Hc + col) =
                pack_f2h(av[mt][nd][2] * i1, av[mt][nd][3] * i1);
        }
    }
}

// ---------------- host orchestration ----------------
static inline int cdiv(long a, int b) { return (int)((a + b - 1) / b); }

extern "C" void kernel_launch(void* const* d_in, const int* in_sizes, int n_in,
                              void* d_out, int out_size) {
    const float* h         = (const float*)d_in[0];
    const float* gin_w1    = (const float*)d_in[1];
    const float* gin_b1    = (const float*)d_in[2];
    const float* gin_w2    = (const float*)d_in[3];
    const float* gin_b2    = (const float*)d_in[4];
    const float* in_proj_w = (const float*)d_in[5];
    const float* in_proj_b = (const float*)d_in[6];
    const float* out_proj_w= (const float*)d_in[7];
    const float* out_proj_b= (const float*)d_in[8];
    const float* bnl_g     = (const float*)d_in[9];
    const float* bnl_b     = (const float*)d_in[10];
    const float* bna_g     = (const float*)d_in[11];
    const float* bna_b     = (const float*)d_in[12];
    const float* bno_g     = (const float*)d_in[13];
    const float* bno_b     = (const float*)d_in[14];
    const float* ffn1_w    = (const float*)d_in[15];
    const float* ffn1_b    = (const float*)d_in[16];
    const float* ffn2_w    = (const float*)d_in[17];
    const float* ffn2_b    = (const float*)d_in[18];
    const int*   e_src     = (const int*)d_in[19];
    const int*   e_dst     = (const int*)d_in[20];
    const int*   bnn       = (const int*)d_in[21];

    const int nN = in_sizes[0] / Hc;
    const int nE = in_sizes[19];
    const int n4 = nN * H4c;
    const float invN = 1.0f / (float)nN;
    const int halfN = nN / 2;

    float *p_hh, *p_st;
    int *p_inv;
    __half *p_wh, *p_h16, *p_ha16, *p_z116, *p_qkv16, *p_ad16, *p_hh16, *p_f116,
           *p_PL16, *p_PA16;
    cudaGetSymbolAddress((void**)&p_hh,    g_hh);
    cudaGetSymbolAddress((void**)&p_st,    g_bnstats);
    cudaGetSymbolAddress((void**)&p_inv,   g_inv);
    cudaGetSymbolAddress((void**)&p_wh,    g_wh);
    cudaGetSymbolAddress((void**)&p_h16,   g_h16);
    cudaGetSymbolAddress((void**)&p_ha16,  g_ha16);
    cudaGetSymbolAddress((void**)&p_z116,  g_z116);
    cudaGetSymbolAddress((void**)&p_qkv16, g_qkv16);
    cudaGetSymbolAddress((void**)&p_ad16,  g_ad16);
    cudaGetSymbolAddress((void**)&p_hh16,  g_hh16);
    cudaGetSymbolAddress((void**)&p_f116,  g_f116);
    cudaGetSymbolAddress((void**)&p_PL16,  g_PL16);
    cudaGetSymbolAddress((void**)&p_PA16,  g_PA16);

    float* st_l = p_st;
    float* st_a = p_st + 2 * Hc;
    float* st_o = p_st + 4 * Hc;

    cudaFuncSetAttribute(mma_gemm<true>,  cudaFuncAttributeMaxDynamicSharedMemorySize, GEMM_SMEM);
    cudaFuncSetAttribute(mma_gemm<false>, cudaFuncAttributeMaxDynamicSharedMemorySize, GEMM_SMEM);

    static cudaStream_t s_side = nullptr;
    static cudaEvent_t  e_fork = nullptr, e_join = nullptr, e_fork2 = nullptr, e_join2 = nullptr;
    if (s_side == nullptr) {
        cudaStreamCreateWithFlags(&s_side, cudaStreamNonBlocking);
        cudaEventCreateWithFlags(&e_fork,  cudaEventDisableTiming);
        cudaEventCreateWithFlags(&e_join,  cudaEventDisableTiming);
        cudaEventCreateWithFlags(&e_fork2, cudaEventDisableTiming);
        cudaEventCreateWithFlags(&e_join2, cudaEventDisableTiming);
    }

    const int OFF_GIN1 = 0;
    const int OFF_GIN2 = 65536;
    const int OFF_QKV  = 131072;
    const int OFF_OUT  = 327680;
    const int OFF_F1   = 393216;
    const int OFF_F2   = 524288;

    auto gemm = [&](cudaStream_t st, bool relu, const __half* A, const int* a_inv,
                    int woff, const float* bias, const float* res, const int* c_inv,
                    float* C32, __half* C16, float* stats, int Nc, int K, int nRows) {
        dim3 grid(Nc / 128, nRows / 128);
        if (relu)
            mma_gemm<true><<<grid, 256, GEMM_SMEM, st>>>(A, a_inv, p_wh + woff,
                bias, res, c_inv, C32, C16, stats, Nc, K);
        else
            mma_gemm<false><<<grid, 256, GEMM_SMEM, st>>>(A, a_inv, p_wh + woff,
                bias, res, c_inv, C32, C16, stats, Nc, K);
    };

    // ---- serial prologue ----
    wsplit_all<<<768, 256>>>(gin_w1, gin_w2, in_proj_w, out_proj_w, ffn1_w, ffn2_w, bnn);
    h_split<<<cdiv(n4, 256), 256>>>(h, n4, e_dst, nE);

    // ---- fork: GIN on side, attention on legacy ----
    cudaEventRecord(e_fork, 0);
    cudaStreamWaitEvent(s_side, e_fork, 0);

    gemm(0, false, p_h16, p_inv, OFF_QKV, in_proj_b, nullptr, nullptr,
         nullptr, p_qkv16, nullptr, 3 * Hc, Hc, nN);
    attn_mma<<<Bc * NHc, 128>>>();
    gemm(0, false, p_ad16, nullptr, OFF_OUT, out_proj_b, h, p_inv,
         nullptr, p_PA16, st_a, Hc, Hc, nN);

    csr_scan<<<1, 1024, 0, s_side>>>();
    csr_fill<<<cdiv(nE, 256), 256, 0, s_side>>>(e_src, e_dst, nE);
    gather_k<<<nN / 8, 256, 0, s_side>>>();
    gemm(s_side, true,  p_ha16, nullptr, OFF_GIN1, gin_b1, nullptr, nullptr,
         nullptr, p_z116, nullptr, Hc, Hc, nN);
    gemm(s_side, false, p_z116, nullptr, OFF_GIN2, gin_b2, h, nullptr,
         nullptr, p_PL16, st_l, Hc, Hc, nN);

    // ---- join both branches ----
    cudaEventRecord(e_join, s_side);
    cudaStreamWaitEvent(0, e_join, 0);

    // ---- tail fork: row halves on both streams ----
    cudaEventRecord(e_fork2, 0);
    cudaStreamWaitEvent(s_side, e_fork2, 0);

    const int h4 = halfN * H4c;
    bn_combine<<<cdiv(h4, 256), 256>>>(p_PL16, p_PA16, bnl_g, bnl_b, bna_g, bna_b,
                                       st_l, st_a, p_hh, invN, 0, h4);
    gemm(0, true,  p_hh16, nullptr, OFF_F1, ffn1_b, nullptr, nullptr,
         nullptr, p_f116, nullptr, 2 * Hc, Hc, halfN);
    gemm(0, false, p_f116, nullptr, OFF_F2, ffn2_b, p_hh, nullptr,
         nullptr, p_ad16, st_o, Hc, 2 * Hc, halfN);
    bn_combine<<<cdiv(h4, 256), 256, 0, s_side>>>(p_PL16, p_PA16, bnl_g, bnl_b,
                                                  bna_g, bna_b, st_l, st_a,
                                                  p_hh, invN, h4, h4);
    gemm(s_side, true,  p_hh16 + (size_t)halfN * Hc, nullptr, OFF_F1, ffn1_b,
         nullptr, nullptr, nullptr, p_f116 + (size_t)halfN * 2 * Hc, nullptr,
         2 * Hc, Hc, halfN);
    gemm(s_side, false, p_f116 + (size_t)halfN * 2 * Hc, nullptr, OFF_F2, ffn2_b,
         p_hh + (size_t)halfN * Hc, nullptr, nullptr,
         p_ad16 + (size_t)halfN * Hc, st_o, Hc, 2 * Hc, halfN);

    cudaEventRecord(e_join2, s_side);
    cudaStreamWaitEvent(0, e_join2, 0);

    // ---- final BN ----
    bn_apply16<<<cdiv(n4, 256), 256>>>(p_ad16, st_o, bno_g, bno_b,
                                       (float*)d_out, invN, n4);
}

// round 17
// speedup vs baseline: 1.3486x; 1.0341x over previous
#include <cuda_runtime.h>
#include <cuda_bf16.h>
#include <cuda_fp16.h>
#include <cstdint>
#include <cstdio>

// ---------------- problem constants ----------------
#define Hc   256
#define H4c  64
#define Bc   256
#define Mc   128
#define NHc  8
#define DHc  32
#define NMAX 32768
#define EMAX 524288

// ---------------- device scratch -------------------
__device__ float g_bnstats[3 * 2 * Hc];
__device__ int   g_inv   [Bc * Mc];
__device__ int   g_mask  [Bc * Mc];
__device__ int   g_deg   [NMAX];
__device__ int   g_cs    [NMAX + 1];
__device__ int   g_cur   [NMAX];
__device__ int   g_csrc  [EMAX];
#define WTOT 655360
__device__ __align__(16) __half g_wh[WTOT];
__device__ __align__(16) __half g_h16  [NMAX * Hc];
__device__ __align__(16) __half g_ha16 [NMAX * Hc];
__device__ __align__(16) __half g_z116 [NMAX * Hc];
__device__ __align__(16) __half g_qkv16[Bc * Mc * 3 * Hc];
__device__ __align__(16) __half g_ad16 [NMAX * Hc];   // attn out; later PO16
__device__ __align__(16) __half g_hh16 [NMAX * Hc];
__device__ __align__(16) __half g_f116 [NMAX * 2 * Hc];
__device__ __align__(16) __half g_PL16 [NMAX * Hc];
__device__ __align__(16) __half g_PA16 [NMAX * Hc];
__device__ __align__(16) __half g_zrow[64];

// ---------------- PTX helpers ----------------------
__device__ __forceinline__ uint32_t smem_u32(const void* p) {
    uint32_t a;
    asm("{ .reg .u64 t; cvta.to.shared.u64 t, %1; cvt.u32.u64 %0, t; }"
        : "=r"(a) : "l"(p));
    return a;
}
#define LDSM_X4(r0, r1, r2, r3, addr)                                    \
    asm volatile("ldmatrix.sync.aligned.m8n8.x4.shared.b16 {%0,%1,%2,%3}, [%4];" \
                 : "=r"(r0), "=r"(r1), "=r"(r2), "=r"(r3) : "r"(addr))
#define MMA16816(d, a, b0, b1)                                           \
    asm volatile("mma.sync.aligned.m16n8k16.row.col.f32.f16.f16.f32 "    \
                 "{%0,%1,%2,%3}, {%4,%5,%6,%7}, {%8,%9}, {%0,%1,%2,%3};" \
                 : "+f"((d)[0]), "+f"((d)[1]), "+f"((d)[2]), "+f"((d)[3]) \
                 : "r"((a)[0]), "r"((a)[1]), "r"((a)[2]), "r"((a)[3]),   \
                   "r"(b0), "r"(b1))
#define CP_ASYNC16(dst, src)                                             \
    asm volatile("cp.async.ca.shared.global [%0], [%1], 16;" :: "r"(dst), "l"(src))
#define CP_COMMIT() asm volatile("cp.async.commit_group;")
#define CP_WAIT0()  asm volatile("cp.async.wait_group 0;" ::: "memory")

__device__ __forceinline__ uint32_t pack_h2(__half a, __half b) {
    __half2 p{a, b};
    return *(uint32_t*)&p;
}
__device__ __forceinline__ uint32_t pack_f2h(float a, float b) {
    return pack_h2(__float2half_rn(a), __float2half_rn(b));
}
__device__ __forceinline__ float ex2f(float x) {
    float y;
    asm("ex2.approx.ftz.f32 %0, %1;" : "=f"(y) : "f"(x));
    return y;
}
__device__ __forceinline__ uint2 cvt4(float4 v) {
    return make_uint2(pack_f2h(v.x, v.y), pack_f2h(v.z, v.w));
}
__device__ __forceinline__ float4 up4(uint2 x) {
    const __half2* h2 = (const __half2*)&x;
    float2 f0 = __half22float2(h2[0]), f1 = __half22float2(h2[1]);
    return make_float4(f0.x, f0.y, f1.x, f1.y);
}
__device__ __forceinline__ float2 up2(uint32_t x) {
    __half2 h = *(__half2*)&x;
    return __half22float2(h);
}

// ---------------- single-pass fp16 GEMM ------------
// Residual (if any) is fp16 via res16.
#define ROWB 80
#define OFF_A 0
#define OFF_B 10240
#define BUFSZ 20480
#define GEMM_SMEM (2 * BUFSZ)

template<bool RELU>
__global__ __launch_bounds__(256, 2)
void mma_gemm(const __half* __restrict__ A, const int* __restrict__ a_inv,
              const __half* __restrict__ W, const float* __restrict__ bias,
              const __half* __restrict__ res16, const int* __restrict__ c_inv,
              __half* __restrict__ C16, float* __restrict__ stats, int Nc, int K) {
    extern __shared__ char smem[];
    const uint32_t sb = smem_u32(smem);
    const int tid = threadIdx.x;
    const int wid = tid >> 5, lane = tid & 31;
    const int wm = (wid >> 1) * 32, wn = (wid & 1) * 64;
    const int row0 = blockIdx.y * 128;
    const int col0 = blockIdx.x * 128;
    const int r = tid >> 1, half = tid & 1;

    const __half* pA;
    bool avalid = true;
    {
        int arow = row0 + r;
        if (a_inv) {
            int nd = a_inv[arow];
            avalid = nd >= 0;
            pA = A + (size_t)(avalid ? nd : 0) * K;
        } else {
            pA = A + (size_t)arow * K;
        }
    }

    float acc[2][8][4];
#pragma unroll
    for (int mt = 0; mt < 2; mt++)
#pragma unroll
        for (int nt = 0; nt < 8; nt++)
#pragma unroll
            for (int q = 0; q < 4; q++) acc[mt][nt][q] = 0.f;

    const int nit = K >> 5;

    auto issue = [&](int i) {
        const uint32_t bo = (uint32_t)(i & 1) * BUFSZ;
        const int k0 = i * 32;
        const char* sA = avalid ? (const char*)(pA + k0 + half * 16)
                                : (const char*)(g_zrow + half * 16);
        uint32_t dA = sb + bo + OFF_A + r * ROWB + half * 32;
        CP_ASYNC16(dA, sA); CP_ASYNC16(dA + 16, sA + 16);
        const char* gb = (const char*)(W + (size_t)(col0 + r) * K + k0 + half * 16);
        uint32_t dB = sb + bo + OFF_B + r * ROWB + half * 32;
        CP_ASYNC16(dB, gb); CP_ASYNC16(dB + 16, gb + 16);
        CP_COMMIT();
    };

    issue(0);
    for (int i = 0; i < nit; i++) {
        const uint32_t boff = (uint32_t)(i & 1) * BUFSZ;
        CP_WAIT0();
        __syncthreads();
        if (i + 1 < nit) issue(i + 1);
#pragma unroll
        for (int ks = 0; ks < 2; ks++) {
            uint32_t ah[2][4];
#pragma unroll
            for (int mt = 0; mt < 2; mt++) {
                uint32_t arow = wm + mt * 16 + (lane & 15);
                uint32_t kb = ks * 32 + ((lane >> 4) * 16);
                LDSM_X4(ah[mt][0], ah[mt][1], ah[mt][2], ah[mt][3],
                        sb + boff + OFF_A + arow * ROWB + kb);
            }
#pragma unroll
            for (int np = 0; np < 4; np++) {
                uint32_t nrow = wn + np * 16 + ((lane >> 4) << 3) + (lane & 7);
                uint32_t kb = ks * 32 + (((lane >> 3) & 1) << 4);
                uint32_t bh[4];
                LDSM_X4(bh[0], bh[1], bh[2], bh[3],
                        sb + boff + OFF_B + nrow * ROWB + kb);
#pragma unroll
                for (int mt = 0; mt < 2; mt++) {
                    MMA16816(acc[mt][2 * np],     ah[mt], bh[0], bh[1]);
                    MMA16816(acc[mt][2 * np + 1], ah[mt], bh[2], bh[3]);
                }
            }
        }
    }
    __syncthreads();

    // ---- epilogue ----
    float* ssum = (float*)smem;
    float* ssq  = ssum + 128;
    if (stats) {
        if (tid < 128) { ssum[tid] = 0.f; ssq[tid] = 0.f; }
        __syncthreads();
    }
    int rA0 = row0 + wm + (lane >> 2);
    int nmap[2][2];
    if (c_inv) {
        nmap[0][0] = c_inv[rA0];      nmap[0][1] = c_inv[rA0 + 8];
        nmap[1][0] = c_inv[rA0 + 16]; nmap[1][1] = c_inv[rA0 + 24];
    }
#pragma unroll
    for (int nt = 0; nt < 8; nt++) {
        int c = col0 + wn + nt * 8 + (lane & 3) * 2;
        float2 bi = *(const float2*)(bias + c);
        float cs0 = 0.f, cs1 = 0.f, cq0 = 0.f, cq1 = 0.f;
#pragma unroll
        for (int mt = 0; mt < 2; mt++) {
            int ra = rA0 + mt * 16;
            float o0 = acc[mt][nt][0] + bi.x, o1 = acc[mt][nt][1] + bi.y;
            float o2 = acc[mt][nt][2] + bi.x, o3 = acc[mt][nt][3] + bi.y;
            if (c_inv) {
                int na = nmap[mt][0], nb = nmap[mt][1];
                if (na >= 0) {
                    float2 rv = up2(*(const uint32_t*)(res16 + (size_t)na * Nc + c));
                    o0 += rv.x; o1 += rv.y;
                    *(uint32_t*)(C16 + (size_t)na * Nc + c) = pack_f2h(o0, o1);
                    cs0 += o0; cq0 += o0 * o0; cs1 += o1; cq1 += o1 * o1;
                }
                if (nb >= 0) {
                    float2 rv = up2(*(const uint32_t*)(res16 + (size_t)nb * Nc + c));
                    o2 += rv.x; o3 += rv.y;
                    *(uint32_t*)(C16 + (size_t)nb * Nc + c) = pack_f2h(o2, o3);
                    cs0 += o2; cq0 += o2 * o2; cs1 += o3; cq1 += o3 * o3;
                }
            } else {
                if (res16) {
                    float2 r0 = up2(*(const uint32_t*)(res16 + (size_t)ra * Nc + c));
                    float2 r1 = up2(*(const uint32_t*)(res16 + (size_t)(ra + 8) * Nc + c));
                    o0 += r0.x; o1 += r0.y; o2 += r1.x; o3 += r1.y;
                }
                if (RELU) {
                    o0 = fmaxf(o0, 0.f); o1 = fmaxf(o1, 0.f);
                    o2 = fmaxf(o2, 0.f); o3 = fmaxf(o3, 0.f);
                }
                *(uint32_t*)(C16 + (size_t)ra * Nc + c) = pack_f2h(o0, o1);
                *(uint32_t*)(C16 + (size_t)(ra + 8) * Nc + c) = pack_f2h(o2, o3);
                if (stats) {
                    cs0 += o0 + o2; cq0 += o0 * o0 + o2 * o2;
                    cs1 += o1 + o3; cq1 += o1 * o1 + o3 * o3;
                }
            }
        }
        if (stats) {
            int lc = c - col0;
            atomicAdd(&ssum[lc], cs0); atomicAdd(&ssq[lc], cq0);
            atomicAdd(&ssum[lc + 1], cs1); atomicAdd(&ssq[lc + 1], cq1);
        }
    }
    if (stats) {
        __syncthreads();
        if (tid < 128) {
            atomicAdd(&stats[col0 + tid], ssum[tid]);
            atomicAdd(&stats[Hc + col0 + tid], ssq[tid]);
        }
    }
}

// ---------------- weight convert + deg zero + inv fused ---------
__global__ void wsplit_all(const float* w0, const float* w1, const float* w2,
                           const float* w3, const float* w4, const float* w5,
                           const int* __restrict__ bnn) {
    int blk = blockIdx.x;
    int t = threadIdx.x;
    if (blk >= 640) {
        __shared__ int sm[256];
        sm[t] = bnn[t];
        __syncthreads();
        for (int off = 1; off < 256; off <<= 1) {
            int v = sm[t] + ((t >= off) ? sm[t - off] : 0);
            __syncthreads();
            sm[t] = v;
            __syncthreads();
        }
        int s = (blk - 640) * 256 + t;
        int b = s >> 7, rr = s & (Mc - 1);
        int cumb = (b == 0) ? 0 : sm[b - 1];
        int nb = sm[b] - cumb;
        bool v = rr < nb;
        g_inv[s] = v ? (cumb + rr) : -1;
        g_mask[s] = v ? 1 : 0;
        if (blk == 640) {
            for (int i = t; i < 6 * Hc; i += 256) g_bnstats[i] = 0.f;
        }
        return;
    }
    int gid = blk * 256 + t;
    if (gid < NMAX) g_deg[gid] = 0;
    const float* W; int sblk; int oel;
    if      (blk < 64)  { W = w0; sblk = 0;   oel = 0;      }
    else if (blk < 128) { W = w1; sblk = 64;  oel = 65536;  }
    else if (blk < 320) { W = w2; sblk = 128; oel = 131072; }
    else if (blk < 384) { W = w3; sblk = 320; oel = 327680; }
    else if (blk < 512) { W = w4; sblk = 384; oel = 393216; }
    else                { W = w5; sblk = 512; oel = 524288; }
    int i4 = (blk - sblk) * 256 + t;
    float4 v = ((const float4*)W)[i4];
    ((uint2*)(g_wh + oel))[i4] = cvt4(v);
}

// h -> fp16, plus edge histogram fused
__global__ void h_split(const float* __restrict__ h, int n4,
                        const int* __restrict__ dst, int E) {
    int gid = blockIdx.x * 256 + threadIdx.x;
    if (gid < n4)
        ((uint2*)g_h16)[gid] = cvt4(((const float4*)h)[gid]);
    if (gid < E)
        atomicAdd(&g_deg[dst[gid]], 1);
}

// ---------------- CSR build ------------------------
__global__ void csr_scan() {
    __shared__ int sm[1024];
    int t = threadIdx.x;
    int base = t * 32;
    int loc[32];
    int s = 0;
#pragma unroll
    for (int i = 0; i < 32; i++) { loc[i] = s; s += g_deg[base + i]; }
    sm[t] = s;
    __syncthreads();
    for (int off = 1; off < 1024; off <<= 1) {
        int v = sm[t] + ((t >= off) ? sm[t - off] : 0);
        __syncthreads();
        sm[t] = v;
        __syncthreads();
    }
    int pref = (t == 0) ? 0 : sm[t - 1];
#pragma unroll
    for (int i = 0; i < 32; i++) {
        int v = pref + loc[i];
        g_cs[base + i] = v;
        g_cur[base + i] = v;
    }
    if (t == 1023) g_cs[NMAX] = sm[1023];
}

__global__ void csr_fill(const int* __restrict__ src, const int* __restrict__ dst, int E) {
    int e = blockIdx.x * 256 + threadIdx.x;
    if (e >= E) return;
    int d = dst[e];
    int pos = atomicAdd(&g_cur[d], 1);
    g_csrc[pos] = src[e];
}

// ---------------- fused gather (from fp16) ----------
__global__ __launch_bounds__(256)
void gather_k() {
    int w = blockIdx.x * 8 + (threadIdx.x >> 5);
    int lane = threadIdx.x & 31;
    const uint4* hr = (const uint4*)(g_h16 + (size_t)w * Hc) + lane;
    float s[8];
    {
        uint4 v = *hr;
        const __half2* h2 = (const __half2*)&v;
#pragma unroll
        for (int j = 0; j < 4; j++) {
            float2 f = __half22float2(h2[j]);
            s[j * 2] = f.x; s[j * 2 + 1] = f.y;
        }
    }
    int beg = g_cs[w], end = g_cs[w + 1];
    for (int e = beg; e < end; e++) {
        int src = __ldg(&g_csrc[e]);
        uint4 v = __ldg((const uint4*)(g_h16 + (size_t)src * Hc) + lane);
        const __half2* h2 = (const __half2*)&v;
#pragma unroll
        for (int j = 0; j < 4; j++) {
            float2 f = __half22float2(h2[j]);
            s[j * 2] += f.x; s[j * 2 + 1] += f.y;
        }
    }
    uint4 o;
    o.x = pack_f2h(s[0], s[1]); o.y = pack_f2h(s[2], s[3]);
    o.z = pack_f2h(s[4], s[5]); o.w = pack_f2h(s[6], s[7]);
    *((uint4*)(g_ha16 + (size_t)w * Hc) + lane) = o;
}

// ---------------- BN kernels ------------------------
__device__ __forceinline__ float4 bn4(float4 x, float4 s, float4 q,
                                      float4 g, float4 b, float invN) {
    float4 o;
    { float m = s.x * invN, v = q.x * invN - m * m; o.x = g.x * (x.x - m) * rsqrtf(v + 1e-5f) + b.x; }
    { float m = s.y * invN, v = q.y * invN - m * m; o.y = g.y * (x.y - m) * rsqrtf(v + 1e-5f) + b.y; }
    { float m = s.z * invN, v = q.z * invN - m * m; o.z = g.z * (x.z - m) * rsqrtf(v + 1e-5f) + b.z; }
    { float m = s.w * invN, v = q.w * invN - m * m; o.w = g.w * (x.w - m) * rsqrtf(v + 1e-5f) + b.w; }
    return o;
}

// bn_combine over a row range, fp16 in/out (hh16 only)
__global__ void bn_combine(const __half* __restrict__ PL16, const __half* __restrict__ PA16,
                           const float* __restrict__ gl, const float* __restrict__ bl,
                           const float* __restrict__ ga, const float* __restrict__ ba,
                           const float* __restrict__ stl, const float* __restrict__ sta,
                           float invN, int base4, int cnt4) {
    int gid = base4 + blockIdx.x * 256 + threadIdx.x;
    if (gid >= base4 + cnt4) return;
    int c4 = gid & 63;
    float4 a = bn4(up4(((const uint2*)PL16)[gid]), ((const float4*)stl)[c4],
                   ((const float4*)stl)[H4c + c4], ((const float4*)gl)[c4],
                   ((const float4*)bl)[c4], invN);
    float4 b = bn4(up4(((const uint2*)PA16)[gid]), ((const float4*)sta)[c4],
                   ((const float4*)sta)[H4c + c4], ((const float4*)ga)[c4],
                   ((const float4*)ba)[c4], invN);
    a.x += b.x; a.y += b.y; a.z += b.z; a.w += b.w;
    ((uint2*)g_hh16)[gid] = cvt4(a);
}

__global__ void bn_apply16(const __half* __restrict__ X16, const float* __restrict__ st,
                           const float* __restrict__ gamma, const float* __restrict__ beta,
                           float* __restrict__ out, float invN, int n4total) {
    int gid = blockIdx.x * 256 + threadIdx.x;
    if (gid >= n4total) return;
    int c4 = gid & 63;
    float4 x = up4(((const uint2*)X16)[gid]);
    float4 o = bn4(x, ((const float4*)st)[c4],
                   ((const float4*)st)[H4c + c4], ((const float4*)gamma)[c4],
                   ((const float4*)beta)[c4], invN);
    ((float4*)out)[gid] = o;
}

// ---------------- tensor-core attention (online softmax, 2 halves) ----
#define AQ   0
#define AKS  10240
#define AVT  20480
#define AMB  29184
#define ASMEM 29696

__global__ __launch_bounds__(128, 3)
void attn_mma() {
    __shared__ char smem[ASMEM];
    const uint32_t sb = smem_u32(smem);
    const int b = blockIdx.x >> 3;
    const int head = blockIdx.x & 7;
    const int tid = threadIdx.x;
    const int wid = tid >> 5, lane = tid & 31;
    const int wm = wid * 32;

    const float sc2 = 0.17677669529663687f * 1.44269504088896341f;

    {
        const __half* base = g_qkv16 + (size_t)(b * Mc + tid) * (3 * Hc);
        const uint4* qp = (const uint4*)(base + head * DHc);
        const uint4* kp = (const uint4*)(base + Hc + head * DHc);
        const uint4* vp = (const uint4*)(base + 2 * Hc + head * DHc);
        __half2 s2 = __float2half2_rn(sc2);
        __half* vt = (__half*)(smem + AVT);
#pragma unroll
        for (int j = 0; j < 4; j++) {
            uint4 q = qp[j];
            __half2* qh = (__half2*)&q;
#pragma unroll
            for (int u = 0; u < 4; u++) qh[u] = __hmul2(qh[u], s2);
            *(uint4*)(smem + AQ + tid * ROWB + j * 16) = q;
            *(uint4*)(smem + AKS + tid * ROWB + j * 16) = kp[j];
            uint4 v = vp[j];
            const __half* vh = (const __half*)&v;
#pragma unroll
            for (int u = 0; u < 8; u++)
                vt[(j * 8 + u) * 136 + tid] = vh[u];
        }
        ((float*)(smem + AMB))[tid] = g_mask[b * Mc + tid] ? 0.f : -1e30f;
    }
    __syncthreads();

    uint32_t aq[2][2][4];
#pragma unroll
    for (int ks = 0; ks < 2; ks++)
#pragma unroll
        for (int mt = 0; mt < 2; mt++) {
            uint32_t arow = wm + mt * 16 + (lane & 15);
            uint32_t kb = ks * 32 + ((lane >> 4) * 16);
            LDSM_X4(aq[ks][mt][0], aq[ks][mt][1], aq[ks][mt][2], aq[ks][mt][3],
                    sb + AQ + arow * ROWB + kb);
        }

    float m[4], l[4];
#pragma unroll
    for (int rg = 0; rg < 4; rg++) { m[rg] = -3.0e38f; l[rg] = 0.f; }
    float av[2][4][4];
#pragma unroll
    for (int mt = 0; mt < 2; mt++)
#pragma unroll
        for (int nd = 0; nd < 4; nd++)
#pragma unroll
            for (int q = 0; q < 4; q++) av[mt][nd][q] = 0.f;

    const float* mb = (const float*)(smem + AMB);

#pragma unroll
    for (int hf = 0; hf < 2; hf++) {
        float sch[2][8][4];
#pragma unroll
        for (int mt = 0; mt < 2; mt++)
#pragma unroll
            for (int nt = 0; nt < 8; nt++)
#pragma unroll
                for (int q = 0; q < 4; q++) sch[mt][nt][q] = 0.f;

#pragma unroll
        for (int ks = 0; ks < 2; ks++) {
#pragma unroll
            for (int npl = 0; npl < 4; npl++) {
                uint32_t nrow = hf * 64 + npl * 16 + ((lane >> 4) << 3) + (lane & 7);
                uint32_t kb = ks * 32 + (((lane >> 3) & 1) << 4);
                uint32_t bh[4];
                LDSM_X4(bh[0], bh[1], bh[2], bh[3], sb + AKS + nrow * ROWB + kb);
#pragma unroll
                for (int mt = 0; mt < 2; mt++) {
                    MMA16816(sch[mt][2 * npl],     aq[ks][mt], bh[0], bh[1]);
                    MMA16816(sch[mt][2 * npl + 1], aq[ks][mt], bh[2], bh[3]);
                }
            }
        }
#pragma unroll
        for (int nt = 0; nt < 8; nt++) {
            float2 mp = *(const float2*)(mb + hf * 64 + nt * 8 + (lane & 3) * 2);
#pragma unroll
            for (int mt = 0; mt < 2; mt++) {
                sch[mt][nt][0] += mp.x; sch[mt][nt][1] += mp.y;
                sch[mt][nt][2] += mp.x; sch[mt][nt][3] += mp.y;
            }
        }
#pragma unroll
        for (int rg = 0; rg < 4; rg++) {
            const int mt = rg >> 1, off = (rg & 1) * 2;
            float mh = -3.0e38f;
#pragma unroll
            for (int nt = 0; nt < 8; nt++)
                mh = fmaxf(mh, fmaxf(sch[mt][nt][off], sch[mt][nt][off + 1]));
            mh = fmaxf(mh, __shfl_xor_sync(0xffffffff, mh, 1));
            mh = fmaxf(mh, __shfl_xor_sync(0xffffffff, mh, 2));
            float mnew = fmaxf(m[rg], mh);
            float corr = ex2f(m[rg] - mnew);
            float lh = 0.f;
#pragma unroll
            for (int nt = 0; nt < 8; nt++) {
                float p0 = ex2f(sch[mt][nt][off] - mnew);
                float p1 = ex2f(sch[mt][nt][off + 1] - mnew);
                sch[mt][nt][off] = p0; sch[mt][nt][off + 1] = p1;
                lh += p0 + p1;
            }
            lh += __shfl_xor_sync(0xffffffff, lh, 1);
            lh += __shfl_xor_sync(0xffffffff, lh, 2);
            l[rg] = l[rg] * corr + lh;
            m[rg] = mnew;
#pragma unroll
            for (int nd = 0; nd < 4; nd++) {
                av[mt][nd][off] *= corr;
                av[mt][nd][off + 1] *= corr;
            }
        }
#pragma unroll
        for (int jl = 0; jl < 4; jl++) {
            uint32_t pa[2][4];
#pragma unroll
            for (int mt = 0; mt < 2; mt++) {
                pa[mt][0] = pack_f2h(sch[mt][2 * jl][0],     sch[mt][2 * jl][1]);
                pa[mt][1] = pack_f2h(sch[mt][2 * jl][2],     sch[mt][2 * jl][3]);
                pa[mt][2] = pack_f2h(sch[mt][2 * jl + 1][0], sch[mt][2 * jl + 1][1]);
                pa[mt][3] = pack_f2h(sch[mt][2 * jl + 1][2], sch[mt][2 * jl + 1][3]);
            }
#pragma unroll
            for (int np = 0; np < 2; np++) {
                uint32_t nrow = np * 16 + ((lane >> 4) << 3) + (lane & 7);
                uint32_t kb = (hf * 4 + jl) * 32 + (((lane >> 3) & 1) << 4);
                uint32_t vb[4];
                LDSM_X4(vb[0], vb[1], vb[2], vb[3], sb + AVT + nrow * 272 + kb);
#pragma unroll
                for (int mt = 0; mt < 2; mt++) {
                    MMA16816(av[mt][2 * np],     pa[mt], vb[0], vb[1]);
                    MMA16816(av[mt][2 * np + 1], pa[mt], vb[2], vb[3]);
                }
            }
        }
    }

#pragma unroll
    for (int mt = 0; mt < 2; mt++) {
        int row = b * Mc + wm + mt * 16 + (lane >> 2);
        float i0 = 1.f / l[mt * 2 + 0], i1 = 1.f / l[mt * 2 + 1];
#pragma unroll
        for (int nd = 0; nd < 4; nd++) {
            int col = head * DHc + nd * 8 + (lane & 3) * 2;
            *(uint32_t*)(g_ad16 + (size_t)row * Hc + col) =
                pack_f2h(av[mt][nd][0] * i0, av[mt][nd][1] * i0);
            *(uint32_t*)(g_ad16 + (size_t)(row + 8) * Hc + col) =
                pack_f2h(av[mt][nd][2] * i1, av[mt][nd][3] * i1);
        }
    }
}

// ---------------- host orchestration ----------------
static inline int cdiv(long a, int b) { return (int)((a + b - 1) / b); }

extern "C" void kernel_launch(void* const* d_in, const int* in_sizes, int n_in,
                              void* d_out, int out_size) {
    const float* h         = (const float*)d_in[0];
    const float* gin_w1    = (const float*)d_in[1];
    const float* gin_b1    = (const float*)d_in[2];
    const float* gin_w2    = (const float*)d_in[3];
    const float* gin_b2    = (const float*)d_in[4];
    const float* in_proj_w = (const float*)d_in[5];
    const float* in_proj_b = (const float*)d_in[6];
    const float* out_proj_w= (const float*)d_in[7];
    const float* out_proj_b= (const float*)d_in[8];
    const float* bnl_g     = (const float*)d_in[9];
    const float* bnl_b     = (const float*)d_in[10];
    const float* bna_g     = (const float*)d_in[11];
    const float* bna_b     = (const float*)d_in[12];
    const float* bno_g     = (const float*)d_in[13];
    const float* bno_b     = (const float*)d_in[14];
    const float* ffn1_w    = (const float*)d_in[15];
    const float* ffn1_b    = (const float*)d_in[16];
    const float* ffn2_w    = (const float*)d_in[17];
    const float* ffn2_b    = (const float*)d_in[18];
    const int*   e_src     = (const int*)d_in[19];
    const int*   e_dst     = (const int*)d_in[20];
    const int*   bnn       = (const int*)d_in[21];

    const int nN = in_sizes[0] / Hc;
    const int nE = in_sizes[19];
    const int n4 = nN * H4c;
    const float invN = 1.0f / (float)nN;
    const int halfN = nN / 2;

    float *p_st;
    int *p_inv;
    __half *p_wh, *p_h16, *p_ha16, *p_z116, *p_qkv16, *p_ad16, *p_hh16, *p_f116,
           *p_PL16, *p_PA16;
    cudaGetSymbolAddress((void**)&p_st,    g_bnstats);
    cudaGetSymbolAddress((void**)&p_inv,   g_inv);
    cudaGetSymbolAddress((void**)&p_wh,    g_wh);
    cudaGetSymbolAddress((void**)&p_h16,   g_h16);
    cudaGetSymbolAddress((void**)&p_ha16,  g_ha16);
    cudaGetSymbolAddress((void**)&p_z116,  g_z116);
    cudaGetSymbolAddress((void**)&p_qkv16, g_qkv16);
    cudaGetSymbolAddress((void**)&p_ad16,  g_ad16);
    cudaGetSymbolAddress((void**)&p_hh16,  g_hh16);
    cudaGetSymbolAddress((void**)&p_f116,  g_f116);
    cudaGetSymbolAddress((void**)&p_PL16,  g_PL16);
    cudaGetSymbolAddress((void**)&p_PA16,  g_PA16);

    float* st_l = p_st;
    float* st_a = p_st + 2 * Hc;
    float* st_o = p_st + 4 * Hc;

    cudaFuncSetAttribute(mma_gemm<true>,  cudaFuncAttributeMaxDynamicSharedMemorySize, GEMM_SMEM);
    cudaFuncSetAttribute(mma_gemm<false>, cudaFuncAttributeMaxDynamicSharedMemorySize, GEMM_SMEM);

    static cudaStream_t s_side = nullptr;
    static cudaEvent_t  e_fork = nullptr, e_join = nullptr, e_fork2 = nullptr, e_join2 = nullptr;
    if (s_side == nullptr) {
        cudaStreamCreateWithFlags(&s_side, cudaStreamNonBlocking);
        cudaEventCreateWithFlags(&e_fork,  cudaEventDisableTiming);
        cudaEventCreateWithFlags(&e_join,  cudaEventDisableTiming);
        cudaEventCreateWithFlags(&e_fork2, cudaEventDisableTiming);
        cudaEventCreateWithFlags(&e_join2, cudaEventDisableTiming);
    }

    const int OFF_GIN1 = 0;
    const int OFF_GIN2 = 65536;
    const int OFF_QKV  = 131072;
    const int OFF_OUT  = 327680;
    const int OFF_F1   = 393216;
    const int OFF_F2   = 524288;

    auto gemm = [&](cudaStream_t st, bool relu, const __half* A, const int* a_inv,
                    int woff, const float* bias, const __half* res16, const int* c_inv,
                    __half* C16, float* stats, int Nc, int K, int nRows) {
        dim3 grid(Nc / 128, nRows / 128);
        if (relu)
            mma_gemm<true><<<grid, 256, GEMM_SMEM, st>>>(A, a_inv, p_wh + woff,
                bias, res16, c_inv, C16, stats, Nc, K);
        else
            mma_gemm<false><<<grid, 256, GEMM_SMEM, st>>>(A, a_inv, p_wh + woff,
                bias, res16, c_inv, C16, stats, Nc, K);
    };

    // ---- serial prologue ----
    wsplit_all<<<768, 256>>>(gin_w1, gin_w2, in_proj_w, out_proj_w, ffn1_w, ffn2_w, bnn);
    h_split<<<cdiv(n4, 256), 256>>>(h, n4, e_dst, nE);

    // ---- fork: GIN on side, attention on legacy ----
    cudaEventRecord(e_fork, 0);
    cudaStreamWaitEvent(s_side, e_fork, 0);

    gemm(0, false, p_h16, p_inv, OFF_QKV, in_proj_b, nullptr, nullptr,
         p_qkv16, nullptr, 3 * Hc, Hc, nN);
    attn_mma<<<Bc * NHc, 128>>>();
    gemm(0, false, p_ad16, nullptr, OFF_OUT, out_proj_b, p_h16, p_inv,
         p_PA16, st_a, Hc, Hc, nN);

    csr_scan<<<1, 1024, 0, s_side>>>();
    csr_fill<<<cdiv(nE, 256), 256, 0, s_side>>>(e_src, e_dst, nE);
    gather_k<<<nN / 8, 256, 0, s_side>>>();
    gemm(s_side, true,  p_ha16, nullptr, OFF_GIN1, gin_b1, nullptr, nullptr,
         p_z116, nullptr, Hc, Hc, nN);
    gemm(s_side, false, p_z116, nullptr, OFF_GIN2, gin_b2, p_h16, nullptr,
         p_PL16, st_l, Hc, Hc, nN);

    // ---- join both branches ----
    cudaEventRecord(e_join, s_side);
    cudaStreamWaitEvent(0, e_join, 0);

    // ---- tail fork: row halves on both streams ----
    cudaEventRecord(e_fork2, 0);
    cudaStreamWaitEvent(s_side, e_fork2, 0);

    const int h4 = halfN * H4c;
    bn_combine<<<cdiv(h4, 256), 256>>>(p_PL16, p_PA16, bnl_g, bnl_b, bna_g, bna_b,
                                       st_l, st_a, invN, 0, h4);
    gemm(0, true,  p_hh16, nullptr, OFF_F1, ffn1_b, nullptr, nullptr,
         p_f116, nullptr, 2 * Hc, Hc, halfN);
    gemm(0, false, p_f116, nullptr, OFF_F2, ffn2_b, p_hh16, nullptr,
         p_ad16, st_o, Hc, 2 * Hc, halfN);
    bn_combine<<<cdiv(h4, 256), 256, 0, s_side>>>(p_PL16, p_PA16, bnl_g, bnl_b,
                                                  bna_g, bna_b, st_l, st_a,
                                                  invN, h4, h4);
    gemm(s_side, true,  p_hh16 + (size_t)halfN * Hc, nullptr, OFF_F1, ffn1_b,
         nullptr, nullptr, p_f116 + (size_t)halfN * 2 * Hc, nullptr,
         2 * Hc, Hc, halfN);
    gemm(s_side, false, p_f116 + (size_t)halfN * 2 * Hc, nullptr, OFF_F2, ffn2_b,
         p_hh16 + (size_t)halfN * Hc, nullptr,
         p_ad16 + (size_t)halfN * Hc, st_o, Hc, 2 * Hc, halfN);

    cudaEventRecord(e_join2, s_side);
    cudaStreamWaitEvent(0, e_join2, 0);

    // ---- final BN ----
    bn_apply16<<<cdiv(n4, 256), 256>>>(p_ad16, st_o, bno_g, bno_b,
                                       (float*)d_out, invN, n4);
}